// round 11
// baseline (speedup 1.0000x reference)
#include <cuda_runtime.h>
#include <cuda_fp16.h>
#include <math.h>
#include <stdint.h>

#define BB   8
#define TT   12
#define NN   512
#define FINN 3
#define DD   128
#define HH   4
#define HMM  256
#define LL   3
#define PP   12
#define TOK  (BB*TT*NN)          // 49152 tokens

typedef __half h16;

// ---------------- scratch ----------------------------------------------------
__device__ h16   g_qkv  [TOK*3*DD];    // temporal qkv [tok,384] fp16
__device__ h16   g_qkv12[TOK*6*DD];    // geo|sem qkv  [tok,768] fp16
__device__ float g_xc [TOK*LL*DD];
__device__ float b_gs [LL*6*DD];
// fp16 activations
__device__ h16 a_hA[TOK*DD];
__device__ h16 a_hB[TOK*DD];
__device__ h16 a_at[TOK*DD];
__device__ h16 a_a2[TOK*DD];
__device__ h16 a_ct[TOK*2*DD];
__device__ h16 a_ml[TOK*HMM];
// fp16 weights
__device__ h16 w_tq[LL*3*DD*DD];
__device__ h16 w_gs[LL*6*DD*DD];
__device__ h16 w_tp[LL*DD*DD];
__device__ h16 w_gp[LL*DD*DD];
__device__ h16 w_sp[LL*DD*DD];
__device__ h16 w_f1[LL*HMM*2*DD];
__device__ h16 w_cb[LL*DD*(HMM+DD)];

__device__ __forceinline__ uint32_t smem_u32(const void* p) {
    uint32_t a;
    asm("{ .reg .u64 t; cvta.to.shared.u64 t, %1; cvt.u32.u64 %0, t; }"
        : "=r"(a) : "l"(p));
    return a;
}
__device__ __forceinline__ uint32_t pack2h(float a, float b) {
    __half2 h = __floats2half2_rn(a, b);
    return *(uint32_t*)&h;
}
#define CP_ASYNC16(dst, src) \
    asm volatile("cp.async.cg.shared.global [%0], [%1], 16;" :: "r"(dst), "l"(src))
#define CP_COMMIT() asm volatile("cp.async.commit_group;" ::: "memory")
#define CP_WAIT(n)  asm volatile("cp.async.wait_group %0;" :: "n"(n) : "memory")

// ================= one-shot weight conversion ================================
__global__ void cvt_all(const float* __restrict__ t_qkvW,
                        const float* __restrict__ g_qkvW, const float* __restrict__ s_qkvW,
                        const float* __restrict__ t_pW,   const float* __restrict__ g_pW,
                        const float* __restrict__ s_pW,   const float* __restrict__ fc1W,
                        const float* __restrict__ fc2W,   const float* __restrict__ resW,
                        const float* __restrict__ g_qkvb, const float* __restrict__ s_qkvb)
{
    int i = blockIdx.x * 256 + threadIdx.x;
    const int NQ  = LL*3*DD*DD;
    const int NGS = LL*6*DD*DD;
    const int NPw = LL*DD*DD;
    const int NF1 = LL*HMM*2*DD;
    const int NCB = LL*DD*(HMM+DD);
    float v; h16* dst; int off;
    if (i < NQ) { v = t_qkvW[i]; dst = w_tq; off = i; }
    else if ((i -= NQ) < NGS) {
        int l = i / (768*DD), r = (i / DD) % 768, k = i % DD;
        v = (r < 384) ? g_qkvW[((size_t)l*384 + r)*DD + k]
                      : s_qkvW[((size_t)l*384 + (r-384))*DD + k];
        if (k == 0) b_gs[l*768 + r] = (r < 384) ? g_qkvb[l*384 + r] : s_qkvb[l*384 + r - 384];
        dst = w_gs; off = i;
    }
    else if ((i -= NGS) < NPw) { v = t_pW[i]; dst = w_tp; off = i; }
    else if ((i -= NPw) < NPw) { v = g_pW[i]; dst = w_gp; off = i; }
    else if ((i -= NPw) < NPw) { v = s_pW[i]; dst = w_sp; off = i; }
    else if ((i -= NPw) < NF1) { v = fc1W[i]; dst = w_f1; off = i; }
    else if ((i -= NF1) < NCB) {
        const int KK = HMM + DD;
        int l = i / (DD*KK), r = (i / KK) % DD, k = i % KK;
        v = (k < HMM) ? fc2W[((size_t)l*DD + r)*HMM + k]
                      : resW[((size_t)l*DD + r)*DD + (k - HMM)];
        dst = w_cb; off = i;
    }
    else return;
    dst[off] = __float2half(v);
}

// ================= single-pass fp16 mma GEMM (+optional fused LN) ===========
// C = act(concat(A1,A2) @ W^T + bias [+bias2]).
// If lnW != null (requires gridDim.x==1, N=128): fused LayerNorm epilogue
// writing ln_hout (fp16 [tok,128]) and ln_xc (fp32, stride ldxc).
// Dynamic smem: 40 KB = double-buffered tiles; reused as fp32 staging for LN.
__global__ void __launch_bounds__(256, 2)
mma_gemm(const h16* __restrict__ A1, int K1, const h16* __restrict__ A2, int K2,
         const h16* __restrict__ W,
         const float* __restrict__ bias, const float* __restrict__ bias2,
         float* __restrict__ outf, h16* __restrict__ outh, int ldo, int gelu,
         const float* __restrict__ lnW, const float* __restrict__ lnB,
         h16* __restrict__ ln_hout, float* __restrict__ ln_xc, int ldxc)
{
    extern __shared__ char dsm[];
    h16* As = (h16*)dsm;              // [2][128][40]
    h16* Bs = As + 2*5120;            // [2][128][40]
    float* stage = (float*)dsm;       // LN staging [64][132], reuses tiles

    const int tid  = threadIdx.x;
    const int wid  = tid >> 5;
    const int lane = tid & 31;
    const int l16  = lane & 15;
    const int warp_m = wid >> 2;
    const int warp_n = wid & 3;
    const int m0 = blockIdx.y * 128;
    const int n0 = blockIdx.x * 128;
    const int K  = K1 + K2;
    const int KC = K >> 5;

    float acc[4][4][4];
#pragma unroll
    for (int mi = 0; mi < 4; ++mi)
#pragma unroll
        for (int ni = 0; ni < 4; ++ni)
#pragma unroll
            for (int r = 0; r < 4; ++r) acc[mi][ni][r] = 0.f;

    auto load_chunk = [&](int buf, int kp) {
        const int kof = kp * 32;
        const h16* Asrc; int lda, acol;
        if (kof < K1) { Asrc = A1; lda = K1; acol = kof; }
        else          { Asrc = A2; lda = K2; acol = kof - K1; }
#pragma unroll
        for (int t = 0; t < 2; ++t) {
            const int c   = tid + t * 256;
            const int row = c >> 2;
            const int cc  = (c & 3) * 8;
            CP_ASYNC16(smem_u32(As + buf*5120 + row*40 + cc),
                       Asrc + (size_t)(m0 + row) * lda + acol + cc);
            CP_ASYNC16(smem_u32(Bs + buf*5120 + row*40 + cc),
                       W + (size_t)(n0 + row) * K + kof + cc);
        }
    };

    auto compute = [&](int buf) {
#pragma unroll
        for (int ks = 0; ks < 2; ++ks) {
            const int k = ks * 16;
            uint32_t a[4][4], b[4][2];
#pragma unroll
            for (int mi = 0; mi < 4; ++mi) {
                uint32_t ad = smem_u32(As + buf*5120 + (warp_m*64 + mi*16 + l16)*40 + k + (lane >> 4) * 8);
                asm volatile("ldmatrix.sync.aligned.m8n8.x4.shared.b16 {%0,%1,%2,%3}, [%4];"
                             : "=r"(a[mi][0]), "=r"(a[mi][1]), "=r"(a[mi][2]), "=r"(a[mi][3])
                             : "r"(ad));
            }
#pragma unroll
            for (int ni = 0; ni < 4; ++ni) {
                uint32_t bd = smem_u32(Bs + buf*5120 + (warp_n*32 + ni*8 + (l16 & 7))*40 + k + (l16 >> 3) * 8);
                asm volatile("ldmatrix.sync.aligned.m8n8.x2.shared.b16 {%0,%1}, [%2];"
                             : "=r"(b[ni][0]), "=r"(b[ni][1]) : "r"(bd));
            }
#pragma unroll
            for (int mi = 0; mi < 4; ++mi)
#pragma unroll
                for (int ni = 0; ni < 4; ++ni)
                    asm volatile(
                        "mma.sync.aligned.m16n8k16.row.col.f32.f16.f16.f32 "
                        "{%0,%1,%2,%3}, {%4,%5,%6,%7}, {%8,%9}, {%0,%1,%2,%3};"
                        : "+f"(acc[mi][ni][0]), "+f"(acc[mi][ni][1]),
                          "+f"(acc[mi][ni][2]), "+f"(acc[mi][ni][3])
                        : "r"(a[mi][0]), "r"(a[mi][1]), "r"(a[mi][2]), "r"(a[mi][3]),
                          "r"(b[ni][0]), "r"(b[ni][1]));
        }
    };

    load_chunk(0, 0);
    CP_COMMIT();
    int buf = 0;
    for (int i = 0; i < KC; ++i) {
        if (i + 1 < KC) {
            load_chunk(buf ^ 1, i + 1);
            CP_COMMIT();
            CP_WAIT(1);
        } else {
            CP_WAIT(0);
        }
        __syncthreads();
        compute(buf);
        __syncthreads();
        buf ^= 1;
    }

    const int quad = lane >> 2, qi = lane & 3;

    if (lnW == nullptr) {
        // ---- plain epilogue ----
#pragma unroll
        for (int mi = 0; mi < 4; ++mi)
#pragma unroll
            for (int ni = 0; ni < 4; ++ni)
#pragma unroll
                for (int h = 0; h < 2; ++h) {
                    const int row = m0 + warp_m * 64 + mi * 16 + quad + h * 8;
                    const int col = n0 + warp_n * 32 + ni * 8 + qi * 2;
                    float v0 = acc[mi][ni][h * 2 + 0] + bias[col];
                    float v1 = acc[mi][ni][h * 2 + 1] + bias[col + 1];
                    if (bias2) { v0 += bias2[col]; v1 += bias2[col + 1]; }
                    const size_t o = (size_t)row * ldo + col;
                    if (gelu) {
                        v0 = 0.5f * v0 * (1.0f + erff(v0 * 0.70710678118654752f));
                        v1 = 0.5f * v1 * (1.0f + erff(v1 * 0.70710678118654752f));
                    }
                    if (outf) { outf[o] = v0; outf[o + 1] = v1; }
                    if (outh) *(uint32_t*)&outh[o] = pack2h(v0, v1);
                }
    } else {
        // ---- fused LayerNorm epilogue (gridDim.x==1, N=128) ----
#pragma unroll
        for (int half = 0; half < 2; ++half) {
            __syncthreads();                     // tiles / previous stage free
            if (warp_m == half) {
#pragma unroll
                for (int mi = 0; mi < 4; ++mi)
#pragma unroll
                    for (int ni = 0; ni < 4; ++ni)
#pragma unroll
                        for (int h = 0; h < 2; ++h) {
                            const int rl  = mi * 16 + quad + h * 8;   // 0..63
                            const int col = warp_n * 32 + ni * 8 + qi * 2;
                            float v0 = acc[mi][ni][h * 2 + 0] + bias[col]     + bias2[col];
                            float v1 = acc[mi][ni][h * 2 + 1] + bias[col + 1] + bias2[col + 1];
                            stage[rl * 132 + col]     = v0;
                            stage[rl * 132 + col + 1] = v1;
                        }
            }
            __syncthreads();
            // each warp normalizes 8 rows
#pragma unroll
            for (int rr = 0; rr < 8; ++rr) {
                const int rl = wid * 8 + rr;
                float v[4];
#pragma unroll
                for (int i = 0; i < 4; ++i) v[i] = stage[rl * 132 + lane + 32 * i];
                float s = v[0] + v[1] + v[2] + v[3];
#pragma unroll
                for (int o = 16; o; o >>= 1) s += __shfl_xor_sync(0xffffffffu, s, o);
                const float mean = s * (1.f / 128.f);
                float q = 0.f;
#pragma unroll
                for (int i = 0; i < 4; ++i) { v[i] -= mean; q += v[i] * v[i]; }
#pragma unroll
                for (int o = 16; o; o >>= 1) q += __shfl_xor_sync(0xffffffffu, q, o);
                const float inv = rsqrtf(q * (1.f / 128.f) + 1e-5f);
                const size_t row = (size_t)(m0 + half * 64 + rl);
#pragma unroll
                for (int i = 0; i < 4; ++i) {
                    const int d = lane + 32 * i;
                    const float o = v[i] * inv * lnW[d] + lnB[d];
                    ln_hout[row * DD + d] = __float2half(o);
                    ln_xc[row * ldxc + d] = o;
                }
            }
        }
    }
}

// ================= dual-source projection GEMM ===============================
__global__ void __launch_bounds__(256, 2)
mma_gemm_dual(const h16* __restrict__ Aa, const h16* __restrict__ Ab,
              const h16* __restrict__ Wa, const h16* __restrict__ Wb,
              const float* __restrict__ ba, const float* __restrict__ bb,
              h16* __restrict__ outh /* [tok, 256] */)
{
    __shared__ h16 As[2][128][40];
    __shared__ h16 Bs[2][128][40];

    const int tid  = threadIdx.x;
    const int wid  = tid >> 5;
    const int lane = tid & 31;
    const int l16  = lane & 15;
    const int warp_m = wid >> 2;
    const int warp_n = wid & 3;
    const int m0 = blockIdx.y * 128;
    const int sel = blockIdx.x;
    const h16* A = sel ? Ab : Aa;
    const h16* W = sel ? Wb : Wa;
    const float* bias = sel ? bb : ba;
    const int n0 = sel * 128;

    float acc[4][4][4];
#pragma unroll
    for (int mi = 0; mi < 4; ++mi)
#pragma unroll
        for (int ni = 0; ni < 4; ++ni)
#pragma unroll
            for (int r = 0; r < 4; ++r) acc[mi][ni][r] = 0.f;

    auto load_chunk = [&](int buf, int kp) {
        const int kof = kp * 32;
#pragma unroll
        for (int t = 0; t < 2; ++t) {
            const int c   = tid + t * 256;
            const int row = c >> 2;
            const int cc  = (c & 3) * 8;
            CP_ASYNC16(smem_u32(&As[buf][row][cc]),
                       A + (size_t)(m0 + row) * DD + kof + cc);
            CP_ASYNC16(smem_u32(&Bs[buf][row][cc]),
                       W + (size_t)row * DD + kof + cc);
        }
    };

    auto compute = [&](int buf) {
#pragma unroll
        for (int ks = 0; ks < 2; ++ks) {
            const int k = ks * 16;
            uint32_t a[4][4], b[4][2];
#pragma unroll
            for (int mi = 0; mi < 4; ++mi) {
                uint32_t ad = smem_u32(&As[buf][warp_m*64 + mi*16 + l16][k + (lane >> 4) * 8]);
                asm volatile("ldmatrix.sync.aligned.m8n8.x4.shared.b16 {%0,%1,%2,%3}, [%4];"
                             : "=r"(a[mi][0]), "=r"(a[mi][1]), "=r"(a[mi][2]), "=r"(a[mi][3])
                             : "r"(ad));
            }
#pragma unroll
            for (int ni = 0; ni < 4; ++ni) {
                uint32_t bd = smem_u32(&Bs[buf][warp_n*32 + ni*8 + (l16 & 7)][k + (l16 >> 3) * 8]);
                asm volatile("ldmatrix.sync.aligned.m8n8.x2.shared.b16 {%0,%1}, [%2];"
                             : "=r"(b[ni][0]), "=r"(b[ni][1]) : "r"(bd));
            }
#pragma unroll
            for (int mi = 0; mi < 4; ++mi)
#pragma unroll
                for (int ni = 0; ni < 4; ++ni)
                    asm volatile(
                        "mma.sync.aligned.m16n8k16.row.col.f32.f16.f16.f32 "
                        "{%0,%1,%2,%3}, {%4,%5,%6,%7}, {%8,%9}, {%0,%1,%2,%3};"
                        : "+f"(acc[mi][ni][0]), "+f"(acc[mi][ni][1]),
                          "+f"(acc[mi][ni][2]), "+f"(acc[mi][ni][3])
                        : "r"(a[mi][0]), "r"(a[mi][1]), "r"(a[mi][2]), "r"(a[mi][3]),
                          "r"(b[ni][0]), "r"(b[ni][1]));
        }
    };

    load_chunk(0, 0);
    CP_COMMIT();
    int buf = 0;
    for (int i = 0; i < 4; ++i) {
        if (i + 1 < 4) {
            load_chunk(buf ^ 1, i + 1);
            CP_COMMIT();
            CP_WAIT(1);
        } else {
            CP_WAIT(0);
        }
        __syncthreads();
        compute(buf);
        __syncthreads();
        buf ^= 1;
    }

    const int quad = lane >> 2, qi = lane & 3;
#pragma unroll
    for (int mi = 0; mi < 4; ++mi)
#pragma unroll
        for (int ni = 0; ni < 4; ++ni)
#pragma unroll
            for (int h = 0; h < 2; ++h) {
                const int row = m0 + warp_m * 64 + mi * 16 + quad + h * 8;
                const int col = warp_n * 32 + ni * 8 + qi * 2;
                float v0 = acc[mi][ni][h * 2 + 0] + bias[col];
                float v1 = acc[mi][ni][h * 2 + 1] + bias[col + 1];
                *(uint32_t*)&outh[(size_t)row * (2*DD) + n0 + col] = pack2h(v0, v1);
            }
}

// ---------------- embedding + positional encoding ---------------------------
__global__ void embed_kernel(const float* __restrict__ x,
                             const float* __restrict__ tokW,
                             const float* __restrict__ tokb,
                             h16* __restrict__ h)
{
    size_t idx = (size_t)blockIdx.x * 256 + threadIdx.x;
    size_t token = idx >> 7;
    int d = (int)(idx & 127);
    int t = (int)((token / NN) % TT);
    const float* xp = x + token * FINN;
    float val = xp[0]*tokW[d*3+0] + xp[1]*tokW[d*3+1] + xp[2]*tokW[d*3+2] + tokb[d];
    int i2 = d & ~1;
    float div = expf((float)i2 * (-logf(10000.0f) / (float)DD));
    float ang = (float)t * div;
    val += (d & 1) ? cosf(ang) : sinf(ang);
    h[idx] = __float2half(val);
}

// ---------------- temporal attention (T=12), vectorized fp16 qkv -------------
__global__ void temporal_attn_kernel(const h16* __restrict__ qkv,
                                     h16* __restrict__ outp)
{
    const int bidx = blockIdx.x;
    const int b = bidx >> 9, n = bidx & 511;
    const int tid = threadIdx.x;
    __shared__ float q[TT][DD+4], k[TT][DD+4], v[TT][DD+4];
    __shared__ float S[HH][TT][TT];
    // vectorized load: 12 rows x 48 uint4 chunks
    for (int i = tid; i < TT*48; i += 128) {
        int t = i / 48, c = i - (i / 48) * 48;
        uint4 vv = *(const uint4*)(qkv + ((size_t)(b*TT + t) * NN + n) * 384 + c * 8);
        h16 tmp[8]; *(uint4*)tmp = vv;
        int bc = c * 8;
        float* dst = (bc < 128) ? &q[t][bc] : (bc < 256 ? &k[t][bc-128] : &v[t][bc-256]);
#pragma unroll
        for (int z = 0; z < 8; ++z) dst[z] = __half2float(tmp[z]);
    }
    __syncthreads();
    const float scale = 0.17677669529663687f;
    for (int idx = tid; idx < HH*TT*TT; idx += 128) {
        int hh = idx / (TT*TT);
        int rem = idx - hh*(TT*TT);
        int xx = rem / TT, yy = rem - xx*TT;
        const float4* q4 = (const float4*)&q[xx][hh*32];
        const float4* k4 = (const float4*)&k[yy][hh*32];
        float s = 0.f;
#pragma unroll
        for (int e = 0; e < 8; ++e) {
            float4 qa = q4[e], kb = k4[e];
            s = fmaf(qa.x, kb.x, s); s = fmaf(qa.y, kb.y, s);
            s = fmaf(qa.z, kb.z, s); s = fmaf(qa.w, kb.w, s);
        }
        S[hh][xx][yy] = s * scale;
    }
    __syncthreads();
    if (tid < HH*TT) {
        int hh = tid / TT, xx = tid % TT;
        float mx = -1e30f;
#pragma unroll
        for (int y = 0; y < TT; ++y) mx = fmaxf(mx, S[hh][xx][y]);
        float sum = 0.f;
#pragma unroll
        for (int y = 0; y < TT; ++y) { float p = __expf(S[hh][xx][y]-mx); S[hh][xx][y] = p; sum += p; }
        float inv = 1.f / sum;
#pragma unroll
        for (int y = 0; y < TT; ++y) S[hh][xx][y] *= inv;
    }
    __syncthreads();
    const int hh = tid >> 5;
    float vr[TT];
#pragma unroll
    for (int yy = 0; yy < TT; ++yy) vr[yy] = v[yy][tid];
#pragma unroll
    for (int xx = 0; xx < TT; ++xx) {
        float o = 0.f;
#pragma unroll
        for (int yy = 0; yy < TT; ++yy) o = fmaf(S[hh][xx][yy], vr[yy], o);
        outp[((size_t)(b*TT + xx) * NN + n) * DD + tid] = __float2half(o);
    }
}

// ============ merged spatial attention (geo+sem, flash, fp16 in/out) =========
__global__ void __launch_bounds__(256, 1)
spatial_attn_mma(const h16* __restrict__ qkv,
                 h16* __restrict__ gout, h16* __restrict__ sout)
{
    const int qtile = blockIdx.x;
    const int sel   = blockIdx.y >> 2;
    const int head  = blockIdx.y & 3;
    const int bt    = blockIdx.z;
    const int tid  = threadIdx.x;
    const int wid  = tid >> 5;
    const int lane = tid & 31;
    const int l16  = lane & 15;

    h16* outp = sel ? sout : gout;
    const int colq = sel * 384 + head * 32;

    __shared__ __half Qs[128][40];
    __shared__ __half Ks[128][40];
    __shared__ __half Vt[32][136];

    const size_t base = (size_t)bt * NN;
    const float scale = 0.17677669529663687f;
    const __half2 hs2 = __floats2half2_rn(scale, scale);

    for (int i = tid; i < 128*4; i += 256) {
        int r = i >> 2, ec = (i & 3) * 8;
        uint4 vq = *(const uint4*)(qkv + (base + (size_t)qtile*128 + r)*768 + colq + ec);
        __half2* p = (__half2*)&vq;
#pragma unroll
        for (int z = 0; z < 4; ++z) p[z] = __hmul2(p[z], hs2);
        *(uint4*)&Qs[r][ec] = vq;
    }
    __syncthreads();

    uint32_t qf[2][4];
#pragma unroll
    for (int kc = 0; kc < 2; ++kc) {
        uint32_t ad = smem_u32(&Qs[wid*16 + l16][kc*16 + (lane>>4)*8]);
        asm volatile("ldmatrix.sync.aligned.m8n8.x4.shared.b16 {%0,%1,%2,%3}, [%4];"
                     : "=r"(qf[kc][0]), "=r"(qf[kc][1]), "=r"(qf[kc][2]), "=r"(qf[kc][3])
                     : "r"(ad));
    }

    float m0 = -1e30f, m1 = -1e30f, l0 = 0.f, l1 = 0.f;
    float oacc[4][4];
#pragma unroll
    for (int ef = 0; ef < 4; ++ef)
#pragma unroll
        for (int r = 0; r < 4; ++r) oacc[ef][r] = 0.f;

    for (int kt = 0; kt < 4; ++kt) {
        __syncthreads();
        for (int i = tid; i < 128*4; i += 256) {
            int j = i >> 2, ec = (i & 3) * 8;
            const h16* rp = qkv + (base + (size_t)kt*128 + j)*768 + colq + 128 + ec;
            *(uint4*)&Ks[j][ec] = *(const uint4*)rp;
            uint4 vv = *(const uint4*)(rp + 128);
            h16 tmp[8]; *(uint4*)tmp = vv;
#pragma unroll
            for (int z = 0; z < 8; ++z) Vt[ec + z][j] = tmp[z];
        }
        __syncthreads();

        float sacc[16][4];
#pragma unroll
        for (int nf = 0; nf < 16; ++nf) {
            sacc[nf][0] = sacc[nf][1] = sacc[nf][2] = sacc[nf][3] = 0.f;
#pragma unroll
            for (int kc = 0; kc < 2; ++kc) {
                uint32_t b0, b1;
                uint32_t bd = smem_u32(&Ks[nf*8 + (l16 & 7)][kc*16 + (l16 >> 3)*8]);
                asm volatile("ldmatrix.sync.aligned.m8n8.x2.shared.b16 {%0,%1}, [%2];"
                             : "=r"(b0), "=r"(b1) : "r"(bd));
                asm volatile(
                    "mma.sync.aligned.m16n8k16.row.col.f32.f16.f16.f32 "
                    "{%0,%1,%2,%3}, {%4,%5,%6,%7}, {%8,%9}, {%0,%1,%2,%3};"
                    : "+f"(sacc[nf][0]), "+f"(sacc[nf][1]),
                      "+f"(sacc[nf][2]), "+f"(sacc[nf][3])
                    : "r"(qf[kc][0]), "r"(qf[kc][1]), "r"(qf[kc][2]), "r"(qf[kc][3]),
                      "r"(b0), "r"(b1));
            }
        }

        float mx0 = -1e30f, mx1 = -1e30f;
#pragma unroll
        for (int nf = 0; nf < 16; ++nf) {
            mx0 = fmaxf(mx0, fmaxf(sacc[nf][0], sacc[nf][1]));
            mx1 = fmaxf(mx1, fmaxf(sacc[nf][2], sacc[nf][3]));
        }
        mx0 = fmaxf(mx0, __shfl_xor_sync(0xffffffffu, mx0, 1));
        mx0 = fmaxf(mx0, __shfl_xor_sync(0xffffffffu, mx0, 2));
        mx1 = fmaxf(mx1, __shfl_xor_sync(0xffffffffu, mx1, 1));
        mx1 = fmaxf(mx1, __shfl_xor_sync(0xffffffffu, mx1, 2));
        const float nm0 = fmaxf(m0, mx0), nm1 = fmaxf(m1, mx1);
        const float c0 = __expf(m0 - nm0), c1 = __expf(m1 - nm1);
        m0 = nm0; m1 = nm1;
#pragma unroll
        for (int ef = 0; ef < 4; ++ef) {
            oacc[ef][0] *= c0; oacc[ef][1] *= c0;
            oacc[ef][2] *= c1; oacc[ef][3] *= c1;
        }

        float rs0 = 0.f, rs1 = 0.f;
#pragma unroll
        for (int jc = 0; jc < 8; ++jc) {
            float p00 = __expf(sacc[2*jc][0]   - nm0);
            float p01 = __expf(sacc[2*jc][1]   - nm0);
            float p10 = __expf(sacc[2*jc][2]   - nm1);
            float p11 = __expf(sacc[2*jc][3]   - nm1);
            float p20 = __expf(sacc[2*jc+1][0] - nm0);
            float p21 = __expf(sacc[2*jc+1][1] - nm0);
            float p30 = __expf(sacc[2*jc+1][2] - nm1);
            float p31 = __expf(sacc[2*jc+1][3] - nm1);
            rs0 += p00 + p01 + p20 + p21;
            rs1 += p10 + p11 + p30 + p31;
            uint32_t pf0 = pack2h(p00, p01);
            uint32_t pf1 = pack2h(p10, p11);
            uint32_t pf2 = pack2h(p20, p21);
            uint32_t pf3 = pack2h(p30, p31);
#pragma unroll
            for (int ef = 0; ef < 4; ++ef) {
                uint32_t b0, b1;
                uint32_t bd = smem_u32(&Vt[ef*8 + (l16 & 7)][jc*16 + (l16 >> 3)*8]);
                asm volatile("ldmatrix.sync.aligned.m8n8.x2.shared.b16 {%0,%1}, [%2];"
                             : "=r"(b0), "=r"(b1) : "r"(bd));
                asm volatile(
                    "mma.sync.aligned.m16n8k16.row.col.f32.f16.f16.f32 "
                    "{%0,%1,%2,%3}, {%4,%5,%6,%7}, {%8,%9}, {%0,%1,%2,%3};"
                    : "+f"(oacc[ef][0]), "+f"(oacc[ef][1]),
                      "+f"(oacc[ef][2]), "+f"(oacc[ef][3])
                    : "r"(pf0), "r"(pf1), "r"(pf2), "r"(pf3),
                      "r"(b0), "r"(b1));
            }
        }
        rs0 += __shfl_xor_sync(0xffffffffu, rs0, 1);
        rs0 += __shfl_xor_sync(0xffffffffu, rs0, 2);
        rs1 += __shfl_xor_sync(0xffffffffu, rs1, 1);
        rs1 += __shfl_xor_sync(0xffffffffu, rs1, 2);
        l0 = l0 * c0 + rs0;
        l1 = l1 * c1 + rs1;
    }

    const float i0 = 1.f / l0, i1 = 1.f / l1;
    const int r0 = wid*16 + (lane >> 2);
#pragma unroll
    for (int ef = 0; ef < 4; ++ef) {
        const int col = head*32 + ef*8 + (lane & 3)*2;
        size_t rowA = (base + (size_t)qtile*128 + r0) * DD + col;
        size_t rowB = (base + (size_t)qtile*128 + r0 + 8) * DD + col;
        *(uint32_t*)&outp[rowA] = pack2h(oacc[ef][0] * i0, oacc[ef][1] * i0);
        *(uint32_t*)&outp[rowB] = pack2h(oacc[ef][2] * i1, oacc[ef][3] * i1);
    }
}

// ---------------- output head ------------------------------------------------
__global__ void head_kernel(const float* __restrict__ xc, const float* __restrict__ w1g,
                            const float* __restrict__ b1g, const float* __restrict__ w2g,
                            const float* __restrict__ b2g, float* __restrict__ y)
{
    const int bidx = blockIdx.x;
    const int b = bidx >> 9, n = bidx & 511;
    const int tid = threadIdx.x;
    __shared__ float xs[TT][LL*DD];
    __shared__ float w1[PP][TT];
    __shared__ float b1[PP];
    __shared__ float w2[LL*DD];
    __shared__ float red[PP][4];
    for (int t = 0; t < TT; ++t) {
        size_t rowoff = ((size_t)(b*TT + t) * NN + n) * (LL*DD);
        for (int c = tid; c < LL*DD; c += 128) xs[t][c] = xc[rowoff + c];
    }
    for (int i = tid; i < PP*TT; i += 128) w1[i/TT][i%TT] = w1g[i];
    if (tid < PP) b1[tid] = b1g[tid];
    for (int c = tid; c < LL*DD; c += 128) w2[c] = w2g[c];
    __syncthreads();

    float part[PP];
#pragma unroll
    for (int p = 0; p < PP; ++p) part[p] = 0.f;
    for (int c = tid; c < LL*DD; c += 128) {
        float xt[TT];
#pragma unroll
        for (int t = 0; t < TT; ++t) xt[t] = xs[t][c];
        float wc = w2[c];
#pragma unroll
        for (int p = 0; p < PP; ++p) {
            float sacc = b1[p];
#pragma unroll
            for (int t = 0; t < TT; ++t) sacc = fmaf(xt[t], w1[p][t], sacc);
            sacc = fmaxf(sacc, 0.f);
            part[p] = fmaf(sacc, wc, part[p]);
        }
    }
    const int warp = tid >> 5, lane = tid & 31;
#pragma unroll
    for (int p = 0; p < PP; ++p) {
        float sv = part[p];
#pragma unroll
        for (int o = 16; o; o >>= 1) sv += __shfl_xor_sync(0xffffffffu, sv, o);
        if (lane == 0) red[p][warp] = sv;
    }
    __syncthreads();
    if (tid < PP) {
        float sv = red[tid][0] + red[tid][1] + red[tid][2] + red[tid][3];
        y[(size_t)(b*PP + tid) * NN + n] = sv + b2g[0];
    }
}

// ---------------- launcher ---------------------------------------------------
extern "C" void kernel_launch(void* const* d_in, const int* in_sizes, int n_in,
                              void* d_out, int out_size)
{
    (void)in_sizes; (void)n_in; (void)out_size;
    const float* x      = (const float*)d_in[0];
    const float* tokW   = (const float*)d_in[1];
    const float* tokb   = (const float*)d_in[2];
    const float* t_qkvW = (const float*)d_in[3];
    const float* t_qkvb = (const float*)d_in[4];
    const float* t_pW   = (const float*)d_in[5];
    const float* t_pb   = (const float*)d_in[6];
    const float* g_qkvW = (const float*)d_in[7];
    const float* g_qkvb = (const float*)d_in[8];
    const float* g_pW   = (const float*)d_in[9];
    const float* g_pb   = (const float*)d_in[10];
    const float* s_qkvW = (const float*)d_in[11];
    const float* s_qkvb = (const float*)d_in[12];
    const float* s_pW   = (const float*)d_in[13];
    const float* s_pb   = (const float*)d_in[14];
    const float* resW   = (const float*)d_in[15];
    const float* resb   = (const float*)d_in[16];
    const float* normW  = (const float*)d_in[17];
    const float* normb  = (const float*)d_in[18];
    const float* fc1W   = (const float*)d_in[19];
    const float* fc1b   = (const float*)d_in[20];
    const float* fc2W   = (const float*)d_in[21];
    const float* fc2b   = (const float*)d_in[22];
    const float* e1W    = (const float*)d_in[23];
    const float* e1b    = (const float*)d_in[24];
    const float* e2W    = (const float*)d_in[25];
    const float* e2b    = (const float*)d_in[26];
    float* out = (float*)d_out;

    float *xcB, *bgsB;
    h16 *qkvB, *qkv12B;
    cudaGetSymbolAddress((void**)&qkvB,   g_qkv);
    cudaGetSymbolAddress((void**)&qkv12B, g_qkv12);
    cudaGetSymbolAddress((void**)&xcB,    g_xc);
    cudaGetSymbolAddress((void**)&bgsB,   b_gs);

    h16 *hA,*hB,*at,*a2,*ct,*ml;
    cudaGetSymbolAddress((void**)&hA, a_hA);
    cudaGetSymbolAddress((void**)&hB, a_hB);
    cudaGetSymbolAddress((void**)&at, a_at);
    cudaGetSymbolAddress((void**)&a2, a_a2);
    cudaGetSymbolAddress((void**)&ct, a_ct);
    cudaGetSymbolAddress((void**)&ml, a_ml);

    h16 *tq,*gs,*tp,*gp,*sp,*f1,*cb;
    cudaGetSymbolAddress((void**)&tq, w_tq);
    cudaGetSymbolAddress((void**)&gs, w_gs);
    cudaGetSymbolAddress((void**)&tp, w_tp);
    cudaGetSymbolAddress((void**)&gp, w_gp);
    cudaGetSymbolAddress((void**)&sp, w_sp);
    cudaGetSymbolAddress((void**)&f1, w_f1);
    cudaGetSymbolAddress((void**)&cb, w_cb);

    const int MBt = TOK / 128;
    const int DSM = 40960;

    const int CVT_N = LL*3*DD*DD + LL*6*DD*DD + 3*(LL*DD*DD) + LL*HMM*2*DD + LL*DD*(HMM+DD);
    cvt_all<<<(CVT_N+255)/256, 256>>>(t_qkvW, g_qkvW, s_qkvW, t_pW, g_pW, s_pW,
                                      fc1W, fc2W, resW, g_qkvb, s_qkvb);

    embed_kernel<<<(TOK*DD)/256, 256>>>(x, tokW, tokb, hA);

    for (int l = 0; l < LL; ++l) {
        const size_t oq = (size_t)l*3*DD*DD, oqb = (size_t)l*3*DD;
        const size_t op = (size_t)l*DD*DD,   opb = (size_t)l*DD;
        const size_t ogs = (size_t)l*6*DD*DD;

        // temporal attention
        mma_gemm<<<dim3(3, MBt), 256, DSM>>>(hA, DD, nullptr, 0, tq+oq,
                                             t_qkvb+oqb, nullptr, nullptr, qkvB, 3*DD, 0,
                                             nullptr, nullptr, nullptr, nullptr, 0);
        temporal_attn_kernel<<<BB*NN, 128>>>(qkvB, at);
        mma_gemm<<<dim3(1, MBt), 256, DSM>>>(at, DD, nullptr, 0, tp+op,
                                             t_pb+opb, nullptr, nullptr, hB, DD, 0,
                                             nullptr, nullptr, nullptr, nullptr, 0);
        // merged geo+sem qkv -> qkv12 [tok,768] fp16
        mma_gemm<<<dim3(6, MBt), 256, DSM>>>(hB, DD, nullptr, 0, gs+ogs,
                                             bgsB + (size_t)l*768, nullptr, nullptr, qkv12B, 6*DD, 0,
                                             nullptr, nullptr, nullptr, nullptr, 0);
        // merged spatial attention: geo -> at, sem -> a2
        spatial_attn_mma<<<dim3(NN/128, 2*HH, BB*TT), 256>>>(qkv12B, at, a2);
        // dual projection into cat
        mma_gemm_dual<<<dim3(2, MBt), 256>>>(at, a2, gp+op, sp+op,
                                             g_pb+opb, s_pb+opb, ct);
        // MLP fc1 (+gelu)
        mma_gemm<<<dim3(2, MBt), 256, DSM>>>(ct, 2*DD, nullptr, 0,
                                             f1+(size_t)l*HMM*2*DD,
                                             fc1b+(size_t)l*HMM, nullptr,
                                             nullptr, ml, HMM, 1,
                                             nullptr, nullptr, nullptr, nullptr, 0);
        // fused fc2 + residual-linear + LayerNorm -> hA (fp16), xc slice (fp32)
        mma_gemm<<<dim3(1, MBt), 256, DSM>>>(ml, HMM, hA, DD,
                                             cb+(size_t)l*DD*(HMM+DD),
                                             fc2b+opb, resb+opb,
                                             nullptr, nullptr, DD, 0,
                                             normW+opb, normb+opb,
                                             hA, xcB + (size_t)l*DD, LL*DD);
    }

    head_kernel<<<BB*NN, 128>>>(xcB, e1W, e1b, e2W, e2b, out);
}

// round 12
// speedup vs baseline: 1.0782x; 1.0782x over previous
#include <cuda_runtime.h>
#include <cuda_fp16.h>
#include <math.h>
#include <stdint.h>

#define BB   8
#define TT   12
#define NN   512
#define FINN 3
#define DD   128
#define HH   4
#define HMM  256
#define LL   3
#define PP   12
#define TOK  (BB*TT*NN)          // 49152 tokens

typedef __half h16;

// ---------------- scratch ----------------------------------------------------
__device__ h16   g_qkv  [TOK*3*DD];    // temporal qkv [tok,384]
__device__ h16   g_qkv12[TOK*6*DD];    // geo|sem qkv  [tok,768]
__device__ h16   g_xc [TOK*LL*DD];     // concat layer outputs (fp16)
__device__ float b_gs [LL*6*DD];       // folded gs-qkv bias
__device__ float b_12 [LL*HMM];        // folded fc1 bias
// fp16 activations
__device__ h16 a_hA[TOK*DD];
__device__ h16 a_at[TOK*DD];
__device__ h16 a_a2[TOK*DD];
__device__ h16 a_ml[TOK*HMM];
// fp16 weights
__device__ h16 w_tq[LL*3*DD*DD];
__device__ h16 w_gsF[LL*6*DD*DD];      // folded (gs_qkv . t_p)
__device__ h16 w_12F[LL*HMM*2*DD];     // folded (fc1 . [gp|sp])
__device__ h16 w_cb[LL*DD*(HMM+DD)];   // [fc2 | res]

__device__ __forceinline__ uint32_t smem_u32(const void* p) {
    uint32_t a;
    asm("{ .reg .u64 t; cvta.to.shared.u64 t, %1; cvt.u32.u64 %0, t; }"
        : "=r"(a) : "l"(p));
    return a;
}
__device__ __forceinline__ uint32_t pack2h(float a, float b) {
    __half2 h = __floats2half2_rn(a, b);
    return *(uint32_t*)&h;
}
#define CP_ASYNC16(dst, src) \
    asm volatile("cp.async.cg.shared.global [%0], [%1], 16;" :: "r"(dst), "l"(src))
#define CP_COMMIT() asm volatile("cp.async.commit_group;" ::: "memory")
#define CP_WAIT(n)  asm volatile("cp.async.wait_group %0;" :: "n"(n) : "memory")

// ================= weight conversion (tq + cb) ===============================
__global__ void cvt_all(const float* __restrict__ t_qkvW,
                        const float* __restrict__ fc2W, const float* __restrict__ resW)
{
    int i = blockIdx.x * 256 + threadIdx.x;
    const int NQ  = LL*3*DD*DD;
    const int NCB = LL*DD*(HMM+DD);
    if (i < NQ) { w_tq[i] = __float2half(t_qkvW[i]); return; }
    i -= NQ;
    if (i < NCB) {
        const int KK = HMM + DD;
        int l = i / (DD*KK), r = (i / KK) % DD, k = i % KK;
        float v = (k < HMM) ? fc2W[((size_t)l*DD + r)*HMM + k]
                            : resW[((size_t)l*DD + r)*DD + (k - HMM)];
        w_cb[i] = __float2half(v);
    }
}

// ================= fold: Wc = gsW . tpW ; bc = gsb + gsW . tpb ===============
__global__ void fold_gs(const float* __restrict__ gq, const float* __restrict__ sq,
                        const float* __restrict__ gqb, const float* __restrict__ sqb,
                        const float* __restrict__ tpW, const float* __restrict__ tpb)
{
    int i = blockIdx.x * 256 + threadIdx.x;
    if (i >= LL*768*DD) return;
    const int l = i / (768*DD);
    const int p = (i / DD) % 768;
    const int k = i % DD;
    const float* grow = (p < 384) ? gq + ((size_t)l*384 + p)*DD
                                  : sq + ((size_t)l*384 + (p-384))*DD;
    const float* tw = tpW + (size_t)l*DD*DD;   // [o][i]
    float s = 0.f;
#pragma unroll 8
    for (int o = 0; o < DD; ++o) s += grow[o] * tw[o*DD + k];
    w_gsF[i] = __float2half(s);
    if (k == 0) {
        float bb = (p < 384) ? gqb[l*384 + p] : sqb[l*384 + (p-384)];
        const float* tb = tpb + l*DD;
#pragma unroll 8
        for (int o = 0; o < DD; ++o) bb += grow[o] * tb[o];
        b_gs[l*768 + p] = bb;
    }
}

// ================= fold: W12 = f1W . [gpW | spW]; b12 ========================
__global__ void fold_f1(const float* __restrict__ f1W, const float* __restrict__ f1b,
                        const float* __restrict__ gpW, const float* __restrict__ gpb,
                        const float* __restrict__ spW, const float* __restrict__ spb)
{
    int i = blockIdx.x * 256 + threadIdx.x;
    if (i >= LL*HMM*2*DD) return;
    const int l = i / (HMM*2*DD);
    const int h = (i / (2*DD)) % HMM;
    const int k = i % (2*DD);
    const float* frow = f1W + ((size_t)l*HMM + h)*(2*DD);
    float s = 0.f;
    if (k < DD) {
        const float* pw = gpW + (size_t)l*DD*DD;      // [d][i]
#pragma unroll 8
        for (int d = 0; d < DD; ++d) s += frow[d] * pw[d*DD + k];
    } else {
        const float* pw = spW + (size_t)l*DD*DD;
#pragma unroll 8
        for (int d = 0; d < DD; ++d) s += frow[DD + d] * pw[d*DD + (k - DD)];
    }
    w_12F[i] = __float2half(s);
    if (k == 0) {
        float bb = f1b[l*HMM + h];
        const float* gb = gpb + l*DD;
        const float* sb = spb + l*DD;
#pragma unroll 8
        for (int d = 0; d < DD; ++d) bb += frow[d]*gb[d] + frow[DD + d]*sb[d];
        b_12[l*HMM + h] = bb;
    }
}

// ================= single-pass fp16 mma GEMM (+optional fused LN) ===========
__global__ void __launch_bounds__(256, 2)
mma_gemm(const h16* __restrict__ A1, int K1, const h16* __restrict__ A2, int K2,
         const h16* __restrict__ W,
         const float* __restrict__ bias, const float* __restrict__ bias2,
         h16* __restrict__ outh, int ldo, int gelu,
         const float* __restrict__ lnW, const float* __restrict__ lnB,
         h16* __restrict__ ln_hout, h16* __restrict__ ln_xc, int ldxc)
{
    extern __shared__ char dsm[];
    h16* As = (h16*)dsm;              // [2][128][40]
    h16* Bs = As + 2*5120;            // [2][128][40]
    float* stage = (float*)dsm;       // LN staging [64][132]

    const int tid  = threadIdx.x;
    const int wid  = tid >> 5;
    const int lane = tid & 31;
    const int l16  = lane & 15;
    const int warp_m = wid >> 2;
    const int warp_n = wid & 3;
    const int m0 = blockIdx.y * 128;
    const int n0 = blockIdx.x * 128;
    const int K  = K1 + K2;
    const int KC = K >> 5;

    float acc[4][4][4];
#pragma unroll
    for (int mi = 0; mi < 4; ++mi)
#pragma unroll
        for (int ni = 0; ni < 4; ++ni)
#pragma unroll
            for (int r = 0; r < 4; ++r) acc[mi][ni][r] = 0.f;

    auto load_chunk = [&](int buf, int kp) {
        const int kof = kp * 32;
        const h16* Asrc; int lda, acol;
        if (kof < K1) { Asrc = A1; lda = K1; acol = kof; }
        else          { Asrc = A2; lda = K2; acol = kof - K1; }
#pragma unroll
        for (int t = 0; t < 2; ++t) {
            const int c   = tid + t * 256;
            const int row = c >> 2;
            const int cc  = (c & 3) * 8;
            CP_ASYNC16(smem_u32(As + buf*5120 + row*40 + cc),
                       Asrc + (size_t)(m0 + row) * lda + acol + cc);
            CP_ASYNC16(smem_u32(Bs + buf*5120 + row*40 + cc),
                       W + (size_t)(n0 + row) * K + kof + cc);
        }
    };

    auto compute = [&](int buf) {
#pragma unroll
        for (int ks = 0; ks < 2; ++ks) {
            const int k = ks * 16;
            uint32_t a[4][4], b[4][2];
#pragma unroll
            for (int mi = 0; mi < 4; ++mi) {
                uint32_t ad = smem_u32(As + buf*5120 + (warp_m*64 + mi*16 + l16)*40 + k + (lane >> 4) * 8);
                asm volatile("ldmatrix.sync.aligned.m8n8.x4.shared.b16 {%0,%1,%2,%3}, [%4];"
                             : "=r"(a[mi][0]), "=r"(a[mi][1]), "=r"(a[mi][2]), "=r"(a[mi][3])
                             : "r"(ad));
            }
#pragma unroll
            for (int ni = 0; ni < 4; ++ni) {
                uint32_t bd = smem_u32(Bs + buf*5120 + (warp_n*32 + ni*8 + (l16 & 7))*40 + k + (l16 >> 3) * 8);
                asm volatile("ldmatrix.sync.aligned.m8n8.x2.shared.b16 {%0,%1}, [%2];"
                             : "=r"(b[ni][0]), "=r"(b[ni][1]) : "r"(bd));
            }
#pragma unroll
            for (int mi = 0; mi < 4; ++mi)
#pragma unroll
                for (int ni = 0; ni < 4; ++ni)
                    asm volatile(
                        "mma.sync.aligned.m16n8k16.row.col.f32.f16.f16.f32 "
                        "{%0,%1,%2,%3}, {%4,%5,%6,%7}, {%8,%9}, {%0,%1,%2,%3};"
                        : "+f"(acc[mi][ni][0]), "+f"(acc[mi][ni][1]),
                          "+f"(acc[mi][ni][2]), "+f"(acc[mi][ni][3])
                        : "r"(a[mi][0]), "r"(a[mi][1]), "r"(a[mi][2]), "r"(a[mi][3]),
                          "r"(b[ni][0]), "r"(b[ni][1]));
        }
    };

    load_chunk(0, 0);
    CP_COMMIT();
    int buf = 0;
    for (int i = 0; i < KC; ++i) {
        if (i + 1 < KC) {
            load_chunk(buf ^ 1, i + 1);
            CP_COMMIT();
            CP_WAIT(1);
        } else {
            CP_WAIT(0);
        }
        __syncthreads();
        compute(buf);
        __syncthreads();
        buf ^= 1;
    }

    const int quad = lane >> 2, qi = lane & 3;

    if (lnW == nullptr) {
#pragma unroll
        for (int mi = 0; mi < 4; ++mi)
#pragma unroll
            for (int ni = 0; ni < 4; ++ni)
#pragma unroll
                for (int h = 0; h < 2; ++h) {
                    const int row = m0 + warp_m * 64 + mi * 16 + quad + h * 8;
                    const int col = n0 + warp_n * 32 + ni * 8 + qi * 2;
                    float v0 = acc[mi][ni][h * 2 + 0] + bias[col];
                    float v1 = acc[mi][ni][h * 2 + 1] + bias[col + 1];
                    if (gelu) {
                        v0 = 0.5f * v0 * (1.0f + erff(v0 * 0.70710678118654752f));
                        v1 = 0.5f * v1 * (1.0f + erff(v1 * 0.70710678118654752f));
                    }
                    *(uint32_t*)&outh[(size_t)row * ldo + col] = pack2h(v0, v1);
                }
    } else {
        // fused LayerNorm epilogue (gridDim.x==1, N=128)
#pragma unroll
        for (int half = 0; half < 2; ++half) {
            __syncthreads();
            if (warp_m == half) {
#pragma unroll
                for (int mi = 0; mi < 4; ++mi)
#pragma unroll
                    for (int ni = 0; ni < 4; ++ni)
#pragma unroll
                        for (int h = 0; h < 2; ++h) {
                            const int rl  = mi * 16 + quad + h * 8;
                            const int col = warp_n * 32 + ni * 8 + qi * 2;
                            stage[rl * 132 + col]     = acc[mi][ni][h*2+0] + bias[col]   + bias2[col];
                            stage[rl * 132 + col + 1] = acc[mi][ni][h*2+1] + bias[col+1] + bias2[col+1];
                        }
            }
            __syncthreads();
#pragma unroll
            for (int rr = 0; rr < 8; ++rr) {
                const int rl = wid * 8 + rr;
                float v[4];
#pragma unroll
                for (int i = 0; i < 4; ++i) v[i] = stage[rl * 132 + lane + 32 * i];
                float s = v[0] + v[1] + v[2] + v[3];
#pragma unroll
                for (int o = 16; o; o >>= 1) s += __shfl_xor_sync(0xffffffffu, s, o);
                const float mean = s * (1.f / 128.f);
                float q = 0.f;
#pragma unroll
                for (int i = 0; i < 4; ++i) { v[i] -= mean; q += v[i] * v[i]; }
#pragma unroll
                for (int o = 16; o; o >>= 1) q += __shfl_xor_sync(0xffffffffu, q, o);
                const float inv = rsqrtf(q * (1.f / 128.f) + 1e-5f);
                const size_t row = (size_t)(m0 + half * 64 + rl);
#pragma unroll
                for (int i = 0; i < 4; ++i) {
                    const int d = lane + 32 * i;
                    const float o = v[i] * inv * lnW[d] + lnB[d];
                    ln_hout[row * DD + d]  = __float2half(o);
                    ln_xc[row * ldxc + d]  = __float2half(o);
                }
            }
        }
    }
}

// ---------------- embedding + positional encoding ---------------------------
__global__ void embed_kernel(const float* __restrict__ x,
                             const float* __restrict__ tokW,
                             const float* __restrict__ tokb,
                             h16* __restrict__ h)
{
    size_t idx = (size_t)blockIdx.x * 256 + threadIdx.x;
    size_t token = idx >> 7;
    int d = (int)(idx & 127);
    int t = (int)((token / NN) % TT);
    const float* xp = x + token * FINN;
    float val = xp[0]*tokW[d*3+0] + xp[1]*tokW[d*3+1] + xp[2]*tokW[d*3+2] + tokb[d];
    int i2 = d & ~1;
    float div = expf((float)i2 * (-logf(10000.0f) / (float)DD));
    float ang = (float)t * div;
    val += (d & 1) ? cosf(ang) : sinf(ang);
    h[idx] = __float2half(val);
}

// ---------------- temporal attention (T=12) ----------------------------------
__global__ void temporal_attn_kernel(const h16* __restrict__ qkv,
                                     h16* __restrict__ outp)
{
    const int bidx = blockIdx.x;
    const int b = bidx >> 9, n = bidx & 511;
    const int tid = threadIdx.x;
    __shared__ float q[TT][DD+4], k[TT][DD+4], v[TT][DD+4];
    __shared__ float S[HH][TT][TT];
#pragma unroll
    for (int t = 0; t < TT; ++t) {
        size_t row = ((size_t)(b*TT + t) * NN + n) * 384;
        q[t][tid] = __half2float(qkv[row + tid]);
        k[t][tid] = __half2float(qkv[row + 128 + tid]);
        v[t][tid] = __half2float(qkv[row + 256 + tid]);
    }
    __syncthreads();
    const float scale = 0.17677669529663687f;
    for (int idx = tid; idx < HH*TT*TT; idx += 128) {
        int hh = idx / (TT*TT);
        int rem = idx - hh*(TT*TT);
        int xx = rem / TT, yy = rem - xx*TT;
        const float4* q4 = (const float4*)&q[xx][hh*32];
        const float4* k4 = (const float4*)&k[yy][hh*32];
        float s = 0.f;
#pragma unroll
        for (int e = 0; e < 8; ++e) {
            float4 qa = q4[e], kb = k4[e];
            s = fmaf(qa.x, kb.x, s); s = fmaf(qa.y, kb.y, s);
            s = fmaf(qa.z, kb.z, s); s = fmaf(qa.w, kb.w, s);
        }
        S[hh][xx][yy] = s * scale;
    }
    __syncthreads();
    if (tid < HH*TT) {
        int hh = tid / TT, xx = tid % TT;
        float mx = -1e30f;
#pragma unroll
        for (int y = 0; y < TT; ++y) mx = fmaxf(mx, S[hh][xx][y]);
        float sum = 0.f;
#pragma unroll
        for (int y = 0; y < TT; ++y) { float p = __expf(S[hh][xx][y]-mx); S[hh][xx][y] = p; sum += p; }
        float inv = 1.f / sum;
#pragma unroll
        for (int y = 0; y < TT; ++y) S[hh][xx][y] *= inv;
    }
    __syncthreads();
    const int hh = tid >> 5;
    float vr[TT];
#pragma unroll
    for (int yy = 0; yy < TT; ++yy) vr[yy] = v[yy][tid];
#pragma unroll
    for (int xx = 0; xx < TT; ++xx) {
        float o = 0.f;
#pragma unroll
        for (int yy = 0; yy < TT; ++yy) o = fmaf(S[hh][xx][yy], vr[yy], o);
        outp[((size_t)(b*TT + xx) * NN + n) * DD + tid] = __float2half(o);
    }
}

// ============ merged spatial attention (geo+sem, flash, fp16 in/out) =========
__global__ void __launch_bounds__(256, 1)
spatial_attn_mma(const h16* __restrict__ qkv,
                 h16* __restrict__ gout, h16* __restrict__ sout)
{
    const int qtile = blockIdx.x;
    const int sel   = blockIdx.y >> 2;
    const int head  = blockIdx.y & 3;
    const int bt    = blockIdx.z;
    const int tid  = threadIdx.x;
    const int wid  = tid >> 5;
    const int lane = tid & 31;
    const int l16  = lane & 15;

    h16* outp = sel ? sout : gout;
    const int colq = sel * 384 + head * 32;

    __shared__ __half Qs[128][40];
    __shared__ __half Ks[128][40];
    __shared__ __half Vt[32][136];

    const size_t base = (size_t)bt * NN;
    const float scale = 0.17677669529663687f;
    const __half2 hs2 = __floats2half2_rn(scale, scale);

    for (int i = tid; i < 128*4; i += 256) {
        int r = i >> 2, ec = (i & 3) * 8;
        uint4 vq = *(const uint4*)(qkv + (base + (size_t)qtile*128 + r)*768 + colq + ec);
        __half2* p = (__half2*)&vq;
#pragma unroll
        for (int z = 0; z < 4; ++z) p[z] = __hmul2(p[z], hs2);
        *(uint4*)&Qs[r][ec] = vq;
    }
    __syncthreads();

    uint32_t qf[2][4];
#pragma unroll
    for (int kc = 0; kc < 2; ++kc) {
        uint32_t ad = smem_u32(&Qs[wid*16 + l16][kc*16 + (lane>>4)*8]);
        asm volatile("ldmatrix.sync.aligned.m8n8.x4.shared.b16 {%0,%1,%2,%3}, [%4];"
                     : "=r"(qf[kc][0]), "=r"(qf[kc][1]), "=r"(qf[kc][2]), "=r"(qf[kc][3])
                     : "r"(ad));
    }

    float m0 = -1e30f, m1 = -1e30f, l0 = 0.f, l1 = 0.f;
    float oacc[4][4];
#pragma unroll
    for (int ef = 0; ef < 4; ++ef)
#pragma unroll
        for (int r = 0; r < 4; ++r) oacc[ef][r] = 0.f;

    for (int kt = 0; kt < 4; ++kt) {
        __syncthreads();
        for (int i = tid; i < 128*4; i += 256) {
            int j = i >> 2, ec = (i & 3) * 8;
            const h16* rp = qkv + (base + (size_t)kt*128 + j)*768 + colq + 128 + ec;
            *(uint4*)&Ks[j][ec] = *(const uint4*)rp;
            uint4 vv = *(const uint4*)(rp + 128);
            h16 tmp[8]; *(uint4*)tmp = vv;
#pragma unroll
            for (int z = 0; z < 8; ++z) Vt[ec + z][j] = tmp[z];
        }
        __syncthreads();

        float sacc[16][4];
#pragma unroll
        for (int nf = 0; nf < 16; ++nf) {
            sacc[nf][0] = sacc[nf][1] = sacc[nf][2] = sacc[nf][3] = 0.f;
#pragma unroll
            for (int kc = 0; kc < 2; ++kc) {
                uint32_t b0, b1;
                uint32_t bd = smem_u32(&Ks[nf*8 + (l16 & 7)][kc*16 + (l16 >> 3)*8]);
                asm volatile("ldmatrix.sync.aligned.m8n8.x2.shared.b16 {%0,%1}, [%2];"
                             : "=r"(b0), "=r"(b1) : "r"(bd));
                asm volatile(
                    "mma.sync.aligned.m16n8k16.row.col.f32.f16.f16.f32 "
                    "{%0,%1,%2,%3}, {%4,%5,%6,%7}, {%8,%9}, {%0,%1,%2,%3};"
                    : "+f"(sacc[nf][0]), "+f"(sacc[nf][1]),
                      "+f"(sacc[nf][2]), "+f"(sacc[nf][3])
                    : "r"(qf[kc][0]), "r"(qf[kc][1]), "r"(qf[kc][2]), "r"(qf[kc][3]),
                      "r"(b0), "r"(b1));
            }
        }

        float mx0 = -1e30f, mx1 = -1e30f;
#pragma unroll
        for (int nf = 0; nf < 16; ++nf) {
            mx0 = fmaxf(mx0, fmaxf(sacc[nf][0], sacc[nf][1]));
            mx1 = fmaxf(mx1, fmaxf(sacc[nf][2], sacc[nf][3]));
        }
        mx0 = fmaxf(mx0, __shfl_xor_sync(0xffffffffu, mx0, 1));
        mx0 = fmaxf(mx0, __shfl_xor_sync(0xffffffffu, mx0, 2));
        mx1 = fmaxf(mx1, __shfl_xor_sync(0xffffffffu, mx1, 1));
        mx1 = fmaxf(mx1, __shfl_xor_sync(0xffffffffu, mx1, 2));
        const float nm0 = fmaxf(m0, mx0), nm1 = fmaxf(m1, mx1);
        const float c0 = __expf(m0 - nm0), c1 = __expf(m1 - nm1);
        m0 = nm0; m1 = nm1;
#pragma unroll
        for (int ef = 0; ef < 4; ++ef) {
            oacc[ef][0] *= c0; oacc[ef][1] *= c0;
            oacc[ef][2] *= c1; oacc[ef][3] *= c1;
        }

        float rs0 = 0.f, rs1 = 0.f;
#pragma unroll
        for (int jc = 0; jc < 8; ++jc) {
            float p00 = __expf(sacc[2*jc][0]   - nm0);
            float p01 = __expf(sacc[2*jc][1]   - nm0);
            float p10 = __expf(sacc[2*jc][2]   - nm1);
            float p11 = __expf(sacc[2*jc][3]   - nm1);
            float p20 = __expf(sacc[2*jc+1][0] - nm0);
            float p21 = __expf(sacc[2*jc+1][1] - nm0);
            float p30 = __expf(sacc[2*jc+1][2] - nm1);
            float p31 = __expf(sacc[2*jc+1][3] - nm1);
            rs0 += p00 + p01 + p20 + p21;
            rs1 += p10 + p11 + p30 + p31;
            uint32_t pf0 = pack2h(p00, p01);
            uint32_t pf1 = pack2h(p10, p11);
            uint32_t pf2 = pack2h(p20, p21);
            uint32_t pf3 = pack2h(p30, p31);
#pragma unroll
            for (int ef = 0; ef < 4; ++ef) {
                uint32_t b0, b1;
                uint32_t bd = smem_u32(&Vt[ef*8 + (l16 & 7)][jc*16 + (l16 >> 3)*8]);
                asm volatile("ldmatrix.sync.aligned.m8n8.x2.shared.b16 {%0,%1}, [%2];"
                             : "=r"(b0), "=r"(b1) : "r"(bd));
                asm volatile(
                    "mma.sync.aligned.m16n8k16.row.col.f32.f16.f16.f32 "
                    "{%0,%1,%2,%3}, {%4,%5,%6,%7}, {%8,%9}, {%0,%1,%2,%3};"
                    : "+f"(oacc[ef][0]), "+f"(oacc[ef][1]),
                      "+f"(oacc[ef][2]), "+f"(oacc[ef][3])
                    : "r"(pf0), "r"(pf1), "r"(pf2), "r"(pf3),
                      "r"(b0), "r"(b1));
            }
        }
        rs0 += __shfl_xor_sync(0xffffffffu, rs0, 1);
        rs0 += __shfl_xor_sync(0xffffffffu, rs0, 2);
        rs1 += __shfl_xor_sync(0xffffffffu, rs1, 1);
        rs1 += __shfl_xor_sync(0xffffffffu, rs1, 2);
        l0 = l0 * c0 + rs0;
        l1 = l1 * c1 + rs1;
    }

    const float i0 = 1.f / l0, i1 = 1.f / l1;
    const int r0 = wid*16 + (lane >> 2);
#pragma unroll
    for (int ef = 0; ef < 4; ++ef) {
        const int col = head*32 + ef*8 + (lane & 3)*2;
        size_t rowA = (base + (size_t)qtile*128 + r0) * DD + col;
        size_t rowB = (base + (size_t)qtile*128 + r0 + 8) * DD + col;
        *(uint32_t*)&outp[rowA] = pack2h(oacc[ef][0] * i0, oacc[ef][1] * i0);
        *(uint32_t*)&outp[rowB] = pack2h(oacc[ef][2] * i1, oacc[ef][3] * i1);
    }
}

// ---------------- output head (fp16 xc) ---------------------------------------
__global__ void head_kernel(const h16* __restrict__ xc, const float* __restrict__ w1g,
                            const float* __restrict__ b1g, const float* __restrict__ w2g,
                            const float* __restrict__ b2g, float* __restrict__ y)
{
    const int bidx = blockIdx.x;
    const int b = bidx >> 9, n = bidx & 511;
    const int tid = threadIdx.x;
    __shared__ float xs[TT][LL*DD];
    __shared__ float w1[PP][TT];
    __shared__ float b1[PP];
    __shared__ float w2[LL*DD];
    __shared__ float red[PP][4];
    for (int t = 0; t < TT; ++t) {
        size_t rowoff = ((size_t)(b*TT + t) * NN + n) * (LL*DD);
        for (int c = tid; c < LL*DD; c += 128) xs[t][c] = __half2float(xc[rowoff + c]);
    }
    for (int i = tid; i < PP*TT; i += 128) w1[i/TT][i%TT] = w1g[i];
    if (tid < PP) b1[tid] = b1g[tid];
    for (int c = tid; c < LL*DD; c += 128) w2[c] = w2g[c];
    __syncthreads();

    float part[PP];
#pragma unroll
    for (int p = 0; p < PP; ++p) part[p] = 0.f;
    for (int c = tid; c < LL*DD; c += 128) {
        float xt[TT];
#pragma unroll
        for (int t = 0; t < TT; ++t) xt[t] = xs[t][c];
        float wc = w2[c];
#pragma unroll
        for (int p = 0; p < PP; ++p) {
            float sacc = b1[p];
#pragma unroll
            for (int t = 0; t < TT; ++t) sacc = fmaf(xt[t], w1[p][t], sacc);
            sacc = fmaxf(sacc, 0.f);
            part[p] = fmaf(sacc, wc, part[p]);
        }
    }
    const int warp = tid >> 5, lane = tid & 31;
#pragma unroll
    for (int p = 0; p < PP; ++p) {
        float sv = part[p];
#pragma unroll
        for (int o = 16; o; o >>= 1) sv += __shfl_xor_sync(0xffffffffu, sv, o);
        if (lane == 0) red[p][warp] = sv;
    }
    __syncthreads();
    if (tid < PP) {
        float sv = red[tid][0] + red[tid][1] + red[tid][2] + red[tid][3];
        y[(size_t)(b*PP + tid) * NN + n] = sv + b2g[0];
    }
}

// ---------------- launcher ---------------------------------------------------
extern "C" void kernel_launch(void* const* d_in, const int* in_sizes, int n_in,
                              void* d_out, int out_size)
{
    (void)in_sizes; (void)n_in; (void)out_size;
    const float* x      = (const float*)d_in[0];
    const float* tokW   = (const float*)d_in[1];
    const float* tokb   = (const float*)d_in[2];
    const float* t_qkvW = (const float*)d_in[3];
    const float* t_qkvb = (const float*)d_in[4];
    const float* t_pW   = (const float*)d_in[5];
    const float* t_pb   = (const float*)d_in[6];
    const float* g_qkvW = (const float*)d_in[7];
    const float* g_qkvb = (const float*)d_in[8];
    const float* g_pW   = (const float*)d_in[9];
    const float* g_pb   = (const float*)d_in[10];
    const float* s_qkvW = (const float*)d_in[11];
    const float* s_qkvb = (const float*)d_in[12];
    const float* s_pW   = (const float*)d_in[13];
    const float* s_pb   = (const float*)d_in[14];
    const float* resW   = (const float*)d_in[15];
    const float* resb   = (const float*)d_in[16];
    const float* normW  = (const float*)d_in[17];
    const float* normb  = (const float*)d_in[18];
    const float* fc1W   = (const float*)d_in[19];
    const float* fc1b   = (const float*)d_in[20];
    const float* fc2W   = (const float*)d_in[21];
    const float* fc2b   = (const float*)d_in[22];
    const float* e1W    = (const float*)d_in[23];
    const float* e1b    = (const float*)d_in[24];
    const float* e2W    = (const float*)d_in[25];
    const float* e2b    = (const float*)d_in[26];
    float* out = (float*)d_out;

    float *bgsB, *b12B;
    h16 *qkvB, *qkv12B, *xcB;
    cudaGetSymbolAddress((void**)&qkvB,   g_qkv);
    cudaGetSymbolAddress((void**)&qkv12B, g_qkv12);
    cudaGetSymbolAddress((void**)&xcB,    g_xc);
    cudaGetSymbolAddress((void**)&bgsB,   b_gs);
    cudaGetSymbolAddress((void**)&b12B,   b_12);

    h16 *hA,*at,*a2,*ml;
    cudaGetSymbolAddress((void**)&hA, a_hA);
    cudaGetSymbolAddress((void**)&at, a_at);
    cudaGetSymbolAddress((void**)&a2, a_a2);
    cudaGetSymbolAddress((void**)&ml, a_ml);

    h16 *tq,*gsF,*w12,*cb;
    cudaGetSymbolAddress((void**)&tq,  w_tq);
    cudaGetSymbolAddress((void**)&gsF, w_gsF);
    cudaGetSymbolAddress((void**)&w12, w_12F);
    cudaGetSymbolAddress((void**)&cb,  w_cb);

    const int MBt = TOK / 128;
    const int DSM = 40960;

    const int CVT_N = LL*3*DD*DD + LL*DD*(HMM+DD);
    cvt_all<<<(CVT_N+255)/256, 256>>>(t_qkvW, fc2W, resW);
    fold_gs<<<(LL*768*DD+255)/256, 256>>>(g_qkvW, s_qkvW, g_qkvb, s_qkvb, t_pW, t_pb);
    fold_f1<<<(LL*HMM*2*DD+255)/256, 256>>>(fc1W, fc1b, g_pW, g_pb, s_pW, s_pb);

    embed_kernel<<<(TOK*DD)/256, 256>>>(x, tokW, tokb, hA);

    for (int l = 0; l < LL; ++l) {
        const size_t oq = (size_t)l*3*DD*DD, oqb = (size_t)l*3*DD;
        const size_t opb = (size_t)l*DD;
        const size_t ogs = (size_t)l*6*DD*DD;

        // temporal qkv
        mma_gemm<<<dim3(3, MBt), 256, DSM>>>(hA, DD, nullptr, 0, tq+oq,
                                             t_qkvb+oqb, nullptr, qkvB, 3*DD, 0,
                                             nullptr, nullptr, nullptr, nullptr, 0);
        temporal_attn_kernel<<<BB*NN, 128>>>(qkvB, at);
        // folded (t_p . gs_qkv): qkv12 = at @ Wc^T + bc
        mma_gemm<<<dim3(6, MBt), 256, DSM>>>(at, DD, nullptr, 0, gsF+ogs,
                                             bgsB + (size_t)l*768, nullptr, qkv12B, 6*DD, 0,
                                             nullptr, nullptr, nullptr, nullptr, 0);
        // merged spatial attention: geo -> at, sem -> a2
        spatial_attn_mma<<<dim3(NN/128, 2*HH, BB*TT), 256>>>(qkv12B, at, a2);
        // folded (proj . fc1) + gelu: ml = gelu(at@W1^T + a2@W2^T + b12)
        mma_gemm<<<dim3(2, MBt), 256, DSM>>>(at, DD, a2, DD,
                                             w12+(size_t)l*HMM*2*DD,
                                             b12B+(size_t)l*HMM, nullptr,
                                             ml, HMM, 1,
                                             nullptr, nullptr, nullptr, nullptr, 0);
        // fused fc2 + residual-linear + LayerNorm -> hA (fp16), xc slice (fp16)
        mma_gemm<<<dim3(1, MBt), 256, DSM>>>(ml, HMM, hA, DD,
                                             cb+(size_t)l*DD*(HMM+DD),
                                             fc2b+opb, resb+opb,
                                             nullptr, DD, 0,
                                             normW+opb, normb+opb,
                                             hA, xcB + (size_t)l*DD, LL*DD);
    }

    head_kernel<<<BB*NN, 128>>>(xcB, e1W, e1b, e2W, e2b, out);
}

// round 13
// speedup vs baseline: 1.2725x; 1.1801x over previous
#include <cuda_runtime.h>
#include <cuda_fp16.h>
#include <math.h>
#include <stdint.h>

#define BB   8
#define TT   12
#define NN   512
#define FINN 3
#define DD   128
#define HH   4
#define HMM  256
#define LL   3
#define PP   12
#define TOK  (BB*TT*NN)          // 49152 tokens

typedef __half h16;

// ---------------- scratch ----------------------------------------------------
__device__ h16   g_qkv  [TOK*3*DD];    // temporal qkv [tok,384]
__device__ h16   g_qkv12[TOK*6*DD];    // geo|sem qkv  [tok,768]
__device__ h16   g_xc [TOK*LL*DD];     // concat layer outputs (fp16)
__device__ float b_gs [LL*6*DD];       // folded gs-qkv bias
__device__ float b_12 [LL*HMM];        // folded fc1 bias
__device__ float g_pe [TT*DD];         // positional encoding table
// fp16 activations
__device__ h16 a_hA[TOK*DD];
__device__ h16 a_at[TOK*DD];
__device__ h16 a_a2[TOK*DD];
__device__ h16 a_ml[TOK*HMM];
// fp16 weights
__device__ h16 w_tq[LL*3*DD*DD];
__device__ h16 w_gsF[LL*6*DD*DD];      // folded (gs_qkv . t_p)
__device__ h16 w_12F[LL*HMM*2*DD];     // folded (fc1 . [gp|sp])
__device__ h16 w_cb[LL*DD*(HMM+DD)];   // [fc2 | res]

__device__ __forceinline__ uint32_t smem_u32(const void* p) {
    uint32_t a;
    asm("{ .reg .u64 t; cvta.to.shared.u64 t, %1; cvt.u32.u64 %0, t; }"
        : "=r"(a) : "l"(p));
    return a;
}
__device__ __forceinline__ uint32_t pack2h(float a, float b) {
    __half2 h = __floats2half2_rn(a, b);
    return *(uint32_t*)&h;
}
#define CP_ASYNC16(dst, src) \
    asm volatile("cp.async.cg.shared.global [%0], [%1], 16;" :: "r"(dst), "l"(src))
#define CP_COMMIT() asm volatile("cp.async.commit_group;" ::: "memory")
#define CP_WAIT(n)  asm volatile("cp.async.wait_group %0;" :: "n"(n) : "memory")

// ================= PE table ===================================================
__global__ void pe_kernel()
{
    int i = blockIdx.x * 256 + threadIdx.x;
    if (i >= TT*DD) return;
    int t = i / DD, d = i % DD;
    int i2 = d & ~1;
    float div = expf((float)i2 * (-logf(10000.0f) / (float)DD));
    float ang = (float)t * div;
    g_pe[i] = (d & 1) ? cosf(ang) : sinf(ang);
}

// ================= weight conversion (tq + cb) ===============================
__global__ void cvt_all(const float* __restrict__ t_qkvW,
                        const float* __restrict__ fc2W, const float* __restrict__ resW)
{
    int i = blockIdx.x * 256 + threadIdx.x;
    const int NQ  = LL*3*DD*DD;
    const int NCB = LL*DD*(HMM+DD);
    if (i < NQ) { w_tq[i] = __float2half(t_qkvW[i]); return; }
    i -= NQ;
    if (i < NCB) {
        const int KK = HMM + DD;
        int l = i / (DD*KK), r = (i / KK) % DD, k = i % KK;
        float v = (k < HMM) ? fc2W[((size_t)l*DD + r)*HMM + k]
                            : resW[((size_t)l*DD + r)*DD + (k - HMM)];
        w_cb[i] = __float2half(v);
    }
}

// ================= fold: Wc = gsW . tpW ; bc = gsb + gsW . tpb ===============
__global__ void fold_gs(const float* __restrict__ gq, const float* __restrict__ sq,
                        const float* __restrict__ gqb, const float* __restrict__ sqb,
                        const float* __restrict__ tpW, const float* __restrict__ tpb)
{
    int i = blockIdx.x * 256 + threadIdx.x;
    if (i >= LL*768*DD) return;
    const int l = i / (768*DD);
    const int p = (i / DD) % 768;
    const int k = i % DD;
    const float* grow = (p < 384) ? gq + ((size_t)l*384 + p)*DD
                                  : sq + ((size_t)l*384 + (p-384))*DD;
    const float* tw = tpW + (size_t)l*DD*DD;   // [o][i]
    float s = 0.f;
#pragma unroll 8
    for (int o = 0; o < DD; ++o) s += grow[o] * tw[o*DD + k];
    w_gsF[i] = __float2half(s);
    if (k == 0) {
        float bb = (p < 384) ? gqb[l*384 + p] : sqb[l*384 + (p-384)];
        const float* tb = tpb + l*DD;
#pragma unroll 8
        for (int o = 0; o < DD; ++o) bb += grow[o] * tb[o];
        b_gs[l*768 + p] = bb;
    }
}

// ================= fold: W12 = f1W . [gpW | spW]; b12 ========================
__global__ void fold_f1(const float* __restrict__ f1W, const float* __restrict__ f1b,
                        const float* __restrict__ gpW, const float* __restrict__ gpb,
                        const float* __restrict__ spW, const float* __restrict__ spb)
{
    int i = blockIdx.x * 256 + threadIdx.x;
    if (i >= LL*HMM*2*DD) return;
    const int l = i / (HMM*2*DD);
    const int h = (i / (2*DD)) % HMM;
    const int k = i % (2*DD);
    const float* frow = f1W + ((size_t)l*HMM + h)*(2*DD);
    float s = 0.f;
    if (k < DD) {
        const float* pw = gpW + (size_t)l*DD*DD;
#pragma unroll 8
        for (int d = 0; d < DD; ++d) s += frow[d] * pw[d*DD + k];
    } else {
        const float* pw = spW + (size_t)l*DD*DD;
#pragma unroll 8
        for (int d = 0; d < DD; ++d) s += frow[DD + d] * pw[d*DD + (k - DD)];
    }
    w_12F[i] = __float2half(s);
    if (k == 0) {
        float bb = f1b[l*HMM + h];
        const float* gb = gpb + l*DD;
        const float* sb = spb + l*DD;
#pragma unroll 8
        for (int d = 0; d < DD; ++d) bb += frow[d]*gb[d] + frow[DD + d]*sb[d];
        b_12[l*HMM + h] = bb;
    }
}

// ================= single-pass fp16 mma GEMM (+optional fused LN) ===========
__global__ void __launch_bounds__(256, 2)
mma_gemm(const h16* __restrict__ A1, int K1, const h16* __restrict__ A2, int K2,
         const h16* __restrict__ W,
         const float* __restrict__ bias, const float* __restrict__ bias2,
         h16* __restrict__ outh, int ldo, int gelu,
         const float* __restrict__ lnW, const float* __restrict__ lnB,
         h16* __restrict__ ln_hout, h16* __restrict__ ln_xc, int ldxc)
{
    extern __shared__ char dsm[];
    h16* As = (h16*)dsm;              // [2][128][40]
    h16* Bs = As + 2*5120;            // [2][128][40]
    float* stage = (float*)dsm;       // LN staging [64][132]

    const int tid  = threadIdx.x;
    const int wid  = tid >> 5;
    const int lane = tid & 31;
    const int l16  = lane & 15;
    const int warp_m = wid >> 2;
    const int warp_n = wid & 3;
    const int m0 = blockIdx.y * 128;
    const int n0 = blockIdx.x * 128;
    const int K  = K1 + K2;
    const int KC = K >> 5;

    float acc[4][4][4];
#pragma unroll
    for (int mi = 0; mi < 4; ++mi)
#pragma unroll
        for (int ni = 0; ni < 4; ++ni)
#pragma unroll
            for (int r = 0; r < 4; ++r) acc[mi][ni][r] = 0.f;

    auto load_chunk = [&](int buf, int kp) {
        const int kof = kp * 32;
        const h16* Asrc; int lda, acol;
        if (kof < K1) { Asrc = A1; lda = K1; acol = kof; }
        else          { Asrc = A2; lda = K2; acol = kof - K1; }
#pragma unroll
        for (int t = 0; t < 2; ++t) {
            const int c   = tid + t * 256;
            const int row = c >> 2;
            const int cc  = (c & 3) * 8;
            CP_ASYNC16(smem_u32(As + buf*5120 + row*40 + cc),
                       Asrc + (size_t)(m0 + row) * lda + acol + cc);
            CP_ASYNC16(smem_u32(Bs + buf*5120 + row*40 + cc),
                       W + (size_t)(n0 + row) * K + kof + cc);
        }
    };

    auto compute = [&](int buf) {
#pragma unroll
        for (int ks = 0; ks < 2; ++ks) {
            const int k = ks * 16;
            uint32_t a[4][4], b[4][2];
#pragma unroll
            for (int mi = 0; mi < 4; ++mi) {
                uint32_t ad = smem_u32(As + buf*5120 + (warp_m*64 + mi*16 + l16)*40 + k + (lane >> 4) * 8);
                asm volatile("ldmatrix.sync.aligned.m8n8.x4.shared.b16 {%0,%1,%2,%3}, [%4];"
                             : "=r"(a[mi][0]), "=r"(a[mi][1]), "=r"(a[mi][2]), "=r"(a[mi][3])
                             : "r"(ad));
            }
#pragma unroll
            for (int ni = 0; ni < 4; ++ni) {
                uint32_t bd = smem_u32(Bs + buf*5120 + (warp_n*32 + ni*8 + (l16 & 7))*40 + k + (l16 >> 3) * 8);
                asm volatile("ldmatrix.sync.aligned.m8n8.x2.shared.b16 {%0,%1}, [%2];"
                             : "=r"(b[ni][0]), "=r"(b[ni][1]) : "r"(bd));
            }
#pragma unroll
            for (int mi = 0; mi < 4; ++mi)
#pragma unroll
                for (int ni = 0; ni < 4; ++ni)
                    asm volatile(
                        "mma.sync.aligned.m16n8k16.row.col.f32.f16.f16.f32 "
                        "{%0,%1,%2,%3}, {%4,%5,%6,%7}, {%8,%9}, {%0,%1,%2,%3};"
                        : "+f"(acc[mi][ni][0]), "+f"(acc[mi][ni][1]),
                          "+f"(acc[mi][ni][2]), "+f"(acc[mi][ni][3])
                        : "r"(a[mi][0]), "r"(a[mi][1]), "r"(a[mi][2]), "r"(a[mi][3]),
                          "r"(b[ni][0]), "r"(b[ni][1]));
        }
    };

    load_chunk(0, 0);
    CP_COMMIT();
    int buf = 0;
    for (int i = 0; i < KC; ++i) {
        if (i + 1 < KC) {
            load_chunk(buf ^ 1, i + 1);
            CP_COMMIT();
            CP_WAIT(1);
        } else {
            CP_WAIT(0);
        }
        __syncthreads();
        compute(buf);
        __syncthreads();
        buf ^= 1;
    }

    const int quad = lane >> 2, qi = lane & 3;

    if (lnW == nullptr) {
#pragma unroll
        for (int mi = 0; mi < 4; ++mi)
#pragma unroll
            for (int ni = 0; ni < 4; ++ni)
#pragma unroll
                for (int h = 0; h < 2; ++h) {
                    const int row = m0 + warp_m * 64 + mi * 16 + quad + h * 8;
                    const int col = n0 + warp_n * 32 + ni * 8 + qi * 2;
                    float v0 = acc[mi][ni][h * 2 + 0] + bias[col];
                    float v1 = acc[mi][ni][h * 2 + 1] + bias[col + 1];
                    if (gelu) {
                        v0 = 0.5f * v0 * (1.0f + erff(v0 * 0.70710678118654752f));
                        v1 = 0.5f * v1 * (1.0f + erff(v1 * 0.70710678118654752f));
                    }
                    *(uint32_t*)&outh[(size_t)row * ldo + col] = pack2h(v0, v1);
                }
    } else {
        // fused LayerNorm epilogue (gridDim.x==1, N=128)
#pragma unroll
        for (int half = 0; half < 2; ++half) {
            __syncthreads();
            if (warp_m == half) {
#pragma unroll
                for (int mi = 0; mi < 4; ++mi)
#pragma unroll
                    for (int ni = 0; ni < 4; ++ni)
#pragma unroll
                        for (int h = 0; h < 2; ++h) {
                            const int rl  = mi * 16 + quad + h * 8;
                            const int col = warp_n * 32 + ni * 8 + qi * 2;
                            stage[rl * 132 + col]     = acc[mi][ni][h*2+0] + bias[col]   + bias2[col];
                            stage[rl * 132 + col + 1] = acc[mi][ni][h*2+1] + bias[col+1] + bias2[col+1];
                        }
            }
            __syncthreads();
#pragma unroll
            for (int rr = 0; rr < 8; ++rr) {
                const int rl = wid * 8 + rr;
                float v[4];
#pragma unroll
                for (int i = 0; i < 4; ++i) v[i] = stage[rl * 132 + lane + 32 * i];
                float s = v[0] + v[1] + v[2] + v[3];
#pragma unroll
                for (int o = 16; o; o >>= 1) s += __shfl_xor_sync(0xffffffffu, s, o);
                const float mean = s * (1.f / 128.f);
                float q = 0.f;
#pragma unroll
                for (int i = 0; i < 4; ++i) { v[i] -= mean; q += v[i] * v[i]; }
#pragma unroll
                for (int o = 16; o; o >>= 1) q += __shfl_xor_sync(0xffffffffu, q, o);
                const float inv = rsqrtf(q * (1.f / 128.f) + 1e-5f);
                const size_t row = (size_t)(m0 + half * 64 + rl);
#pragma unroll
                for (int i = 0; i < 4; ++i) {
                    const int d = lane + 32 * i;
                    const float o = v[i] * inv * lnW[d] + lnB[d];
                    ln_hout[row * DD + d]  = __float2half(o);
                    ln_xc[row * ldxc + d]  = __float2half(o);
                }
            }
        }
    }
}

// ---------------- embedding (PE from table) ----------------------------------
__global__ void embed_kernel(const float* __restrict__ x,
                             const float* __restrict__ tokW,
                             const float* __restrict__ tokb,
                             h16* __restrict__ h)
{
    size_t idx = (size_t)blockIdx.x * 256 + threadIdx.x;
    size_t token = idx >> 7;
    int d = (int)(idx & 127);
    int t = (int)((token / NN) % TT);
    const float* xp = x + token * FINN;
    float val = xp[0]*tokW[d*3+0] + xp[1]*tokW[d*3+1] + xp[2]*tokW[d*3+2]
              + tokb[d] + g_pe[t*DD + d];
    h[idx] = __float2half(val);
}

// ---------------- temporal attention (T=12), 2 nodes per block ---------------
__global__ void __launch_bounds__(256, 2)
temporal_attn_kernel(const h16* __restrict__ qkv, h16* __restrict__ outp)
{
    const int tid  = threadIdx.x;
    const int g    = tid >> 7;            // node slot within block
    const int tid2 = tid & 127;
    const int bidx = blockIdx.x * 2 + g;  // b*512 + n
    const int b = bidx >> 9, n = bidx & 511;

    __shared__ float q[2][TT][DD+4], k[2][TT][DD+4], v[2][TT][DD+4];
    __shared__ float S[2][HH][TT][TT];
#pragma unroll
    for (int t = 0; t < TT; ++t) {
        size_t row = ((size_t)(b*TT + t) * NN + n) * 384;
        q[g][t][tid2] = __half2float(qkv[row + tid2]);
        k[g][t][tid2] = __half2float(qkv[row + 128 + tid2]);
        v[g][t][tid2] = __half2float(qkv[row + 256 + tid2]);
    }
    __syncthreads();
    const float scale = 0.17677669529663687f;
    for (int idx = tid2; idx < HH*TT*TT; idx += 128) {
        int hh = idx / (TT*TT);
        int rem = idx - hh*(TT*TT);
        int xx = rem / TT, yy = rem - xx*TT;
        const float4* q4 = (const float4*)&q[g][xx][hh*32];
        const float4* k4 = (const float4*)&k[g][yy][hh*32];
        float s = 0.f;
#pragma unroll
        for (int e = 0; e < 8; ++e) {
            float4 qa = q4[e], kb = k4[e];
            s = fmaf(qa.x, kb.x, s); s = fmaf(qa.y, kb.y, s);
            s = fmaf(qa.z, kb.z, s); s = fmaf(qa.w, kb.w, s);
        }
        S[g][hh][xx][yy] = s * scale;
    }
    __syncthreads();
    if (tid2 < HH*TT) {
        int hh = tid2 / TT, xx = tid2 % TT;
        float mx = -1e30f;
#pragma unroll
        for (int y = 0; y < TT; ++y) mx = fmaxf(mx, S[g][hh][xx][y]);
        float sum = 0.f;
#pragma unroll
        for (int y = 0; y < TT; ++y) { float p = __expf(S[g][hh][xx][y]-mx); S[g][hh][xx][y] = p; sum += p; }
        float inv = 1.f / sum;
#pragma unroll
        for (int y = 0; y < TT; ++y) S[g][hh][xx][y] *= inv;
    }
    __syncthreads();
    const int hh = tid2 >> 5;
    float vr[TT];
#pragma unroll
    for (int yy = 0; yy < TT; ++yy) vr[yy] = v[g][yy][tid2];
#pragma unroll
    for (int xx = 0; xx < TT; ++xx) {
        float o = 0.f;
#pragma unroll
        for (int yy = 0; yy < TT; ++yy) o = fmaf(S[g][hh][xx][yy], vr[yy], o);
        outp[((size_t)(b*TT + xx) * NN + n) * DD + tid2] = __float2half(o);
    }
}

// ============ merged spatial attention (geo+sem, flash, fp16 in/out) =========
__global__ void __launch_bounds__(256, 2)
spatial_attn_mma(const h16* __restrict__ qkv,
                 h16* __restrict__ gout, h16* __restrict__ sout)
{
    const int qtile = blockIdx.x;
    const int sel   = blockIdx.y >> 2;
    const int head  = blockIdx.y & 3;
    const int bt    = blockIdx.z;
    const int tid  = threadIdx.x;
    const int wid  = tid >> 5;
    const int lane = tid & 31;
    const int l16  = lane & 15;

    h16* outp = sel ? sout : gout;
    const int colq = sel * 384 + head * 32;

    __shared__ __half Qs[128][40];
    __shared__ __half Ks[128][40];
    __shared__ __half Vt[32][136];

    const size_t base = (size_t)bt * NN;
    const float scale = 0.17677669529663687f;
    const __half2 hs2 = __floats2half2_rn(scale, scale);

    for (int i = tid; i < 128*4; i += 256) {
        int r = i >> 2, ec = (i & 3) * 8;
        uint4 vq = *(const uint4*)(qkv + (base + (size_t)qtile*128 + r)*768 + colq + ec);
        __half2* p = (__half2*)&vq;
#pragma unroll
        for (int z = 0; z < 4; ++z) p[z] = __hmul2(p[z], hs2);
        *(uint4*)&Qs[r][ec] = vq;
    }
    __syncthreads();

    uint32_t qf[2][4];
#pragma unroll
    for (int kc = 0; kc < 2; ++kc) {
        uint32_t ad = smem_u32(&Qs[wid*16 + l16][kc*16 + (lane>>4)*8]);
        asm volatile("ldmatrix.sync.aligned.m8n8.x4.shared.b16 {%0,%1,%2,%3}, [%4];"
                     : "=r"(qf[kc][0]), "=r"(qf[kc][1]), "=r"(qf[kc][2]), "=r"(qf[kc][3])
                     : "r"(ad));
    }

    float m0 = -1e30f, m1 = -1e30f, l0 = 0.f, l1 = 0.f;
    float oacc[4][4];
#pragma unroll
    for (int ef = 0; ef < 4; ++ef)
#pragma unroll
        for (int r = 0; r < 4; ++r) oacc[ef][r] = 0.f;

    for (int kt = 0; kt < 4; ++kt) {
        __syncthreads();
        for (int i = tid; i < 128*4; i += 256) {
            int j = i >> 2, ec = (i & 3) * 8;
            const h16* rp = qkv + (base + (size_t)kt*128 + j)*768 + colq + 128 + ec;
            *(uint4*)&Ks[j][ec] = *(const uint4*)rp;
            uint4 vv = *(const uint4*)(rp + 128);
            h16 tmp[8]; *(uint4*)tmp = vv;
#pragma unroll
            for (int z = 0; z < 8; ++z) Vt[ec + z][j] = tmp[z];
        }
        __syncthreads();

        float sacc[16][4];
#pragma unroll
        for (int nf = 0; nf < 16; ++nf) {
            sacc[nf][0] = sacc[nf][1] = sacc[nf][2] = sacc[nf][3] = 0.f;
#pragma unroll
            for (int kc = 0; kc < 2; ++kc) {
                uint32_t b0, b1;
                uint32_t bd = smem_u32(&Ks[nf*8 + (l16 & 7)][kc*16 + (l16 >> 3)*8]);
                asm volatile("ldmatrix.sync.aligned.m8n8.x2.shared.b16 {%0,%1}, [%2];"
                             : "=r"(b0), "=r"(b1) : "r"(bd));
                asm volatile(
                    "mma.sync.aligned.m16n8k16.row.col.f32.f16.f16.f32 "
                    "{%0,%1,%2,%3}, {%4,%5,%6,%7}, {%8,%9}, {%0,%1,%2,%3};"
                    : "+f"(sacc[nf][0]), "+f"(sacc[nf][1]),
                      "+f"(sacc[nf][2]), "+f"(sacc[nf][3])
                    : "r"(qf[kc][0]), "r"(qf[kc][1]), "r"(qf[kc][2]), "r"(qf[kc][3]),
                      "r"(b0), "r"(b1));
            }
        }

        float mx0 = -1e30f, mx1 = -1e30f;
#pragma unroll
        for (int nf = 0; nf < 16; ++nf) {
            mx0 = fmaxf(mx0, fmaxf(sacc[nf][0], sacc[nf][1]));
            mx1 = fmaxf(mx1, fmaxf(sacc[nf][2], sacc[nf][3]));
        }
        mx0 = fmaxf(mx0, __shfl_xor_sync(0xffffffffu, mx0, 1));
        mx0 = fmaxf(mx0, __shfl_xor_sync(0xffffffffu, mx0, 2));
        mx1 = fmaxf(mx1, __shfl_xor_sync(0xffffffffu, mx1, 1));
        mx1 = fmaxf(mx1, __shfl_xor_sync(0xffffffffu, mx1, 2));
        const float nm0 = fmaxf(m0, mx0), nm1 = fmaxf(m1, mx1);
        const float c0 = __expf(m0 - nm0), c1 = __expf(m1 - nm1);
        m0 = nm0; m1 = nm1;
#pragma unroll
        for (int ef = 0; ef < 4; ++ef) {
            oacc[ef][0] *= c0; oacc[ef][1] *= c0;
            oacc[ef][2] *= c1; oacc[ef][3] *= c1;
        }

        float rs0 = 0.f, rs1 = 0.f;
#pragma unroll
        for (int jc = 0; jc < 8; ++jc) {
            float p00 = __expf(sacc[2*jc][0]   - nm0);
            float p01 = __expf(sacc[2*jc][1]   - nm0);
            float p10 = __expf(sacc[2*jc][2]   - nm1);
            float p11 = __expf(sacc[2*jc][3]   - nm1);
            float p20 = __expf(sacc[2*jc+1][0] - nm0);
            float p21 = __expf(sacc[2*jc+1][1] - nm0);
            float p30 = __expf(sacc[2*jc+1][2] - nm1);
            float p31 = __expf(sacc[2*jc+1][3] - nm1);
            rs0 += p00 + p01 + p20 + p21;
            rs1 += p10 + p11 + p30 + p31;
            uint32_t pf0 = pack2h(p00, p01);
            uint32_t pf1 = pack2h(p10, p11);
            uint32_t pf2 = pack2h(p20, p21);
            uint32_t pf3 = pack2h(p30, p31);
#pragma unroll
            for (int ef = 0; ef < 4; ++ef) {
                uint32_t b0, b1;
                uint32_t bd = smem_u32(&Vt[ef*8 + (l16 & 7)][jc*16 + (l16 >> 3)*8]);
                asm volatile("ldmatrix.sync.aligned.m8n8.x2.shared.b16 {%0,%1}, [%2];"
                             : "=r"(b0), "=r"(b1) : "r"(bd));
                asm volatile(
                    "mma.sync.aligned.m16n8k16.row.col.f32.f16.f16.f32 "
                    "{%0,%1,%2,%3}, {%4,%5,%6,%7}, {%8,%9}, {%0,%1,%2,%3};"
                    : "+f"(oacc[ef][0]), "+f"(oacc[ef][1]),
                      "+f"(oacc[ef][2]), "+f"(oacc[ef][3])
                    : "r"(pf0), "r"(pf1), "r"(pf2), "r"(pf3),
                      "r"(b0), "r"(b1));
            }
        }
        rs0 += __shfl_xor_sync(0xffffffffu, rs0, 1);
        rs0 += __shfl_xor_sync(0xffffffffu, rs0, 2);
        rs1 += __shfl_xor_sync(0xffffffffu, rs1, 1);
        rs1 += __shfl_xor_sync(0xffffffffu, rs1, 2);
        l0 = l0 * c0 + rs0;
        l1 = l1 * c1 + rs1;
    }

    const float i0 = 1.f / l0, i1 = 1.f / l1;
    const int r0 = wid*16 + (lane >> 2);
#pragma unroll
    for (int ef = 0; ef < 4; ++ef) {
        const int col = head*32 + ef*8 + (lane & 3)*2;
        size_t rowA = (base + (size_t)qtile*128 + r0) * DD + col;
        size_t rowB = (base + (size_t)qtile*128 + r0 + 8) * DD + col;
        *(uint32_t*)&outp[rowA] = pack2h(oacc[ef][0] * i0, oacc[ef][1] * i0);
        *(uint32_t*)&outp[rowB] = pack2h(oacc[ef][2] * i1, oacc[ef][3] * i1);
    }
}

// ---------------- output head (fp16 xc) ---------------------------------------
__global__ void head_kernel(const h16* __restrict__ xc, const float* __restrict__ w1g,
                            const float* __restrict__ b1g, const float* __restrict__ w2g,
                            const float* __restrict__ b2g, float* __restrict__ y)
{
    const int bidx = blockIdx.x;
    const int b = bidx >> 9, n = bidx & 511;
    const int tid = threadIdx.x;
    __shared__ float xs[TT][LL*DD];
    __shared__ float w1[PP][TT];
    __shared__ float b1[PP];
    __shared__ float w2[LL*DD];
    __shared__ float red[PP][4];
    for (int t = 0; t < TT; ++t) {
        size_t rowoff = ((size_t)(b*TT + t) * NN + n) * (LL*DD);
        for (int c = tid; c < LL*DD; c += 128) xs[t][c] = __half2float(xc[rowoff + c]);
    }
    for (int i = tid; i < PP*TT; i += 128) w1[i/TT][i%TT] = w1g[i];
    if (tid < PP) b1[tid] = b1g[tid];
    for (int c = tid; c < LL*DD; c += 128) w2[c] = w2g[c];
    __syncthreads();

    float part[PP];
#pragma unroll
    for (int p = 0; p < PP; ++p) part[p] = 0.f;
    for (int c = tid; c < LL*DD; c += 128) {
        float xt[TT];
#pragma unroll
        for (int t = 0; t < TT; ++t) xt[t] = xs[t][c];
        float wc = w2[c];
#pragma unroll
        for (int p = 0; p < PP; ++p) {
            float sacc = b1[p];
#pragma unroll
            for (int t = 0; t < TT; ++t) sacc = fmaf(xt[t], w1[p][t], sacc);
            sacc = fmaxf(sacc, 0.f);
            part[p] = fmaf(sacc, wc, part[p]);
        }
    }
    const int warp = tid >> 5, lane = tid & 31;
#pragma unroll
    for (int p = 0; p < PP; ++p) {
        float sv = part[p];
#pragma unroll
        for (int o = 16; o; o >>= 1) sv += __shfl_xor_sync(0xffffffffu, sv, o);
        if (lane == 0) red[p][warp] = sv;
    }
    __syncthreads();
    if (tid < PP) {
        float sv = red[tid][0] + red[tid][1] + red[tid][2] + red[tid][3];
        y[(size_t)(b*PP + tid) * NN + n] = sv + b2g[0];
    }
}

// ---------------- launcher ---------------------------------------------------
extern "C" void kernel_launch(void* const* d_in, const int* in_sizes, int n_in,
                              void* d_out, int out_size)
{
    (void)in_sizes; (void)n_in; (void)out_size;
    const float* x      = (const float*)d_in[0];
    const float* tokW   = (const float*)d_in[1];
    const float* tokb   = (const float*)d_in[2];
    const float* t_qkvW = (const float*)d_in[3];
    const float* t_qkvb = (const float*)d_in[4];
    const float* t_pW   = (const float*)d_in[5];
    const float* t_pb   = (const float*)d_in[6];
    const float* g_qkvW = (const float*)d_in[7];
    const float* g_qkvb = (const float*)d_in[8];
    const float* g_pW   = (const float*)d_in[9];
    const float* g_pb   = (const float*)d_in[10];
    const float* s_qkvW = (const float*)d_in[11];
    const float* s_qkvb = (const float*)d_in[12];
    const float* s_pW   = (const float*)d_in[13];
    const float* s_pb   = (const float*)d_in[14];
    const float* resW   = (const float*)d_in[15];
    const float* resb   = (const float*)d_in[16];
    const float* normW  = (const float*)d_in[17];
    const float* normb  = (const float*)d_in[18];
    const float* fc1W   = (const float*)d_in[19];
    const float* fc1b   = (const float*)d_in[20];
    const float* fc2W   = (const float*)d_in[21];
    const float* fc2b   = (const float*)d_in[22];
    const float* e1W    = (const float*)d_in[23];
    const float* e1b    = (const float*)d_in[24];
    const float* e2W    = (const float*)d_in[25];
    const float* e2b    = (const float*)d_in[26];
    float* out = (float*)d_out;

    float *bgsB, *b12B;
    h16 *qkvB, *qkv12B, *xcB;
    cudaGetSymbolAddress((void**)&qkvB,   g_qkv);
    cudaGetSymbolAddress((void**)&qkv12B, g_qkv12);
    cudaGetSymbolAddress((void**)&xcB,    g_xc);
    cudaGetSymbolAddress((void**)&bgsB,   b_gs);
    cudaGetSymbolAddress((void**)&b12B,   b_12);

    h16 *hA,*at,*a2,*ml;
    cudaGetSymbolAddress((void**)&hA, a_hA);
    cudaGetSymbolAddress((void**)&at, a_at);
    cudaGetSymbolAddress((void**)&a2, a_a2);
    cudaGetSymbolAddress((void**)&ml, a_ml);

    h16 *tq,*gsF,*w12,*cb;
    cudaGetSymbolAddress((void**)&tq,  w_tq);
    cudaGetSymbolAddress((void**)&gsF, w_gsF);
    cudaGetSymbolAddress((void**)&w12, w_12F);
    cudaGetSymbolAddress((void**)&cb,  w_cb);

    const int MBt = TOK / 128;
    const int DSM = 40960;

    const int CVT_N = LL*3*DD*DD + LL*DD*(HMM+DD);
    pe_kernel<<<(TT*DD+255)/256, 256>>>();
    cvt_all<<<(CVT_N+255)/256, 256>>>(t_qkvW, fc2W, resW);
    fold_gs<<<(LL*768*DD+255)/256, 256>>>(g_qkvW, s_qkvW, g_qkvb, s_qkvb, t_pW, t_pb);
    fold_f1<<<(LL*HMM*2*DD+255)/256, 256>>>(fc1W, fc1b, g_pW, g_pb, s_pW, s_pb);

    embed_kernel<<<(TOK*DD)/256, 256>>>(x, tokW, tokb, hA);

    for (int l = 0; l < LL; ++l) {
        const size_t oq = (size_t)l*3*DD*DD, oqb = (size_t)l*3*DD;
        const size_t opb = (size_t)l*DD;
        const size_t ogs = (size_t)l*6*DD*DD;

        // temporal qkv
        mma_gemm<<<dim3(3, MBt), 256, DSM>>>(hA, DD, nullptr, 0, tq+oq,
                                             t_qkvb+oqb, nullptr, qkvB, 3*DD, 0,
                                             nullptr, nullptr, nullptr, nullptr, 0);
        temporal_attn_kernel<<<BB*NN/2, 256>>>(qkvB, at);
        // folded (t_p . gs_qkv): qkv12 = at @ Wc^T + bc
        mma_gemm<<<dim3(6, MBt), 256, DSM>>>(at, DD, nullptr, 0, gsF+ogs,
                                             bgsB + (size_t)l*768, nullptr, qkv12B, 6*DD, 0,
                                             nullptr, nullptr, nullptr, nullptr, 0);
        // merged spatial attention: geo -> at, sem -> a2
        spatial_attn_mma<<<dim3(NN/128, 2*HH, BB*TT), 256>>>(qkv12B, at, a2);
        // folded (proj . fc1) + gelu
        mma_gemm<<<dim3(2, MBt), 256, DSM>>>(at, DD, a2, DD,
                                             w12+(size_t)l*HMM*2*DD,
                                             b12B+(size_t)l*HMM, nullptr,
                                             ml, HMM, 1,
                                             nullptr, nullptr, nullptr, nullptr, 0);
        // fused fc2 + residual-linear + LayerNorm
        mma_gemm<<<dim3(1, MBt), 256, DSM>>>(ml, HMM, hA, DD,
                                             cb+(size_t)l*DD*(HMM+DD),
                                             fc2b+opb, resb+opb,
                                             nullptr, DD, 0,
                                             normW+opb, normb+opb,
                                             hA, xcB + (size_t)l*DD, LL*DD);
    }

    head_kernel<<<BB*NN, 128>>>(xcB, e1W, e1b, e2W, e2b, out);
}

// round 14
// speedup vs baseline: 1.2963x; 1.0187x over previous
#include <cuda_runtime.h>
#include <cuda_fp16.h>
#include <math.h>
#include <stdint.h>

#define BB   8
#define TT   12
#define NN   512
#define FINN 3
#define DD   128
#define HH   4
#define HMM  256
#define LL   3
#define PP   12
#define TOK  (BB*TT*NN)          // 49152 tokens

typedef __half h16;

// ---------------- scratch ----------------------------------------------------
__device__ h16   g_qkv  [TOK*3*DD];
__device__ h16   g_qkv12[TOK*6*DD];
__device__ h16   g_xc [TOK*LL*DD];
__device__ float b_gs [LL*6*DD];
__device__ float b_12 [LL*HMM];
__device__ float g_pe [TT*DD];
// fp16 activations
__device__ h16 a_hA[TOK*DD];
__device__ h16 a_at[TOK*DD];
__device__ h16 a_a2[TOK*DD];
__device__ h16 a_ml[TOK*HMM];
// fp16 weights
__device__ h16 w_tq[LL*3*DD*DD];
__device__ h16 w_gsF[LL*6*DD*DD];
__device__ h16 w_12F[LL*HMM*2*DD];
__device__ h16 w_cb[LL*DD*(HMM+DD)];

__device__ __forceinline__ uint32_t smem_u32(const void* p) {
    uint32_t a;
    asm("{ .reg .u64 t; cvta.to.shared.u64 t, %1; cvt.u32.u64 %0, t; }"
        : "=r"(a) : "l"(p));
    return a;
}
__device__ __forceinline__ uint32_t pack2h(float a, float b) {
    __half2 h = __floats2half2_rn(a, b);
    return *(uint32_t*)&h;
}
#define CP_ASYNC16(dst, src) \
    asm volatile("cp.async.cg.shared.global [%0], [%1], 16;" :: "r"(dst), "l"(src))
#define CP_COMMIT() asm volatile("cp.async.commit_group;" ::: "memory")
#define CP_WAIT(n)  asm volatile("cp.async.wait_group %0;" :: "n"(n) : "memory")

// ================= merged setup: pe | cvt | fold_gs | fold_f1 ================
// block ranges: [0,6) pe; [6,1158) cvt; [1158,2310) fold_gs; [2310,3078) fold_f1
__global__ void setup_all(const float* __restrict__ t_qkvW,
                          const float* __restrict__ fc2W, const float* __restrict__ resW,
                          const float* __restrict__ gq, const float* __restrict__ sq,
                          const float* __restrict__ gqb, const float* __restrict__ sqb,
                          const float* __restrict__ tpW, const float* __restrict__ tpb,
                          const float* __restrict__ f1W, const float* __restrict__ f1b,
                          const float* __restrict__ gpW, const float* __restrict__ gpb,
                          const float* __restrict__ spW, const float* __restrict__ spb)
{
    const int blk = blockIdx.x;
    if (blk < 6) {                                    // ---- PE table
        int i = blk * 256 + threadIdx.x;
        if (i >= TT*DD) return;
        int t = i / DD, d = i % DD;
        int i2 = d & ~1;
        float div = expf((float)i2 * (-logf(10000.0f) / (float)DD));
        float ang = (float)t * div;
        g_pe[i] = (d & 1) ? cosf(ang) : sinf(ang);
        return;
    }
    if (blk < 1158) {                                 // ---- cvt tq + cb
        int i = (blk - 6) * 256 + threadIdx.x;
        const int NQ  = LL*3*DD*DD;
        const int NCB = LL*DD*(HMM+DD);
        if (i < NQ) { w_tq[i] = __float2half(t_qkvW[i]); return; }
        i -= NQ;
        if (i < NCB) {
            const int KK = HMM + DD;
            int l = i / (DD*KK), r = (i / KK) % DD, k = i % KK;
            float v = (k < HMM) ? fc2W[((size_t)l*DD + r)*HMM + k]
                                : resW[((size_t)l*DD + r)*DD + (k - HMM)];
            w_cb[i] = __float2half(v);
        }
        return;
    }
    if (blk < 2310) {                                 // ---- fold_gs
        int i = (blk - 1158) * 256 + threadIdx.x;
        if (i >= LL*768*DD) return;
        const int l = i / (768*DD);
        const int p = (i / DD) % 768;
        const int k = i % DD;
        const float* grow = (p < 384) ? gq + ((size_t)l*384 + p)*DD
                                      : sq + ((size_t)l*384 + (p-384))*DD;
        const float* tw = tpW + (size_t)l*DD*DD;
        float s = 0.f;
#pragma unroll 8
        for (int o = 0; o < DD; ++o) s += grow[o] * tw[o*DD + k];
        w_gsF[i] = __float2half(s);
        if (k == 0) {
            float bb = (p < 384) ? gqb[l*384 + p] : sqb[l*384 + (p-384)];
            const float* tb = tpb + l*DD;
#pragma unroll 8
            for (int o = 0; o < DD; ++o) bb += grow[o] * tb[o];
            b_gs[l*768 + p] = bb;
        }
        return;
    }
    {                                                 // ---- fold_f1
        int i = (blk - 2310) * 256 + threadIdx.x;
        if (i >= LL*HMM*2*DD) return;
        const int l = i / (HMM*2*DD);
        const int h = (i / (2*DD)) % HMM;
        const int k = i % (2*DD);
        const float* frow = f1W + ((size_t)l*HMM + h)*(2*DD);
        float s = 0.f;
        if (k < DD) {
            const float* pw = gpW + (size_t)l*DD*DD;
#pragma unroll 8
            for (int d = 0; d < DD; ++d) s += frow[d] * pw[d*DD + k];
        } else {
            const float* pw = spW + (size_t)l*DD*DD;
#pragma unroll 8
            for (int d = 0; d < DD; ++d) s += frow[DD + d] * pw[d*DD + (k - DD)];
        }
        w_12F[i] = __float2half(s);
        if (k == 0) {
            float bb = f1b[l*HMM + h];
            const float* gb = gpb + l*DD;
            const float* sb = spb + l*DD;
#pragma unroll 8
            for (int d = 0; d < DD; ++d) bb += frow[d]*gb[d] + frow[DD + d]*sb[d];
            b_12[l*HMM + h] = bb;
        }
    }
}

// ================= fp16 mma GEMM: 3-stage pipeline, one sync/chunk ===========
// dyn smem: 3*(A+B) stages = 61440 B; LN staging reuses it.
__global__ void __launch_bounds__(256, 2)
mma_gemm(const h16* __restrict__ A1, int K1, const h16* __restrict__ A2, int K2,
         const h16* __restrict__ W,
         const float* __restrict__ bias, const float* __restrict__ bias2,
         h16* __restrict__ outh, int ldo, int gelu,
         const float* __restrict__ lnW, const float* __restrict__ lnB,
         h16* __restrict__ ln_hout, h16* __restrict__ ln_xc, int ldxc)
{
    extern __shared__ char dsm[];
    h16* As = (h16*)dsm;              // [3][128][40]
    h16* Bs = As + 3*5120;            // [3][128][40]
    float* stage = (float*)dsm;       // LN staging [64][132]

    const int tid  = threadIdx.x;
    const int wid  = tid >> 5;
    const int lane = tid & 31;
    const int l16  = lane & 15;
    const int warp_m = wid >> 2;
    const int warp_n = wid & 3;
    const int m0 = blockIdx.y * 128;
    const int n0 = blockIdx.x * 128;
    const int K  = K1 + K2;
    const int KC = K >> 5;

    float acc[4][4][4];
#pragma unroll
    for (int mi = 0; mi < 4; ++mi)
#pragma unroll
        for (int ni = 0; ni < 4; ++ni)
#pragma unroll
            for (int r = 0; r < 4; ++r) acc[mi][ni][r] = 0.f;

    auto load_chunk = [&](int buf, int kp) {
        const int kof = kp * 32;
        const h16* Asrc; int lda, acol;
        if (kof < K1) { Asrc = A1; lda = K1; acol = kof; }
        else          { Asrc = A2; lda = K2; acol = kof - K1; }
#pragma unroll
        for (int t = 0; t < 2; ++t) {
            const int c   = tid + t * 256;
            const int row = c >> 2;
            const int cc  = (c & 3) * 8;
            CP_ASYNC16(smem_u32(As + buf*5120 + row*40 + cc),
                       Asrc + (size_t)(m0 + row) * lda + acol + cc);
            CP_ASYNC16(smem_u32(Bs + buf*5120 + row*40 + cc),
                       W + (size_t)(n0 + row) * K + kof + cc);
        }
    };

    auto compute = [&](int buf) {
#pragma unroll
        for (int ks = 0; ks < 2; ++ks) {
            const int k = ks * 16;
            uint32_t a[4][4], b[4][2];
#pragma unroll
            for (int mi = 0; mi < 4; ++mi) {
                uint32_t ad = smem_u32(As + buf*5120 + (warp_m*64 + mi*16 + l16)*40 + k + (lane >> 4) * 8);
                asm volatile("ldmatrix.sync.aligned.m8n8.x4.shared.b16 {%0,%1,%2,%3}, [%4];"
                             : "=r"(a[mi][0]), "=r"(a[mi][1]), "=r"(a[mi][2]), "=r"(a[mi][3])
                             : "r"(ad));
            }
#pragma unroll
            for (int ni = 0; ni < 4; ++ni) {
                uint32_t bd = smem_u32(Bs + buf*5120 + (warp_n*32 + ni*8 + (l16 & 7))*40 + k + (l16 >> 3) * 8);
                asm volatile("ldmatrix.sync.aligned.m8n8.x2.shared.b16 {%0,%1}, [%2];"
                             : "=r"(b[ni][0]), "=r"(b[ni][1]) : "r"(bd));
            }
#pragma unroll
            for (int mi = 0; mi < 4; ++mi)
#pragma unroll
                for (int ni = 0; ni < 4; ++ni)
                    asm volatile(
                        "mma.sync.aligned.m16n8k16.row.col.f32.f16.f16.f32 "
                        "{%0,%1,%2,%3}, {%4,%5,%6,%7}, {%8,%9}, {%0,%1,%2,%3};"
                        : "+f"(acc[mi][ni][0]), "+f"(acc[mi][ni][1]),
                          "+f"(acc[mi][ni][2]), "+f"(acc[mi][ni][3])
                        : "r"(a[mi][0]), "r"(a[mi][1]), "r"(a[mi][2]), "r"(a[mi][3]),
                          "r"(b[ni][0]), "r"(b[ni][1]));
        }
    };

    // 3-stage pipeline, single sync per chunk.
    load_chunk(0, 0);
    CP_COMMIT();
    if (KC > 1) { load_chunk(1, 1); CP_COMMIT(); }
    int s2 = 2;                    // next stage to fill
    for (int i = 0; i < KC; ++i) {
        if (i + 1 < KC) CP_WAIT(1); else CP_WAIT(0);   // chunk i resident
        __syncthreads();                               // visible + stage (i)%3 free
        if (i + 2 < KC) {
            load_chunk(s2, i + 2);
            CP_COMMIT();
            s2 = (s2 == 2) ? 0 : s2 + 1;
        }
        compute(i % 3);
    }
    __syncthreads();               // all compute done before smem reuse / exit

    const int quad = lane >> 2, qi = lane & 3;

    if (lnW == nullptr) {
#pragma unroll
        for (int mi = 0; mi < 4; ++mi)
#pragma unroll
            for (int ni = 0; ni < 4; ++ni)
#pragma unroll
                for (int h = 0; h < 2; ++h) {
                    const int row = m0 + warp_m * 64 + mi * 16 + quad + h * 8;
                    const int col = n0 + warp_n * 32 + ni * 8 + qi * 2;
                    float v0 = acc[mi][ni][h * 2 + 0] + bias[col];
                    float v1 = acc[mi][ni][h * 2 + 1] + bias[col + 1];
                    if (gelu) {
                        v0 = 0.5f * v0 * (1.0f + erff(v0 * 0.70710678118654752f));
                        v1 = 0.5f * v1 * (1.0f + erff(v1 * 0.70710678118654752f));
                    }
                    *(uint32_t*)&outh[(size_t)row * ldo + col] = pack2h(v0, v1);
                }
    } else {
        // fused LayerNorm epilogue (gridDim.x==1, N=128)
#pragma unroll
        for (int half = 0; half < 2; ++half) {
            __syncthreads();
            if (warp_m == half) {
#pragma unroll
                for (int mi = 0; mi < 4; ++mi)
#pragma unroll
                    for (int ni = 0; ni < 4; ++ni)
#pragma unroll
                        for (int h = 0; h < 2; ++h) {
                            const int rl  = mi * 16 + quad + h * 8;
                            const int col = warp_n * 32 + ni * 8 + qi * 2;
                            stage[rl * 132 + col]     = acc[mi][ni][h*2+0] + bias[col]   + bias2[col];
                            stage[rl * 132 + col + 1] = acc[mi][ni][h*2+1] + bias[col+1] + bias2[col+1];
                        }
            }
            __syncthreads();
#pragma unroll
            for (int rr = 0; rr < 8; ++rr) {
                const int rl = wid * 8 + rr;
                float v[4];
#pragma unroll
                for (int i = 0; i < 4; ++i) v[i] = stage[rl * 132 + lane + 32 * i];
                float s = v[0] + v[1] + v[2] + v[3];
#pragma unroll
                for (int o = 16; o; o >>= 1) s += __shfl_xor_sync(0xffffffffu, s, o);
                const float mean = s * (1.f / 128.f);
                float q = 0.f;
#pragma unroll
                for (int i = 0; i < 4; ++i) { v[i] -= mean; q += v[i] * v[i]; }
#pragma unroll
                for (int o = 16; o; o >>= 1) q += __shfl_xor_sync(0xffffffffu, q, o);
                const float inv = rsqrtf(q * (1.f / 128.f) + 1e-5f);
                const size_t row = (size_t)(m0 + half * 64 + rl);
#pragma unroll
                for (int i = 0; i < 4; ++i) {
                    const int d = lane + 32 * i;
                    const float o = v[i] * inv * lnW[d] + lnB[d];
                    ln_hout[row * DD + d]  = __float2half(o);
                    ln_xc[row * ldxc + d]  = __float2half(o);
                }
            }
        }
    }
}

// ---------------- embedding (PE from table) ----------------------------------
__global__ void embed_kernel(const float* __restrict__ x,
                             const float* __restrict__ tokW,
                             const float* __restrict__ tokb,
                             h16* __restrict__ h)
{
    size_t idx = (size_t)blockIdx.x * 256 + threadIdx.x;
    size_t token = idx >> 7;
    int d = (int)(idx & 127);
    int t = (int)((token / NN) % TT);
    const float* xp = x + token * FINN;
    float val = xp[0]*tokW[d*3+0] + xp[1]*tokW[d*3+1] + xp[2]*tokW[d*3+2]
              + tokb[d] + g_pe[t*DD + d];
    h[idx] = __float2half(val);
}

// ---------------- temporal attention (T=12), 2 nodes per block ---------------
__global__ void __launch_bounds__(256, 2)
temporal_attn_kernel(const h16* __restrict__ qkv, h16* __restrict__ outp)
{
    const int tid  = threadIdx.x;
    const int g    = tid >> 7;
    const int tid2 = tid & 127;
    const int bidx = blockIdx.x * 2 + g;
    const int b = bidx >> 9, n = bidx & 511;

    __shared__ float q[2][TT][DD+4], k[2][TT][DD+4], v[2][TT][DD+4];
    __shared__ float S[2][HH][TT][TT];
#pragma unroll
    for (int t = 0; t < TT; ++t) {
        size_t row = ((size_t)(b*TT + t) * NN + n) * 384;
        q[g][t][tid2] = __half2float(qkv[row + tid2]);
        k[g][t][tid2] = __half2float(qkv[row + 128 + tid2]);
        v[g][t][tid2] = __half2float(qkv[row + 256 + tid2]);
    }
    __syncthreads();
    const float scale = 0.17677669529663687f;
    for (int idx = tid2; idx < HH*TT*TT; idx += 128) {
        int hh = idx / (TT*TT);
        int rem = idx - hh*(TT*TT);
        int xx = rem / TT, yy = rem - xx*TT;
        const float4* q4 = (const float4*)&q[g][xx][hh*32];
        const float4* k4 = (const float4*)&k[g][yy][hh*32];
        float s = 0.f;
#pragma unroll
        for (int e = 0; e < 8; ++e) {
            float4 qa = q4[e], kb = k4[e];
            s = fmaf(qa.x, kb.x, s); s = fmaf(qa.y, kb.y, s);
            s = fmaf(qa.z, kb.z, s); s = fmaf(qa.w, kb.w, s);
        }
        S[g][hh][xx][yy] = s * scale;
    }
    __syncthreads();
    if (tid2 < HH*TT) {
        int hh = tid2 / TT, xx = tid2 % TT;
        float mx = -1e30f;
#pragma unroll
        for (int y = 0; y < TT; ++y) mx = fmaxf(mx, S[g][hh][xx][y]);
        float sum = 0.f;
#pragma unroll
        for (int y = 0; y < TT; ++y) { float p = __expf(S[g][hh][xx][y]-mx); S[g][hh][xx][y] = p; sum += p; }
        float inv = 1.f / sum;
#pragma unroll
        for (int y = 0; y < TT; ++y) S[g][hh][xx][y] *= inv;
    }
    __syncthreads();
    const int hh = tid2 >> 5;
    float vr[TT];
#pragma unroll
    for (int yy = 0; yy < TT; ++yy) vr[yy] = v[g][yy][tid2];
#pragma unroll
    for (int xx = 0; xx < TT; ++xx) {
        float o = 0.f;
#pragma unroll
        for (int yy = 0; yy < TT; ++yy) o = fmaf(S[g][hh][xx][yy], vr[yy], o);
        outp[((size_t)(b*TT + xx) * NN + n) * DD + tid2] = __float2half(o);
    }
}

// ============ merged spatial attention (geo+sem, flash, fp16 in/out) =========
__global__ void __launch_bounds__(256, 2)
spatial_attn_mma(const h16* __restrict__ qkv,
                 h16* __restrict__ gout, h16* __restrict__ sout)
{
    const int qtile = blockIdx.x;
    const int sel   = blockIdx.y >> 2;
    const int head  = blockIdx.y & 3;
    const int bt    = blockIdx.z;
    const int tid  = threadIdx.x;
    const int wid  = tid >> 5;
    const int lane = tid & 31;
    const int l16  = lane & 15;

    h16* outp = sel ? sout : gout;
    const int colq = sel * 384 + head * 32;

    __shared__ __half Qs[128][40];
    __shared__ __half Ks[128][40];
    __shared__ __half Vt[32][136];

    const size_t base = (size_t)bt * NN;
    const float scale = 0.17677669529663687f;
    const __half2 hs2 = __floats2half2_rn(scale, scale);

    for (int i = tid; i < 128*4; i += 256) {
        int r = i >> 2, ec = (i & 3) * 8;
        uint4 vq = *(const uint4*)(qkv + (base + (size_t)qtile*128 + r)*768 + colq + ec);
        __half2* p = (__half2*)&vq;
#pragma unroll
        for (int z = 0; z < 4; ++z) p[z] = __hmul2(p[z], hs2);
        *(uint4*)&Qs[r][ec] = vq;
    }
    __syncthreads();

    uint32_t qf[2][4];
#pragma unroll
    for (int kc = 0; kc < 2; ++kc) {
        uint32_t ad = smem_u32(&Qs[wid*16 + l16][kc*16 + (lane>>4)*8]);
        asm volatile("ldmatrix.sync.aligned.m8n8.x4.shared.b16 {%0,%1,%2,%3}, [%4];"
                     : "=r"(qf[kc][0]), "=r"(qf[kc][1]), "=r"(qf[kc][2]), "=r"(qf[kc][3])
                     : "r"(ad));
    }

    float m0 = -1e30f, m1 = -1e30f, l0 = 0.f, l1 = 0.f;
    float oacc[4][4];
#pragma unroll
    for (int ef = 0; ef < 4; ++ef)
#pragma unroll
        for (int r = 0; r < 4; ++r) oacc[ef][r] = 0.f;

    for (int kt = 0; kt < 4; ++kt) {
        __syncthreads();
        for (int i = tid; i < 128*4; i += 256) {
            int j = i >> 2, ec = (i & 3) * 8;
            const h16* rp = qkv + (base + (size_t)kt*128 + j)*768 + colq + 128 + ec;
            *(uint4*)&Ks[j][ec] = *(const uint4*)rp;
            uint4 vv = *(const uint4*)(rp + 128);
            h16 tmp[8]; *(uint4*)tmp = vv;
#pragma unroll
            for (int z = 0; z < 8; ++z) Vt[ec + z][j] = tmp[z];
        }
        __syncthreads();

        float sacc[16][4];
#pragma unroll
        for (int nf = 0; nf < 16; ++nf) {
            sacc[nf][0] = sacc[nf][1] = sacc[nf][2] = sacc[nf][3] = 0.f;
#pragma unroll
            for (int kc = 0; kc < 2; ++kc) {
                uint32_t b0, b1;
                uint32_t bd = smem_u32(&Ks[nf*8 + (l16 & 7)][kc*16 + (l16 >> 3)*8]);
                asm volatile("ldmatrix.sync.aligned.m8n8.x2.shared.b16 {%0,%1}, [%2];"
                             : "=r"(b0), "=r"(b1) : "r"(bd));
                asm volatile(
                    "mma.sync.aligned.m16n8k16.row.col.f32.f16.f16.f32 "
                    "{%0,%1,%2,%3}, {%4,%5,%6,%7}, {%8,%9}, {%0,%1,%2,%3};"
                    : "+f"(sacc[nf][0]), "+f"(sacc[nf][1]),
                      "+f"(sacc[nf][2]), "+f"(sacc[nf][3])
                    : "r"(qf[kc][0]), "r"(qf[kc][1]), "r"(qf[kc][2]), "r"(qf[kc][3]),
                      "r"(b0), "r"(b1));
            }
        }

        float mx0 = -1e30f, mx1 = -1e30f;
#pragma unroll
        for (int nf = 0; nf < 16; ++nf) {
            mx0 = fmaxf(mx0, fmaxf(sacc[nf][0], sacc[nf][1]));
            mx1 = fmaxf(mx1, fmaxf(sacc[nf][2], sacc[nf][3]));
        }
        mx0 = fmaxf(mx0, __shfl_xor_sync(0xffffffffu, mx0, 1));
        mx0 = fmaxf(mx0, __shfl_xor_sync(0xffffffffu, mx0, 2));
        mx1 = fmaxf(mx1, __shfl_xor_sync(0xffffffffu, mx1, 1));
        mx1 = fmaxf(mx1, __shfl_xor_sync(0xffffffffu, mx1, 2));
        const float nm0 = fmaxf(m0, mx0), nm1 = fmaxf(m1, mx1);
        const float c0 = __expf(m0 - nm0), c1 = __expf(m1 - nm1);
        m0 = nm0; m1 = nm1;
#pragma unroll
        for (int ef = 0; ef < 4; ++ef) {
            oacc[ef][0] *= c0; oacc[ef][1] *= c0;
            oacc[ef][2] *= c1; oacc[ef][3] *= c1;
        }

        float rs0 = 0.f, rs1 = 0.f;
#pragma unroll
        for (int jc = 0; jc < 8; ++jc) {
            float p00 = __expf(sacc[2*jc][0]   - nm0);
            float p01 = __expf(sacc[2*jc][1]   - nm0);
            float p10 = __expf(sacc[2*jc][2]   - nm1);
            float p11 = __expf(sacc[2*jc][3]   - nm1);
            float p20 = __expf(sacc[2*jc+1][0] - nm0);
            float p21 = __expf(sacc[2*jc+1][1] - nm0);
            float p30 = __expf(sacc[2*jc+1][2] - nm1);
            float p31 = __expf(sacc[2*jc+1][3] - nm1);
            rs0 += p00 + p01 + p20 + p21;
            rs1 += p10 + p11 + p30 + p31;
            uint32_t pf0 = pack2h(p00, p01);
            uint32_t pf1 = pack2h(p10, p11);
            uint32_t pf2 = pack2h(p20, p21);
            uint32_t pf3 = pack2h(p30, p31);
#pragma unroll
            for (int ef = 0; ef < 4; ++ef) {
                uint32_t b0, b1;
                uint32_t bd = smem_u32(&Vt[ef*8 + (l16 & 7)][jc*16 + (l16 >> 3)*8]);
                asm volatile("ldmatrix.sync.aligned.m8n8.x2.shared.b16 {%0,%1}, [%2];"
                             : "=r"(b0), "=r"(b1) : "r"(bd));
                asm volatile(
                    "mma.sync.aligned.m16n8k16.row.col.f32.f16.f16.f32 "
                    "{%0,%1,%2,%3}, {%4,%5,%6,%7}, {%8,%9}, {%0,%1,%2,%3};"
                    : "+f"(oacc[ef][0]), "+f"(oacc[ef][1]),
                      "+f"(oacc[ef][2]), "+f"(oacc[ef][3])
                    : "r"(pf0), "r"(pf1), "r"(pf2), "r"(pf3),
                      "r"(b0), "r"(b1));
            }
        }
        rs0 += __shfl_xor_sync(0xffffffffu, rs0, 1);
        rs0 += __shfl_xor_sync(0xffffffffu, rs0, 2);
        rs1 += __shfl_xor_sync(0xffffffffu, rs1, 1);
        rs1 += __shfl_xor_sync(0xffffffffu, rs1, 2);
        l0 = l0 * c0 + rs0;
        l1 = l1 * c1 + rs1;
    }

    const float i0 = 1.f / l0, i1 = 1.f / l1;
    const int r0 = wid*16 + (lane >> 2);
#pragma unroll
    for (int ef = 0; ef < 4; ++ef) {
        const int col = head*32 + ef*8 + (lane & 3)*2;
        size_t rowA = (base + (size_t)qtile*128 + r0) * DD + col;
        size_t rowB = (base + (size_t)qtile*128 + r0 + 8) * DD + col;
        *(uint32_t*)&outp[rowA] = pack2h(oacc[ef][0] * i0, oacc[ef][1] * i0);
        *(uint32_t*)&outp[rowB] = pack2h(oacc[ef][2] * i1, oacc[ef][3] * i1);
    }
}

// ---------------- output head (fp16 xc) ---------------------------------------
__global__ void head_kernel(const h16* __restrict__ xc, const float* __restrict__ w1g,
                            const float* __restrict__ b1g, const float* __restrict__ w2g,
                            const float* __restrict__ b2g, float* __restrict__ y)
{
    const int bidx = blockIdx.x;
    const int b = bidx >> 9, n = bidx & 511;
    const int tid = threadIdx.x;
    __shared__ float xs[TT][LL*DD];
    __shared__ float w1[PP][TT];
    __shared__ float b1[PP];
    __shared__ float w2[LL*DD];
    __shared__ float red[PP][4];
    for (int t = 0; t < TT; ++t) {
        size_t rowoff = ((size_t)(b*TT + t) * NN + n) * (LL*DD);
        for (int c = tid; c < LL*DD; c += 128) xs[t][c] = __half2float(xc[rowoff + c]);
    }
    for (int i = tid; i < PP*TT; i += 128) w1[i/TT][i%TT] = w1g[i];
    if (tid < PP) b1[tid] = b1g[tid];
    for (int c = tid; c < LL*DD; c += 128) w2[c] = w2g[c];
    __syncthreads();

    float part[PP];
#pragma unroll
    for (int p = 0; p < PP; ++p) part[p] = 0.f;
    for (int c = tid; c < LL*DD; c += 128) {
        float xt[TT];
#pragma unroll
        for (int t = 0; t < TT; ++t) xt[t] = xs[t][c];
        float wc = w2[c];
#pragma unroll
        for (int p = 0; p < PP; ++p) {
            float sacc = b1[p];
#pragma unroll
            for (int t = 0; t < TT; ++t) sacc = fmaf(xt[t], w1[p][t], sacc);
            sacc = fmaxf(sacc, 0.f);
            part[p] = fmaf(sacc, wc, part[p]);
        }
    }
    const int warp = tid >> 5, lane = tid & 31;
#pragma unroll
    for (int p = 0; p < PP; ++p) {
        float sv = part[p];
#pragma unroll
        for (int o = 16; o; o >>= 1) sv += __shfl_xor_sync(0xffffffffu, sv, o);
        if (lane == 0) red[p][warp] = sv;
    }
    __syncthreads();
    if (tid < PP) {
        float sv = red[tid][0] + red[tid][1] + red[tid][2] + red[tid][3];
        y[(size_t)(b*PP + tid) * NN + n] = sv + b2g[0];
    }
}

// ---------------- launcher ---------------------------------------------------
extern "C" void kernel_launch(void* const* d_in, const int* in_sizes, int n_in,
                              void* d_out, int out_size)
{
    (void)in_sizes; (void)n_in; (void)out_size;
    const float* x      = (const float*)d_in[0];
    const float* tokW   = (const float*)d_in[1];
    const float* tokb   = (const float*)d_in[2];
    const float* t_qkvW = (const float*)d_in[3];
    const float* t_qkvb = (const float*)d_in[4];
    const float* t_pW   = (const float*)d_in[5];
    const float* t_pb   = (const float*)d_in[6];
    const float* g_qkvW = (const float*)d_in[7];
    const float* g_qkvb = (const float*)d_in[8];
    const float* g_pW   = (const float*)d_in[9];
    const float* g_pb   = (const float*)d_in[10];
    const float* s_qkvW = (const float*)d_in[11];
    const float* s_qkvb = (const float*)d_in[12];
    const float* s_pW   = (const float*)d_in[13];
    const float* s_pb   = (const float*)d_in[14];
    const float* resW   = (const float*)d_in[15];
    const float* resb   = (const float*)d_in[16];
    const float* normW  = (const float*)d_in[17];
    const float* normb  = (const float*)d_in[18];
    const float* fc1W   = (const float*)d_in[19];
    const float* fc1b   = (const float*)d_in[20];
    const float* fc2W   = (const float*)d_in[21];
    const float* fc2b   = (const float*)d_in[22];
    const float* e1W    = (const float*)d_in[23];
    const float* e1b    = (const float*)d_in[24];
    const float* e2W    = (const float*)d_in[25];
    const float* e2b    = (const float*)d_in[26];
    float* out = (float*)d_out;

    float *bgsB, *b12B;
    h16 *qkvB, *qkv12B, *xcB;
    cudaGetSymbolAddress((void**)&qkvB,   g_qkv);
    cudaGetSymbolAddress((void**)&qkv12B, g_qkv12);
    cudaGetSymbolAddress((void**)&xcB,    g_xc);
    cudaGetSymbolAddress((void**)&bgsB,   b_gs);
    cudaGetSymbolAddress((void**)&b12B,   b_12);

    h16 *hA,*at,*a2,*ml;
    cudaGetSymbolAddress((void**)&hA, a_hA);
    cudaGetSymbolAddress((void**)&at, a_at);
    cudaGetSymbolAddress((void**)&a2, a_a2);
    cudaGetSymbolAddress((void**)&ml, a_ml);

    h16 *tq,*gsF,*w12,*cb;
    cudaGetSymbolAddress((void**)&tq,  w_tq);
    cudaGetSymbolAddress((void**)&gsF, w_gsF);
    cudaGetSymbolAddress((void**)&w12, w_12F);
    cudaGetSymbolAddress((void**)&cb,  w_cb);

    const int MBt = TOK / 128;
    const int DSM = 61440;
    cudaFuncSetAttribute(mma_gemm, cudaFuncAttributeMaxDynamicSharedMemorySize, DSM);

    setup_all<<<3078, 256>>>(t_qkvW, fc2W, resW,
                             g_qkvW, s_qkvW, g_qkvb, s_qkvb, t_pW, t_pb,
                             fc1W, fc1b, g_pW, g_pb, s_pW, s_pb);

    embed_kernel<<<(TOK*DD)/256, 256>>>(x, tokW, tokb, hA);

    for (int l = 0; l < LL; ++l) {
        const size_t oq = (size_t)l*3*DD*DD, oqb = (size_t)l*3*DD;
        const size_t opb = (size_t)l*DD;
        const size_t ogs = (size_t)l*6*DD*DD;

        // temporal qkv
        mma_gemm<<<dim3(3, MBt), 256, DSM>>>(hA, DD, nullptr, 0, tq+oq,
                                             t_qkvb+oqb, nullptr, qkvB, 3*DD, 0,
                                             nullptr, nullptr, nullptr, nullptr, 0);
        temporal_attn_kernel<<<BB*NN/2, 256>>>(qkvB, at);
        // folded (t_p . gs_qkv)
        mma_gemm<<<dim3(6, MBt), 256, DSM>>>(at, DD, nullptr, 0, gsF+ogs,
                                             bgsB + (size_t)l*768, nullptr, qkv12B, 6*DD, 0,
                                             nullptr, nullptr, nullptr, nullptr, 0);
        // merged spatial attention
        spatial_attn_mma<<<dim3(NN/128, 2*HH, BB*TT), 256>>>(qkv12B, at, a2);
        // folded (proj . fc1) + gelu
        mma_gemm<<<dim3(2, MBt), 256, DSM>>>(at, DD, a2, DD,
                                             w12+(size_t)l*HMM*2*DD,
                                             b12B+(size_t)l*HMM, nullptr,
                                             ml, HMM, 1,
                                             nullptr, nullptr, nullptr, nullptr, 0);
        // fused fc2 + residual-linear + LayerNorm
        mma_gemm<<<dim3(1, MBt), 256, DSM>>>(ml, HMM, hA, DD,
                                             cb+(size_t)l*DD*(HMM+DD),
                                             fc2b+opb, resb+opb,
                                             nullptr, DD, 0,
                                             normW+opb, normb+opb,
                                             hA, xcB + (size_t)l*DD, LL*DD);
    }

    head_kernel<<<BB*NN, 128>>>(xcB, e1W, e1b, e2W, e2b, out);
}

// round 15
// speedup vs baseline: 1.4917x; 1.1507x over previous
#include <cuda_runtime.h>
#include <cuda_fp16.h>
#include <math.h>
#include <stdint.h>

#define BB   8
#define TT   12
#define NN   512
#define FINN 3
#define DD   128
#define HH   4
#define HMM  256
#define LL   3
#define PP   12
#define TOK  (BB*TT*NN)          // 49152 tokens

typedef __half h16;

// ---------------- scratch ----------------------------------------------------
__device__ h16   g_qkv  [TOK*3*DD];
__device__ h16   g_qkv12[TOK*6*DD];
__device__ h16   g_xc [TOK*LL*DD];
__device__ float b_gs [LL*6*DD];
__device__ float b_12 [LL*HMM];
__device__ float g_pe [TT*DD];
// fp16 activations
__device__ h16 a_hA[TOK*DD];
__device__ h16 a_at[TOK*DD];
__device__ h16 a_a2[TOK*DD];
__device__ h16 a_ml[TOK*HMM];
// fp16 weights
__device__ h16 w_tq[LL*3*DD*DD];
__device__ h16 w_gsF[LL*6*DD*DD];
__device__ h16 w_12F[LL*HMM*2*DD];
__device__ h16 w_cb[LL*DD*(HMM+DD)];

__device__ __forceinline__ uint32_t smem_u32(const void* p) {
    uint32_t a;
    asm("{ .reg .u64 t; cvta.to.shared.u64 t, %1; cvt.u32.u64 %0, t; }"
        : "=r"(a) : "l"(p));
    return a;
}
__device__ __forceinline__ uint32_t pack2h(float a, float b) {
    __half2 h = __floats2half2_rn(a, b);
    return *(uint32_t*)&h;
}
#define CP_ASYNC16(dst, src) \
    asm volatile("cp.async.cg.shared.global [%0], [%1], 16;" :: "r"(dst), "l"(src))
#define CP_COMMIT() asm volatile("cp.async.commit_group;" ::: "memory")
#define CP_WAIT(n)  asm volatile("cp.async.wait_group %0;" :: "n"(n) : "memory")

// ================= merged setup: pe | cvt | fold_gs | fold_f1 ================
__global__ void setup_all(const float* __restrict__ t_qkvW,
                          const float* __restrict__ fc2W, const float* __restrict__ resW,
                          const float* __restrict__ gq, const float* __restrict__ sq,
                          const float* __restrict__ gqb, const float* __restrict__ sqb,
                          const float* __restrict__ tpW, const float* __restrict__ tpb,
                          const float* __restrict__ f1W, const float* __restrict__ f1b,
                          const float* __restrict__ gpW, const float* __restrict__ gpb,
                          const float* __restrict__ spW, const float* __restrict__ spb)
{
    const int blk = blockIdx.x;
    if (blk < 6) {                                    // ---- PE table
        int i = blk * 256 + threadIdx.x;
        if (i >= TT*DD) return;
        int t = i / DD, d = i % DD;
        int i2 = d & ~1;
        float div = expf((float)i2 * (-logf(10000.0f) / (float)DD));
        float ang = (float)t * div;
        g_pe[i] = (d & 1) ? cosf(ang) : sinf(ang);
        return;
    }
    if (blk < 1158) {                                 // ---- cvt tq + cb
        int i = (blk - 6) * 256 + threadIdx.x;
        const int NQ  = LL*3*DD*DD;
        const int NCB = LL*DD*(HMM+DD);
        if (i < NQ) { w_tq[i] = __float2half(t_qkvW[i]); return; }
        i -= NQ;
        if (i < NCB) {
            const int KK = HMM + DD;
            int l = i / (DD*KK), r = (i / KK) % DD, k = i % KK;
            float v = (k < HMM) ? fc2W[((size_t)l*DD + r)*HMM + k]
                                : resW[((size_t)l*DD + r)*DD + (k - HMM)];
            w_cb[i] = __float2half(v);
        }
        return;
    }
    if (blk < 2310) {                                 // ---- fold_gs
        int i = (blk - 1158) * 256 + threadIdx.x;
        if (i >= LL*768*DD) return;
        const int l = i / (768*DD);
        const int p = (i / DD) % 768;
        const int k = i % DD;
        const float* grow = (p < 384) ? gq + ((size_t)l*384 + p)*DD
                                      : sq + ((size_t)l*384 + (p-384))*DD;
        const float* tw = tpW + (size_t)l*DD*DD;
        float s = 0.f;
#pragma unroll 8
        for (int o = 0; o < DD; ++o) s += grow[o] * tw[o*DD + k];
        w_gsF[i] = __float2half(s);
        if (k == 0) {
            float bb = (p < 384) ? gqb[l*384 + p] : sqb[l*384 + (p-384)];
            const float* tb = tpb + l*DD;
#pragma unroll 8
            for (int o = 0; o < DD; ++o) bb += grow[o] * tb[o];
            b_gs[l*768 + p] = bb;
        }
        return;
    }
    {                                                 // ---- fold_f1
        int i = (blk - 2310) * 256 + threadIdx.x;
        if (i >= LL*HMM*2*DD) return;
        const int l = i / (HMM*2*DD);
        const int h = (i / (2*DD)) % HMM;
        const int k = i % (2*DD);
        const float* frow = f1W + ((size_t)l*HMM + h)*(2*DD);
        float s = 0.f;
        if (k < DD) {
            const float* pw = gpW + (size_t)l*DD*DD;
#pragma unroll 8
            for (int d = 0; d < DD; ++d) s += frow[d] * pw[d*DD + k];
        } else {
            const float* pw = spW + (size_t)l*DD*DD;
#pragma unroll 8
            for (int d = 0; d < DD; ++d) s += frow[DD + d] * pw[d*DD + (k - DD)];
        }
        w_12F[i] = __float2half(s);
        if (k == 0) {
            float bb = f1b[l*HMM + h];
            const float* gb = gpb + l*DD;
            const float* sb = spb + l*DD;
#pragma unroll 8
            for (int d = 0; d < DD; ++d) bb += frow[d]*gb[d] + frow[DD + d]*sb[d];
            b_12[l*HMM + h] = bb;
        }
    }
}

// ================= fp16 mma GEMM: 3-stage pipeline, one sync/chunk ===========
__global__ void __launch_bounds__(256, 2)
mma_gemm(const h16* __restrict__ A1, int K1, const h16* __restrict__ A2, int K2,
         const h16* __restrict__ W,
         const float* __restrict__ bias, const float* __restrict__ bias2,
         h16* __restrict__ outh, int ldo, int gelu,
         const float* __restrict__ lnW, const float* __restrict__ lnB,
         h16* __restrict__ ln_hout, h16* __restrict__ ln_xc, int ldxc)
{
    extern __shared__ char dsm[];
    h16* As = (h16*)dsm;              // [3][128][40]
    h16* Bs = As + 3*5120;            // [3][128][40]
    float* stage = (float*)dsm;       // LN staging [64][132]

    const int tid  = threadIdx.x;
    const int wid  = tid >> 5;
    const int lane = tid & 31;
    const int l16  = lane & 15;
    const int warp_m = wid >> 2;
    const int warp_n = wid & 3;
    const int m0 = blockIdx.y * 128;
    const int n0 = blockIdx.x * 128;
    const int K  = K1 + K2;
    const int KC = K >> 5;

    float acc[4][4][4];
#pragma unroll
    for (int mi = 0; mi < 4; ++mi)
#pragma unroll
        for (int ni = 0; ni < 4; ++ni)
#pragma unroll
            for (int r = 0; r < 4; ++r) acc[mi][ni][r] = 0.f;

    auto load_chunk = [&](int buf, int kp) {
        const int kof = kp * 32;
        const h16* Asrc; int lda, acol;
        if (kof < K1) { Asrc = A1; lda = K1; acol = kof; }
        else          { Asrc = A2; lda = K2; acol = kof - K1; }
#pragma unroll
        for (int t = 0; t < 2; ++t) {
            const int c   = tid + t * 256;
            const int row = c >> 2;
            const int cc  = (c & 3) * 8;
            CP_ASYNC16(smem_u32(As + buf*5120 + row*40 + cc),
                       Asrc + (size_t)(m0 + row) * lda + acol + cc);
            CP_ASYNC16(smem_u32(Bs + buf*5120 + row*40 + cc),
                       W + (size_t)(n0 + row) * K + kof + cc);
        }
    };

    auto compute = [&](int buf) {
#pragma unroll
        for (int ks = 0; ks < 2; ++ks) {
            const int k = ks * 16;
            uint32_t a[4][4], b[4][2];
#pragma unroll
            for (int mi = 0; mi < 4; ++mi) {
                uint32_t ad = smem_u32(As + buf*5120 + (warp_m*64 + mi*16 + l16)*40 + k + (lane >> 4) * 8);
                asm volatile("ldmatrix.sync.aligned.m8n8.x4.shared.b16 {%0,%1,%2,%3}, [%4];"
                             : "=r"(a[mi][0]), "=r"(a[mi][1]), "=r"(a[mi][2]), "=r"(a[mi][3])
                             : "r"(ad));
            }
#pragma unroll
            for (int ni = 0; ni < 4; ++ni) {
                uint32_t bd = smem_u32(Bs + buf*5120 + (warp_n*32 + ni*8 + (l16 & 7))*40 + k + (l16 >> 3) * 8);
                asm volatile("ldmatrix.sync.aligned.m8n8.x2.shared.b16 {%0,%1}, [%2];"
                             : "=r"(b[ni][0]), "=r"(b[ni][1]) : "r"(bd));
            }
#pragma unroll
            for (int mi = 0; mi < 4; ++mi)
#pragma unroll
                for (int ni = 0; ni < 4; ++ni)
                    asm volatile(
                        "mma.sync.aligned.m16n8k16.row.col.f32.f16.f16.f32 "
                        "{%0,%1,%2,%3}, {%4,%5,%6,%7}, {%8,%9}, {%0,%1,%2,%3};"
                        : "+f"(acc[mi][ni][0]), "+f"(acc[mi][ni][1]),
                          "+f"(acc[mi][ni][2]), "+f"(acc[mi][ni][3])
                        : "r"(a[mi][0]), "r"(a[mi][1]), "r"(a[mi][2]), "r"(a[mi][3]),
                          "r"(b[ni][0]), "r"(b[ni][1]));
        }
    };

    load_chunk(0, 0);
    CP_COMMIT();
    if (KC > 1) { load_chunk(1, 1); CP_COMMIT(); }
    int s2 = 2;
    for (int i = 0; i < KC; ++i) {
        if (i + 1 < KC) CP_WAIT(1); else CP_WAIT(0);
        __syncthreads();
        if (i + 2 < KC) {
            load_chunk(s2, i + 2);
            CP_COMMIT();
            s2 = (s2 == 2) ? 0 : s2 + 1;
        }
        compute(i % 3);
    }
    __syncthreads();

    const int quad = lane >> 2, qi = lane & 3;

    if (lnW == nullptr) {
#pragma unroll
        for (int mi = 0; mi < 4; ++mi)
#pragma unroll
            for (int ni = 0; ni < 4; ++ni)
#pragma unroll
                for (int h = 0; h < 2; ++h) {
                    const int row = m0 + warp_m * 64 + mi * 16 + quad + h * 8;
                    const int col = n0 + warp_n * 32 + ni * 8 + qi * 2;
                    float v0 = acc[mi][ni][h * 2 + 0] + bias[col];
                    float v1 = acc[mi][ni][h * 2 + 1] + bias[col + 1];
                    if (gelu) {
                        v0 = 0.5f * v0 * (1.0f + erff(v0 * 0.70710678118654752f));
                        v1 = 0.5f * v1 * (1.0f + erff(v1 * 0.70710678118654752f));
                    }
                    *(uint32_t*)&outh[(size_t)row * ldo + col] = pack2h(v0, v1);
                }
    } else {
#pragma unroll
        for (int half = 0; half < 2; ++half) {
            __syncthreads();
            if (warp_m == half) {
#pragma unroll
                for (int mi = 0; mi < 4; ++mi)
#pragma unroll
                    for (int ni = 0; ni < 4; ++ni)
#pragma unroll
                        for (int h = 0; h < 2; ++h) {
                            const int rl  = mi * 16 + quad + h * 8;
                            const int col = warp_n * 32 + ni * 8 + qi * 2;
                            stage[rl * 132 + col]     = acc[mi][ni][h*2+0] + bias[col]   + bias2[col];
                            stage[rl * 132 + col + 1] = acc[mi][ni][h*2+1] + bias[col+1] + bias2[col+1];
                        }
            }
            __syncthreads();
#pragma unroll
            for (int rr = 0; rr < 8; ++rr) {
                const int rl = wid * 8 + rr;
                float v[4];
#pragma unroll
                for (int i = 0; i < 4; ++i) v[i] = stage[rl * 132 + lane + 32 * i];
                float s = v[0] + v[1] + v[2] + v[3];
#pragma unroll
                for (int o = 16; o; o >>= 1) s += __shfl_xor_sync(0xffffffffu, s, o);
                const float mean = s * (1.f / 128.f);
                float q = 0.f;
#pragma unroll
                for (int i = 0; i < 4; ++i) { v[i] -= mean; q += v[i] * v[i]; }
#pragma unroll
                for (int o = 16; o; o >>= 1) q += __shfl_xor_sync(0xffffffffu, q, o);
                const float inv = rsqrtf(q * (1.f / 128.f) + 1e-5f);
                const size_t row = (size_t)(m0 + half * 64 + rl);
#pragma unroll
                for (int i = 0; i < 4; ++i) {
                    const int d = lane + 32 * i;
                    const float o = v[i] * inv * lnW[d] + lnB[d];
                    ln_hout[row * DD + d]  = __float2half(o);
                    ln_xc[row * ldxc + d]  = __float2half(o);
                }
            }
        }
    }
}

// ---------------- embedding (PE from table) ----------------------------------
__global__ void embed_kernel(const float* __restrict__ x,
                             const float* __restrict__ tokW,
                             const float* __restrict__ tokb,
                             h16* __restrict__ h)
{
    size_t idx = (size_t)blockIdx.x * 256 + threadIdx.x;
    size_t token = idx >> 7;
    int d = (int)(idx & 127);
    int t = (int)((token / NN) % TT);
    const float* xp = x + token * FINN;
    float val = xp[0]*tokW[d*3+0] + xp[1]*tokW[d*3+1] + xp[2]*tokW[d*3+2]
              + tokb[d] + g_pe[t*DD + d];
    h[idx] = __float2half(val);
}

// ---------------- temporal attention (T=12), 1 node / 128 threads ------------
__global__ void temporal_attn_kernel(const h16* __restrict__ qkv,
                                     h16* __restrict__ outp)
{
    const int bidx = blockIdx.x;
    const int b = bidx >> 9, n = bidx & 511;
    const int tid = threadIdx.x;
    __shared__ float q[TT][DD+4], k[TT][DD+4], v[TT][DD+4];
    __shared__ float S[HH][TT][TT];
#pragma unroll
    for (int t = 0; t < TT; ++t) {
        size_t row = ((size_t)(b*TT + t) * NN + n) * 384;
        q[t][tid] = __half2float(qkv[row + tid]);
        k[t][tid] = __half2float(qkv[row + 128 + tid]);
        v[t][tid] = __half2float(qkv[row + 256 + tid]);
    }
    __syncthreads();
    const float scale = 0.17677669529663687f;
    for (int idx = tid; idx < HH*TT*TT; idx += 128) {
        int hh = idx / (TT*TT);
        int rem = idx - hh*(TT*TT);
        int xx = rem / TT, yy = rem - xx*TT;
        const float4* q4 = (const float4*)&q[xx][hh*32];
        const float4* k4 = (const float4*)&k[yy][hh*32];
        float s = 0.f;
#pragma unroll
        for (int e = 0; e < 8; ++e) {
            float4 qa = q4[e], kb = k4[e];
            s = fmaf(qa.x, kb.x, s); s = fmaf(qa.y, kb.y, s);
            s = fmaf(qa.z, kb.z, s); s = fmaf(qa.w, kb.w, s);
        }
        S[hh][xx][yy] = s * scale;
    }
    __syncthreads();
    if (tid < HH*TT) {
        int hh = tid / TT, xx = tid % TT;
        float mx = -1e30f;
#pragma unroll
        for (int y = 0; y < TT; ++y) mx = fmaxf(mx, S[hh][xx][y]);
        float sum = 0.f;
#pragma unroll
        for (int y = 0; y < TT; ++y) { float p = __expf(S[hh][xx][y]-mx); S[hh][xx][y] = p; sum += p; }
        float inv = 1.f / sum;
#pragma unroll
        for (int y = 0; y < TT; ++y) S[hh][xx][y] *= inv;
    }
    __syncthreads();
    const int hh = tid >> 5;
    float vr[TT];
#pragma unroll
    for (int yy = 0; yy < TT; ++yy) vr[yy] = v[yy][tid];
#pragma unroll
    for (int xx = 0; xx < TT; ++xx) {
        float o = 0.f;
#pragma unroll
        for (int yy = 0; yy < TT; ++yy) o = fmaf(S[hh][xx][yy], vr[yy], o);
        outp[((size_t)(b*TT + xx) * NN + n) * DD + tid] = __float2half(o);
    }
}

// ============ merged spatial attention (geo+sem, flash, fp16 in/out) =========
// V stored row-major, consumed via ldmatrix.trans (no scatter transpose).
__global__ void __launch_bounds__(256, 2)
spatial_attn_mma(const h16* __restrict__ qkv,
                 h16* __restrict__ gout, h16* __restrict__ sout)
{
    const int qtile = blockIdx.x;
    const int sel   = blockIdx.y >> 2;
    const int head  = blockIdx.y & 3;
    const int bt    = blockIdx.z;
    const int tid  = threadIdx.x;
    const int wid  = tid >> 5;
    const int lane = tid & 31;
    const int l16  = lane & 15;

    h16* outp = sel ? sout : gout;
    const int colq = sel * 384 + head * 32;

    __shared__ __half Qs[128][40];
    __shared__ __half Ks[128][40];
    __shared__ __half Vs[128][40];    // row-major [j][e]

    const size_t base = (size_t)bt * NN;
    const float scale = 0.17677669529663687f;
    const __half2 hs2 = __floats2half2_rn(scale, scale);

    for (int i = tid; i < 128*4; i += 256) {
        int r = i >> 2, ec = (i & 3) * 8;
        uint4 vq = *(const uint4*)(qkv + (base + (size_t)qtile*128 + r)*768 + colq + ec);
        __half2* p = (__half2*)&vq;
#pragma unroll
        for (int z = 0; z < 4; ++z) p[z] = __hmul2(p[z], hs2);
        *(uint4*)&Qs[r][ec] = vq;
    }
    __syncthreads();

    uint32_t qf[2][4];
#pragma unroll
    for (int kc = 0; kc < 2; ++kc) {
        uint32_t ad = smem_u32(&Qs[wid*16 + l16][kc*16 + (lane>>4)*8]);
        asm volatile("ldmatrix.sync.aligned.m8n8.x4.shared.b16 {%0,%1,%2,%3}, [%4];"
                     : "=r"(qf[kc][0]), "=r"(qf[kc][1]), "=r"(qf[kc][2]), "=r"(qf[kc][3])
                     : "r"(ad));
    }

    float m0 = -1e30f, m1 = -1e30f, l0 = 0.f, l1 = 0.f;
    float oacc[4][4];
#pragma unroll
    for (int ef = 0; ef < 4; ++ef)
#pragma unroll
        for (int r = 0; r < 4; ++r) oacc[ef][r] = 0.f;

    for (int kt = 0; kt < 4; ++kt) {
        __syncthreads();
        for (int i = tid; i < 128*4; i += 256) {
            int j = i >> 2, ec = (i & 3) * 8;
            const h16* rp = qkv + (base + (size_t)kt*128 + j)*768 + colq + 128 + ec;
            *(uint4*)&Ks[j][ec] = *(const uint4*)rp;
            *(uint4*)&Vs[j][ec] = *(const uint4*)(rp + 128);
        }
        __syncthreads();

        float sacc[16][4];
#pragma unroll
        for (int nf = 0; nf < 16; ++nf) {
            sacc[nf][0] = sacc[nf][1] = sacc[nf][2] = sacc[nf][3] = 0.f;
#pragma unroll
            for (int kc = 0; kc < 2; ++kc) {
                uint32_t b0, b1;
                uint32_t bd = smem_u32(&Ks[nf*8 + (l16 & 7)][kc*16 + (l16 >> 3)*8]);
                asm volatile("ldmatrix.sync.aligned.m8n8.x2.shared.b16 {%0,%1}, [%2];"
                             : "=r"(b0), "=r"(b1) : "r"(bd));
                asm volatile(
                    "mma.sync.aligned.m16n8k16.row.col.f32.f16.f16.f32 "
                    "{%0,%1,%2,%3}, {%4,%5,%6,%7}, {%8,%9}, {%0,%1,%2,%3};"
                    : "+f"(sacc[nf][0]), "+f"(sacc[nf][1]),
                      "+f"(sacc[nf][2]), "+f"(sacc[nf][3])
                    : "r"(qf[kc][0]), "r"(qf[kc][1]), "r"(qf[kc][2]), "r"(qf[kc][3]),
                      "r"(b0), "r"(b1));
            }
        }

        float mx0 = -1e30f, mx1 = -1e30f;
#pragma unroll
        for (int nf = 0; nf < 16; ++nf) {
            mx0 = fmaxf(mx0, fmaxf(sacc[nf][0], sacc[nf][1]));
            mx1 = fmaxf(mx1, fmaxf(sacc[nf][2], sacc[nf][3]));
        }
        mx0 = fmaxf(mx0, __shfl_xor_sync(0xffffffffu, mx0, 1));
        mx0 = fmaxf(mx0, __shfl_xor_sync(0xffffffffu, mx0, 2));
        mx1 = fmaxf(mx1, __shfl_xor_sync(0xffffffffu, mx1, 1));
        mx1 = fmaxf(mx1, __shfl_xor_sync(0xffffffffu, mx1, 2));
        const float nm0 = fmaxf(m0, mx0), nm1 = fmaxf(m1, mx1);
        const float c0 = __expf(m0 - nm0), c1 = __expf(m1 - nm1);
        m0 = nm0; m1 = nm1;
#pragma unroll
        for (int ef = 0; ef < 4; ++ef) {
            oacc[ef][0] *= c0; oacc[ef][1] *= c0;
            oacc[ef][2] *= c1; oacc[ef][3] *= c1;
        }

        float rs0 = 0.f, rs1 = 0.f;
#pragma unroll
        for (int jc = 0; jc < 8; ++jc) {
            float p00 = __expf(sacc[2*jc][0]   - nm0);
            float p01 = __expf(sacc[2*jc][1]   - nm0);
            float p10 = __expf(sacc[2*jc][2]   - nm1);
            float p11 = __expf(sacc[2*jc][3]   - nm1);
            float p20 = __expf(sacc[2*jc+1][0] - nm0);
            float p21 = __expf(sacc[2*jc+1][1] - nm0);
            float p30 = __expf(sacc[2*jc+1][2] - nm1);
            float p31 = __expf(sacc[2*jc+1][3] - nm1);
            rs0 += p00 + p01 + p20 + p21;
            rs1 += p10 + p11 + p30 + p31;
            uint32_t pf0 = pack2h(p00, p01);
            uint32_t pf1 = pack2h(p10, p11);
            uint32_t pf2 = pack2h(p20, p21);
            uint32_t pf3 = pack2h(p30, p31);
#pragma unroll
            for (int ef = 0; ef < 4; ++ef) {
                uint32_t b0, b1;
                uint32_t bd = smem_u32(&Vs[jc*16 + l16][ef*8]);
                asm volatile("ldmatrix.sync.aligned.m8n8.x2.trans.shared.b16 {%0,%1}, [%2];"
                             : "=r"(b0), "=r"(b1) : "r"(bd));
                asm volatile(
                    "mma.sync.aligned.m16n8k16.row.col.f32.f16.f16.f32 "
                    "{%0,%1,%2,%3}, {%4,%5,%6,%7}, {%8,%9}, {%0,%1,%2,%3};"
                    : "+f"(oacc[ef][0]), "+f"(oacc[ef][1]),
                      "+f"(oacc[ef][2]), "+f"(oacc[ef][3])
                    : "r"(pf0), "r"(pf1), "r"(pf2), "r"(pf3),
                      "r"(b0), "r"(b1));
            }
        }
        rs0 += __shfl_xor_sync(0xffffffffu, rs0, 1);
        rs0 += __shfl_xor_sync(0xffffffffu, rs0, 2);
        rs1 += __shfl_xor_sync(0xffffffffu, rs1, 1);
        rs1 += __shfl_xor_sync(0xffffffffu, rs1, 2);
        l0 = l0 * c0 + rs0;
        l1 = l1 * c1 + rs1;
    }

    const float i0 = 1.f / l0, i1 = 1.f / l1;
    const int r0 = wid*16 + (lane >> 2);
#pragma unroll
    for (int ef = 0; ef < 4; ++ef) {
        const int col = head*32 + ef*8 + (lane & 3)*2;
        size_t rowA = (base + (size_t)qtile*128 + r0) * DD + col;
        size_t rowB = (base + (size_t)qtile*128 + r0 + 8) * DD + col;
        *(uint32_t*)&outp[rowA] = pack2h(oacc[ef][0] * i0, oacc[ef][1] * i0);
        *(uint32_t*)&outp[rowB] = pack2h(oacc[ef][2] * i1, oacc[ef][3] * i1);
    }
}

// ---------------- output head (fp16 xc, vectorized loads) --------------------
__global__ void head_kernel(const h16* __restrict__ xc, const float* __restrict__ w1g,
                            const float* __restrict__ b1g, const float* __restrict__ w2g,
                            const float* __restrict__ b2g, float* __restrict__ y)
{
    const int bidx = blockIdx.x;
    const int b = bidx >> 9, n = bidx & 511;
    const int tid = threadIdx.x;
    __shared__ float xs[TT][LL*DD];
    __shared__ float w1[PP][TT];
    __shared__ float b1[PP];
    __shared__ float w2[LL*DD];
    __shared__ float red[PP][4];
    // vectorized: 12 rows x 48 uint4 chunks of 8 halves
    for (int i = tid; i < TT*48; i += 128) {
        int t = i / 48, c = i - (i / 48) * 48;
        uint4 vv = *(const uint4*)(xc + ((size_t)(b*TT + t) * NN + n) * (LL*DD) + c * 8);
        h16 tmp[8]; *(uint4*)tmp = vv;
        float* dst = &xs[t][c * 8];
#pragma unroll
        for (int z = 0; z < 8; ++z) dst[z] = __half2float(tmp[z]);
    }
    for (int i = tid; i < PP*TT; i += 128) w1[i/TT][i%TT] = w1g[i];
    if (tid < PP) b1[tid] = b1g[tid];
    for (int c = tid; c < LL*DD; c += 128) w2[c] = w2g[c];
    __syncthreads();

    float part[PP];
#pragma unroll
    for (int p = 0; p < PP; ++p) part[p] = 0.f;
    for (int c = tid; c < LL*DD; c += 128) {
        float xt[TT];
#pragma unroll
        for (int t = 0; t < TT; ++t) xt[t] = xs[t][c];
        float wc = w2[c];
#pragma unroll
        for (int p = 0; p < PP; ++p) {
            float sacc = b1[p];
#pragma unroll
            for (int t = 0; t < TT; ++t) sacc = fmaf(xt[t], w1[p][t], sacc);
            sacc = fmaxf(sacc, 0.f);
            part[p] = fmaf(sacc, wc, part[p]);
        }
    }
    const int warp = tid >> 5, lane = tid & 31;
#pragma unroll
    for (int p = 0; p < PP; ++p) {
        float sv = part[p];
#pragma unroll
        for (int o = 16; o; o >>= 1) sv += __shfl_xor_sync(0xffffffffu, sv, o);
        if (lane == 0) red[p][warp] = sv;
    }
    __syncthreads();
    if (tid < PP) {
        float sv = red[tid][0] + red[tid][1] + red[tid][2] + red[tid][3];
        y[(size_t)(b*PP + tid) * NN + n] = sv + b2g[0];
    }
}

// ---------------- launcher ---------------------------------------------------
extern "C" void kernel_launch(void* const* d_in, const int* in_sizes, int n_in,
                              void* d_out, int out_size)
{
    (void)in_sizes; (void)n_in; (void)out_size;
    const float* x      = (const float*)d_in[0];
    const float* tokW   = (const float*)d_in[1];
    const float* tokb   = (const float*)d_in[2];
    const float* t_qkvW = (const float*)d_in[3];
    const float* t_qkvb = (const float*)d_in[4];
    const float* t_pW   = (const float*)d_in[5];
    const float* t_pb   = (const float*)d_in[6];
    const float* g_qkvW = (const float*)d_in[7];
    const float* g_qkvb = (const float*)d_in[8];
    const float* g_pW   = (const float*)d_in[9];
    const float* g_pb   = (const float*)d_in[10];
    const float* s_qkvW = (const float*)d_in[11];
    const float* s_qkvb = (const float*)d_in[12];
    const float* s_pW   = (const float*)d_in[13];
    const float* s_pb   = (const float*)d_in[14];
    const float* resW   = (const float*)d_in[15];
    const float* resb   = (const float*)d_in[16];
    const float* normW  = (const float*)d_in[17];
    const float* normb  = (const float*)d_in[18];
    const float* fc1W   = (const float*)d_in[19];
    const float* fc1b   = (const float*)d_in[20];
    const float* fc2W   = (const float*)d_in[21];
    const float* fc2b   = (const float*)d_in[22];
    const float* e1W    = (const float*)d_in[23];
    const float* e1b    = (const float*)d_in[24];
    const float* e2W    = (const float*)d_in[25];
    const float* e2b    = (const float*)d_in[26];
    float* out = (float*)d_out;

    float *bgsB, *b12B;
    h16 *qkvB, *qkv12B, *xcB;
    cudaGetSymbolAddress((void**)&qkvB,   g_qkv);
    cudaGetSymbolAddress((void**)&qkv12B, g_qkv12);
    cudaGetSymbolAddress((void**)&xcB,    g_xc);
    cudaGetSymbolAddress((void**)&bgsB,   b_gs);
    cudaGetSymbolAddress((void**)&b12B,   b_12);

    h16 *hA,*at,*a2,*ml;
    cudaGetSymbolAddress((void**)&hA, a_hA);
    cudaGetSymbolAddress((void**)&at, a_at);
    cudaGetSymbolAddress((void**)&a2, a_a2);
    cudaGetSymbolAddress((void**)&ml, a_ml);

    h16 *tq,*gsF,*w12,*cb;
    cudaGetSymbolAddress((void**)&tq,  w_tq);
    cudaGetSymbolAddress((void**)&gsF, w_gsF);
    cudaGetSymbolAddress((void**)&w12, w_12F);
    cudaGetSymbolAddress((void**)&cb,  w_cb);

    const int MBt = TOK / 128;
    const int DSM = 61440;
    cudaFuncSetAttribute(mma_gemm, cudaFuncAttributeMaxDynamicSharedMemorySize, DSM);

    setup_all<<<3078, 256>>>(t_qkvW, fc2W, resW,
                             g_qkvW, s_qkvW, g_qkvb, s_qkvb, t_pW, t_pb,
                             fc1W, fc1b, g_pW, g_pb, s_pW, s_pb);

    embed_kernel<<<(TOK*DD)/256, 256>>>(x, tokW, tokb, hA);

    for (int l = 0; l < LL; ++l) {
        const size_t oq = (size_t)l*3*DD*DD, oqb = (size_t)l*3*DD;
        const size_t opb = (size_t)l*DD;
        const size_t ogs = (size_t)l*6*DD*DD;

        // temporal qkv
        mma_gemm<<<dim3(3, MBt), 256, DSM>>>(hA, DD, nullptr, 0, tq+oq,
                                             t_qkvb+oqb, nullptr, qkvB, 3*DD, 0,
                                             nullptr, nullptr, nullptr, nullptr, 0);
        temporal_attn_kernel<<<BB*NN, 128>>>(qkvB, at);
        // folded (t_p . gs_qkv)
        mma_gemm<<<dim3(6, MBt), 256, DSM>>>(at, DD, nullptr, 0, gsF+ogs,
                                             bgsB + (size_t)l*768, nullptr, qkv12B, 6*DD, 0,
                                             nullptr, nullptr, nullptr, nullptr, 0);
        // merged spatial attention
        spatial_attn_mma<<<dim3(NN/128, 2*HH, BB*TT), 256>>>(qkv12B, at, a2);
        // folded (proj . fc1) + gelu
        mma_gemm<<<dim3(2, MBt), 256, DSM>>>(at, DD, a2, DD,
                                             w12+(size_t)l*HMM*2*DD,
                                             b12B+(size_t)l*HMM, nullptr,
                                             ml, HMM, 1,
                                             nullptr, nullptr, nullptr, nullptr, 0);
        // fused fc2 + residual-linear + LayerNorm
        mma_gemm<<<dim3(1, MBt), 256, DSM>>>(ml, HMM, hA, DD,
                                             cb+(size_t)l*DD*(HMM+DD),
                                             fc2b+opb, resb+opb,
                                             nullptr, DD, 0,
                                             normW+opb, normb+opb,
                                             hA, xcB + (size_t)l*DD, LL*DD);
    }

    head_kernel<<<BB*NN, 128>>>(xcB, e1W, e1b, e2W, e2b, out);
}

// round 16
// speedup vs baseline: 1.5804x; 1.0595x over previous
#include <cuda_runtime.h>
#include <cuda_fp16.h>
#include <math.h>
#include <stdint.h>

#define BB   8
#define TT   12
#define NN   512
#define FINN 3
#define DD   128
#define HH   4
#define HMM  256
#define LL   3
#define PP   12
#define TOK  (BB*TT*NN)          // 49152 tokens

typedef __half h16;

// ---------------- scratch ----------------------------------------------------
__device__ h16   g_qkv  [TOK*3*DD];
__device__ h16   g_qkv12[TOK*6*DD];
__device__ h16   g_xc [TOK*LL*DD];
__device__ float b_gs [LL*6*DD];
__device__ float b_12 [LL*HMM];
__device__ float g_pe [TT*DD];
// fp16 activations
__device__ h16 a_hA[TOK*DD];
__device__ h16 a_at[TOK*DD];
__device__ h16 a_a2[TOK*DD];
__device__ h16 a_ml[TOK*HMM];
// fp16 weights
__device__ h16 w_tq[LL*3*DD*DD];
__device__ h16 w_gsF[LL*6*DD*DD];
__device__ h16 w_12F[LL*HMM*2*DD];
__device__ h16 w_cb[LL*DD*(HMM+DD)];

__device__ __forceinline__ uint32_t smem_u32(const void* p) {
    uint32_t a;
    asm("{ .reg .u64 t; cvta.to.shared.u64 t, %1; cvt.u32.u64 %0, t; }"
        : "=r"(a) : "l"(p));
    return a;
}
__device__ __forceinline__ uint32_t pack2h(float a, float b) {
    __half2 h = __floats2half2_rn(a, b);
    return *(uint32_t*)&h;
}
#define CP_ASYNC16(dst, src) \
    asm volatile("cp.async.cg.shared.global [%0], [%1], 16;" :: "r"(dst), "l"(src))
#define CP_COMMIT() asm volatile("cp.async.commit_group;" ::: "memory")
#define CP_WAIT(n)  asm volatile("cp.async.wait_group %0;" :: "n"(n) : "memory")

// ================= merged setup: pe | cvt | fold_gs | fold_f1 ================
__global__ void setup_all(const float* __restrict__ t_qkvW,
                          const float* __restrict__ fc2W, const float* __restrict__ resW,
                          const float* __restrict__ gq, const float* __restrict__ sq,
                          const float* __restrict__ gqb, const float* __restrict__ sqb,
                          const float* __restrict__ tpW, const float* __restrict__ tpb,
                          const float* __restrict__ f1W, const float* __restrict__ f1b,
                          const float* __restrict__ gpW, const float* __restrict__ gpb,
                          const float* __restrict__ spW, const float* __restrict__ spb)
{
    const int blk = blockIdx.x;
    if (blk < 6) {
        int i = blk * 256 + threadIdx.x;
        if (i >= TT*DD) return;
        int t = i / DD, d = i % DD;
        int i2 = d & ~1;
        float div = expf((float)i2 * (-logf(10000.0f) / (float)DD));
        float ang = (float)t * div;
        g_pe[i] = (d & 1) ? cosf(ang) : sinf(ang);
        return;
    }
    if (blk < 1158) {
        int i = (blk - 6) * 256 + threadIdx.x;
        const int NQ  = LL*3*DD*DD;
        const int NCB = LL*DD*(HMM+DD);
        if (i < NQ) { w_tq[i] = __float2half(t_qkvW[i]); return; }
        i -= NQ;
        if (i < NCB) {
            const int KK = HMM + DD;
            int l = i / (DD*KK), r = (i / KK) % DD, k = i % KK;
            float v = (k < HMM) ? fc2W[((size_t)l*DD + r)*HMM + k]
                                : resW[((size_t)l*DD + r)*DD + (k - HMM)];
            w_cb[i] = __float2half(v);
        }
        return;
    }
    if (blk < 2310) {
        int i = (blk - 1158) * 256 + threadIdx.x;
        if (i >= LL*768*DD) return;
        const int l = i / (768*DD);
        const int p = (i / DD) % 768;
        const int k = i % DD;
        const float* grow = (p < 384) ? gq + ((size_t)l*384 + p)*DD
                                      : sq + ((size_t)l*384 + (p-384))*DD;
        const float* tw = tpW + (size_t)l*DD*DD;
        float s = 0.f;
#pragma unroll 8
        for (int o = 0; o < DD; ++o) s += grow[o] * tw[o*DD + k];
        w_gsF[i] = __float2half(s);
        if (k == 0) {
            float bb = (p < 384) ? gqb[l*384 + p] : sqb[l*384 + (p-384)];
            const float* tb = tpb + l*DD;
#pragma unroll 8
            for (int o = 0; o < DD; ++o) bb += grow[o] * tb[o];
            b_gs[l*768 + p] = bb;
        }
        return;
    }
    {
        int i = (blk - 2310) * 256 + threadIdx.x;
        if (i >= LL*HMM*2*DD) return;
        const int l = i / (HMM*2*DD);
        const int h = (i / (2*DD)) % HMM;
        const int k = i % (2*DD);
        const float* frow = f1W + ((size_t)l*HMM + h)*(2*DD);
        float s = 0.f;
        if (k < DD) {
            const float* pw = gpW + (size_t)l*DD*DD;
#pragma unroll 8
            for (int d = 0; d < DD; ++d) s += frow[d] * pw[d*DD + k];
        } else {
            const float* pw = spW + (size_t)l*DD*DD;
#pragma unroll 8
            for (int d = 0; d < DD; ++d) s += frow[DD + d] * pw[d*DD + (k - DD)];
        }
        w_12F[i] = __float2half(s);
        if (k == 0) {
            float bb = f1b[l*HMM + h];
            const float* gb = gpb + l*DD;
            const float* sb = spb + l*DD;
#pragma unroll 8
            for (int d = 0; d < DD; ++d) bb += frow[d]*gb[d] + frow[DD + d]*sb[d];
            b_12[l*HMM + h] = bb;
        }
    }
}

// ================= fp16 mma GEMM: 3-stage pipeline, one sync/chunk ===========
__global__ void __launch_bounds__(256, 2)
mma_gemm(const h16* __restrict__ A1, int K1, const h16* __restrict__ A2, int K2,
         const h16* __restrict__ W,
         const float* __restrict__ bias, const float* __restrict__ bias2,
         h16* __restrict__ outh, int ldo, int gelu,
         const float* __restrict__ lnW, const float* __restrict__ lnB,
         h16* __restrict__ ln_hout, h16* __restrict__ ln_xc, int ldxc)
{
    extern __shared__ char dsm[];
    h16* As = (h16*)dsm;              // [3][128][40]
    h16* Bs = As + 3*5120;            // [3][128][40]
    float* stage = (float*)dsm;       // LN staging [64][132]

    const int tid  = threadIdx.x;
    const int wid  = tid >> 5;
    const int lane = tid & 31;
    const int l16  = lane & 15;
    const int warp_m = wid >> 2;
    const int warp_n = wid & 3;
    const int m0 = blockIdx.y * 128;
    const int n0 = blockIdx.x * 128;
    const int K  = K1 + K2;
    const int KC = K >> 5;

    float acc[4][4][4];
#pragma unroll
    for (int mi = 0; mi < 4; ++mi)
#pragma unroll
        for (int ni = 0; ni < 4; ++ni)
#pragma unroll
            for (int r = 0; r < 4; ++r) acc[mi][ni][r] = 0.f;

    auto load_chunk = [&](int buf, int kp) {
        const int kof = kp * 32;
        const h16* Asrc; int lda, acol;
        if (kof < K1) { Asrc = A1; lda = K1; acol = kof; }
        else          { Asrc = A2; lda = K2; acol = kof - K1; }
#pragma unroll
        for (int t = 0; t < 2; ++t) {
            const int c   = tid + t * 256;
            const int row = c >> 2;
            const int cc  = (c & 3) * 8;
            CP_ASYNC16(smem_u32(As + buf*5120 + row*40 + cc),
                       Asrc + (size_t)(m0 + row) * lda + acol + cc);
            CP_ASYNC16(smem_u32(Bs + buf*5120 + row*40 + cc),
                       W + (size_t)(n0 + row) * K + kof + cc);
        }
    };

    auto compute = [&](int buf) {
#pragma unroll
        for (int ks = 0; ks < 2; ++ks) {
            const int k = ks * 16;
            uint32_t a[4][4], b[4][2];
#pragma unroll
            for (int mi = 0; mi < 4; ++mi) {
                uint32_t ad = smem_u32(As + buf*5120 + (warp_m*64 + mi*16 + l16)*40 + k + (lane >> 4) * 8);
                asm volatile("ldmatrix.sync.aligned.m8n8.x4.shared.b16 {%0,%1,%2,%3}, [%4];"
                             : "=r"(a[mi][0]), "=r"(a[mi][1]), "=r"(a[mi][2]), "=r"(a[mi][3])
                             : "r"(ad));
            }
#pragma unroll
            for (int ni = 0; ni < 4; ++ni) {
                uint32_t bd = smem_u32(Bs + buf*5120 + (warp_n*32 + ni*8 + (l16 & 7))*40 + k + (l16 >> 3) * 8);
                asm volatile("ldmatrix.sync.aligned.m8n8.x2.shared.b16 {%0,%1}, [%2];"
                             : "=r"(b[ni][0]), "=r"(b[ni][1]) : "r"(bd));
            }
#pragma unroll
            for (int mi = 0; mi < 4; ++mi)
#pragma unroll
                for (int ni = 0; ni < 4; ++ni)
                    asm volatile(
                        "mma.sync.aligned.m16n8k16.row.col.f32.f16.f16.f32 "
                        "{%0,%1,%2,%3}, {%4,%5,%6,%7}, {%8,%9}, {%0,%1,%2,%3};"
                        : "+f"(acc[mi][ni][0]), "+f"(acc[mi][ni][1]),
                          "+f"(acc[mi][ni][2]), "+f"(acc[mi][ni][3])
                        : "r"(a[mi][0]), "r"(a[mi][1]), "r"(a[mi][2]), "r"(a[mi][3]),
                          "r"(b[ni][0]), "r"(b[ni][1]));
        }
    };

    load_chunk(0, 0);
    CP_COMMIT();
    if (KC > 1) { load_chunk(1, 1); CP_COMMIT(); }
    int s2 = 2;
    for (int i = 0; i < KC; ++i) {
        if (i + 1 < KC) CP_WAIT(1); else CP_WAIT(0);
        __syncthreads();
        if (i + 2 < KC) {
            load_chunk(s2, i + 2);
            CP_COMMIT();
            s2 = (s2 == 2) ? 0 : s2 + 1;
        }
        compute(i % 3);
    }
    __syncthreads();

    const int quad = lane >> 2, qi = lane & 3;

    if (lnW == nullptr) {
#pragma unroll
        for (int mi = 0; mi < 4; ++mi)
#pragma unroll
            for (int ni = 0; ni < 4; ++ni)
#pragma unroll
                for (int h = 0; h < 2; ++h) {
                    const int row = m0 + warp_m * 64 + mi * 16 + quad + h * 8;
                    const int col = n0 + warp_n * 32 + ni * 8 + qi * 2;
                    float v0 = acc[mi][ni][h * 2 + 0] + bias[col];
                    float v1 = acc[mi][ni][h * 2 + 1] + bias[col + 1];
                    if (gelu) {
                        v0 = 0.5f * v0 * (1.0f + erff(v0 * 0.70710678118654752f));
                        v1 = 0.5f * v1 * (1.0f + erff(v1 * 0.70710678118654752f));
                    }
                    *(uint32_t*)&outh[(size_t)row * ldo + col] = pack2h(v0, v1);
                }
    } else {
#pragma unroll
        for (int half = 0; half < 2; ++half) {
            __syncthreads();
            if (warp_m == half) {
#pragma unroll
                for (int mi = 0; mi < 4; ++mi)
#pragma unroll
                    for (int ni = 0; ni < 4; ++ni)
#pragma unroll
                        for (int h = 0; h < 2; ++h) {
                            const int rl  = mi * 16 + quad + h * 8;
                            const int col = warp_n * 32 + ni * 8 + qi * 2;
                            stage[rl * 132 + col]     = acc[mi][ni][h*2+0] + bias[col]   + bias2[col];
                            stage[rl * 132 + col + 1] = acc[mi][ni][h*2+1] + bias[col+1] + bias2[col+1];
                        }
            }
            __syncthreads();
#pragma unroll
            for (int rr = 0; rr < 8; ++rr) {
                const int rl = wid * 8 + rr;
                float v[4];
#pragma unroll
                for (int i = 0; i < 4; ++i) v[i] = stage[rl * 132 + lane + 32 * i];
                float s = v[0] + v[1] + v[2] + v[3];
#pragma unroll
                for (int o = 16; o; o >>= 1) s += __shfl_xor_sync(0xffffffffu, s, o);
                const float mean = s * (1.f / 128.f);
                float q = 0.f;
#pragma unroll
                for (int i = 0; i < 4; ++i) { v[i] -= mean; q += v[i] * v[i]; }
#pragma unroll
                for (int o = 16; o; o >>= 1) q += __shfl_xor_sync(0xffffffffu, q, o);
                const float inv = rsqrtf(q * (1.f / 128.f) + 1e-5f);
                const size_t row = (size_t)(m0 + half * 64 + rl);
#pragma unroll
                for (int i = 0; i < 4; ++i) {
                    const int d = lane + 32 * i;
                    const float o = v[i] * inv * lnW[d] + lnB[d];
                    ln_hout[row * DD + d]  = __float2half(o);
                    ln_xc[row * ldxc + d]  = __float2half(o);
                }
            }
        }
    }
}

// ---------------- embedding (PE from table) ----------------------------------
__global__ void embed_kernel(const float* __restrict__ x,
                             const float* __restrict__ tokW,
                             const float* __restrict__ tokb,
                             h16* __restrict__ h)
{
    size_t idx = (size_t)blockIdx.x * 256 + threadIdx.x;
    size_t token = idx >> 7;
    int d = (int)(idx & 127);
    int t = (int)((token / NN) % TT);
    const float* xp = x + token * FINN;
    float val = xp[0]*tokW[d*3+0] + xp[1]*tokW[d*3+1] + xp[2]*tokW[d*3+2]
              + tokb[d] + g_pe[t*DD + d];
    h[idx] = __float2half(val);
}

// ---------------- temporal attention (T=12), fp16 smem + half2 dot -----------
__global__ void temporal_attn_kernel(const h16* __restrict__ qkv,
                                     h16* __restrict__ outp)
{
    const int bidx = blockIdx.x;
    const int b = bidx >> 9, n = bidx & 511;
    const int tid = threadIdx.x;
    __shared__ h16 q[TT][DD+8], k[TT][DD+8], v[TT][DD+8];   // 272B rows
    __shared__ float S[HH][TT][TT];
#pragma unroll
    for (int t = 0; t < TT; ++t) {
        size_t row = ((size_t)(b*TT + t) * NN + n) * 384;
        q[t][tid] = qkv[row + tid];
        k[t][tid] = qkv[row + 128 + tid];
        v[t][tid] = qkv[row + 256 + tid];
    }
    __syncthreads();
    const float scale = 0.17677669529663687f;
    for (int idx = tid; idx < HH*TT*TT; idx += 128) {
        int hh = idx / (TT*TT);
        int rem = idx - hh*(TT*TT);
        int xx = rem / TT, yy = rem - xx*TT;
        const __half2* q2 = (const __half2*)&q[xx][hh*32];
        const __half2* k2 = (const __half2*)&k[yy][hh*32];
        float s = 0.f;
#pragma unroll
        for (int e = 0; e < 16; ++e) {
            float2 p = __half22float2(__hmul2(q2[e], k2[e]));
            s += p.x + p.y;
        }
        S[hh][xx][yy] = s * scale;
    }
    __syncthreads();
    if (tid < HH*TT) {
        int hh = tid / TT, xx = tid % TT;
        float mx = -1e30f;
#pragma unroll
        for (int y = 0; y < TT; ++y) mx = fmaxf(mx, S[hh][xx][y]);
        float sum = 0.f;
#pragma unroll
        for (int y = 0; y < TT; ++y) { float p = __expf(S[hh][xx][y]-mx); S[hh][xx][y] = p; sum += p; }
        float inv = 1.f / sum;
#pragma unroll
        for (int y = 0; y < TT; ++y) S[hh][xx][y] *= inv;
    }
    __syncthreads();
    const int hh = tid >> 5;
    float vr[TT];
#pragma unroll
    for (int yy = 0; yy < TT; ++yy) vr[yy] = __half2float(v[yy][tid]);
#pragma unroll
    for (int xx = 0; xx < TT; ++xx) {
        float o = 0.f;
#pragma unroll
        for (int yy = 0; yy < TT; ++yy) o = fmaf(S[hh][xx][yy], vr[yy], o);
        outp[((size_t)(b*TT + xx) * NN + n) * DD + tid] = __float2half(o);
    }
}

// ============ merged spatial attention: double-buffered K/V (cp.async) =======
__global__ void __launch_bounds__(256, 2)
spatial_attn_mma(const h16* __restrict__ qkv,
                 h16* __restrict__ gout, h16* __restrict__ sout)
{
    const int qtile = blockIdx.x;
    const int sel   = blockIdx.y >> 2;
    const int head  = blockIdx.y & 3;
    const int bt    = blockIdx.z;
    const int tid  = threadIdx.x;
    const int wid  = tid >> 5;
    const int lane = tid & 31;
    const int l16  = lane & 15;

    h16* outp = sel ? sout : gout;
    const int colq = sel * 384 + head * 32;

    __shared__ __half Qs[128][40];
    __shared__ __half Ks[2][128][40];
    __shared__ __half Vs[2][128][40];

    const size_t base = (size_t)bt * NN;
    const float scale = 0.17677669529663687f;
    const __half2 hs2 = __floats2half2_rn(scale, scale);

    auto load_kv = [&](int buf, int kt) {
        for (int i = tid; i < 128*4; i += 256) {
            int j = i >> 2, ec = (i & 3) * 8;
            const h16* rp = qkv + (base + (size_t)kt*128 + j)*768 + colq + 128 + ec;
            CP_ASYNC16(smem_u32(&Ks[buf][j][ec]), rp);
            CP_ASYNC16(smem_u32(&Vs[buf][j][ec]), rp + 128);
        }
    };

    load_kv(0, 0);
    CP_COMMIT();

    for (int i = tid; i < 128*4; i += 256) {
        int r = i >> 2, ec = (i & 3) * 8;
        uint4 vq = *(const uint4*)(qkv + (base + (size_t)qtile*128 + r)*768 + colq + ec);
        __half2* p = (__half2*)&vq;
#pragma unroll
        for (int z = 0; z < 4; ++z) p[z] = __hmul2(p[z], hs2);
        *(uint4*)&Qs[r][ec] = vq;
    }
    __syncthreads();

    uint32_t qf[2][4];
#pragma unroll
    for (int kc = 0; kc < 2; ++kc) {
        uint32_t ad = smem_u32(&Qs[wid*16 + l16][kc*16 + (lane>>4)*8]);
        asm volatile("ldmatrix.sync.aligned.m8n8.x4.shared.b16 {%0,%1,%2,%3}, [%4];"
                     : "=r"(qf[kc][0]), "=r"(qf[kc][1]), "=r"(qf[kc][2]), "=r"(qf[kc][3])
                     : "r"(ad));
    }

    float m0 = -1e30f, m1 = -1e30f, l0 = 0.f, l1 = 0.f;
    float oacc[4][4];
#pragma unroll
    for (int ef = 0; ef < 4; ++ef)
#pragma unroll
        for (int r = 0; r < 4; ++r) oacc[ef][r] = 0.f;

    for (int kt = 0; kt < 4; ++kt) {
        const int buf = kt & 1;
        if (kt + 1 < 4) CP_WAIT(1); else CP_WAIT(0);    // tile kt resident
        __syncthreads();                                // visible + buf^1 free
        if (kt + 1 < 4) {
            load_kv(buf ^ 1, kt + 1);
            CP_COMMIT();
        }

        float sacc[16][4];
#pragma unroll
        for (int nf = 0; nf < 16; ++nf) {
            sacc[nf][0] = sacc[nf][1] = sacc[nf][2] = sacc[nf][3] = 0.f;
#pragma unroll
            for (int kc = 0; kc < 2; ++kc) {
                uint32_t b0, b1;
                uint32_t bd = smem_u32(&Ks[buf][nf*8 + (l16 & 7)][kc*16 + (l16 >> 3)*8]);
                asm volatile("ldmatrix.sync.aligned.m8n8.x2.shared.b16 {%0,%1}, [%2];"
                             : "=r"(b0), "=r"(b1) : "r"(bd));
                asm volatile(
                    "mma.sync.aligned.m16n8k16.row.col.f32.f16.f16.f32 "
                    "{%0,%1,%2,%3}, {%4,%5,%6,%7}, {%8,%9}, {%0,%1,%2,%3};"
                    : "+f"(sacc[nf][0]), "+f"(sacc[nf][1]),
                      "+f"(sacc[nf][2]), "+f"(sacc[nf][3])
                    : "r"(qf[kc][0]), "r"(qf[kc][1]), "r"(qf[kc][2]), "r"(qf[kc][3]),
                      "r"(b0), "r"(b1));
            }
        }

        float mx0 = -1e30f, mx1 = -1e30f;
#pragma unroll
        for (int nf = 0; nf < 16; ++nf) {
            mx0 = fmaxf(mx0, fmaxf(sacc[nf][0], sacc[nf][1]));
            mx1 = fmaxf(mx1, fmaxf(sacc[nf][2], sacc[nf][3]));
        }
        mx0 = fmaxf(mx0, __shfl_xor_sync(0xffffffffu, mx0, 1));
        mx0 = fmaxf(mx0, __shfl_xor_sync(0xffffffffu, mx0, 2));
        mx1 = fmaxf(mx1, __shfl_xor_sync(0xffffffffu, mx1, 1));
        mx1 = fmaxf(mx1, __shfl_xor_sync(0xffffffffu, mx1, 2));
        const float nm0 = fmaxf(m0, mx0), nm1 = fmaxf(m1, mx1);
        const float c0 = __expf(m0 - nm0), c1 = __expf(m1 - nm1);
        m0 = nm0; m1 = nm1;
#pragma unroll
        for (int ef = 0; ef < 4; ++ef) {
            oacc[ef][0] *= c0; oacc[ef][1] *= c0;
            oacc[ef][2] *= c1; oacc[ef][3] *= c1;
        }

        float rs0 = 0.f, rs1 = 0.f;
#pragma unroll
        for (int jc = 0; jc < 8; ++jc) {
            float p00 = __expf(sacc[2*jc][0]   - nm0);
            float p01 = __expf(sacc[2*jc][1]   - nm0);
            float p10 = __expf(sacc[2*jc][2]   - nm1);
            float p11 = __expf(sacc[2*jc][3]   - nm1);
            float p20 = __expf(sacc[2*jc+1][0] - nm0);
            float p21 = __expf(sacc[2*jc+1][1] - nm0);
            float p30 = __expf(sacc[2*jc+1][2] - nm1);
            float p31 = __expf(sacc[2*jc+1][3] - nm1);
            rs0 += p00 + p01 + p20 + p21;
            rs1 += p10 + p11 + p30 + p31;
            uint32_t pf0 = pack2h(p00, p01);
            uint32_t pf1 = pack2h(p10, p11);
            uint32_t pf2 = pack2h(p20, p21);
            uint32_t pf3 = pack2h(p30, p31);
#pragma unroll
            for (int ef = 0; ef < 4; ++ef) {
                uint32_t b0, b1;
                uint32_t bd = smem_u32(&Vs[buf][jc*16 + l16][ef*8]);
                asm volatile("ldmatrix.sync.aligned.m8n8.x2.trans.shared.b16 {%0,%1}, [%2];"
                             : "=r"(b0), "=r"(b1) : "r"(bd));
                asm volatile(
                    "mma.sync.aligned.m16n8k16.row.col.f32.f16.f16.f32 "
                    "{%0,%1,%2,%3}, {%4,%5,%6,%7}, {%8,%9}, {%0,%1,%2,%3};"
                    : "+f"(oacc[ef][0]), "+f"(oacc[ef][1]),
                      "+f"(oacc[ef][2]), "+f"(oacc[ef][3])
                    : "r"(pf0), "r"(pf1), "r"(pf2), "r"(pf3),
                      "r"(b0), "r"(b1));
            }
        }
        rs0 += __shfl_xor_sync(0xffffffffu, rs0, 1);
        rs0 += __shfl_xor_sync(0xffffffffu, rs0, 2);
        rs1 += __shfl_xor_sync(0xffffffffu, rs1, 1);
        rs1 += __shfl_xor_sync(0xffffffffu, rs1, 2);
        l0 = l0 * c0 + rs0;
        l1 = l1 * c1 + rs1;
    }

    const float i0 = 1.f / l0, i1 = 1.f / l1;
    const int r0 = wid*16 + (lane >> 2);
#pragma unroll
    for (int ef = 0; ef < 4; ++ef) {
        const int col = head*32 + ef*8 + (lane & 3)*2;
        size_t rowA = (base + (size_t)qtile*128 + r0) * DD + col;
        size_t rowB = (base + (size_t)qtile*128 + r0 + 8) * DD + col;
        *(uint32_t*)&outp[rowA] = pack2h(oacc[ef][0] * i0, oacc[ef][1] * i0);
        *(uint32_t*)&outp[rowB] = pack2h(oacc[ef][2] * i1, oacc[ef][3] * i1);
    }
}

// ---------------- output head (fp16 xc, vectorized loads) --------------------
__global__ void head_kernel(const h16* __restrict__ xc, const float* __restrict__ w1g,
                            const float* __restrict__ b1g, const float* __restrict__ w2g,
                            const float* __restrict__ b2g, float* __restrict__ y)
{
    const int bidx = blockIdx.x;
    const int b = bidx >> 9, n = bidx & 511;
    const int tid = threadIdx.x;
    __shared__ float xs[TT][LL*DD];
    __shared__ float w1[PP][TT];
    __shared__ float b1[PP];
    __shared__ float w2[LL*DD];
    __shared__ float red[PP][4];
    for (int i = tid; i < TT*48; i += 128) {
        int t = i / 48, c = i - (i / 48) * 48;
        uint4 vv = *(const uint4*)(xc + ((size_t)(b*TT + t) * NN + n) * (LL*DD) + c * 8);
        h16 tmp[8]; *(uint4*)tmp = vv;
        float* dst = &xs[t][c * 8];
#pragma unroll
        for (int z = 0; z < 8; ++z) dst[z] = __half2float(tmp[z]);
    }
    for (int i = tid; i < PP*TT; i += 128) w1[i/TT][i%TT] = w1g[i];
    if (tid < PP) b1[tid] = b1g[tid];
    for (int c = tid; c < LL*DD; c += 128) w2[c] = w2g[c];
    __syncthreads();

    float part[PP];
#pragma unroll
    for (int p = 0; p < PP; ++p) part[p] = 0.f;
    for (int c = tid; c < LL*DD; c += 128) {
        float xt[TT];
#pragma unroll
        for (int t = 0; t < TT; ++t) xt[t] = xs[t][c];
        float wc = w2[c];
#pragma unroll
        for (int p = 0; p < PP; ++p) {
            float sacc = b1[p];
#pragma unroll
            for (int t = 0; t < TT; ++t) sacc = fmaf(xt[t], w1[p][t], sacc);
            sacc = fmaxf(sacc, 0.f);
            part[p] = fmaf(sacc, wc, part[p]);
        }
    }
    const int warp = tid >> 5, lane = tid & 31;
#pragma unroll
    for (int p = 0; p < PP; ++p) {
        float sv = part[p];
#pragma unroll
        for (int o = 16; o; o >>= 1) sv += __shfl_xor_sync(0xffffffffu, sv, o);
        if (lane == 0) red[p][warp] = sv;
    }
    __syncthreads();
    if (tid < PP) {
        float sv = red[tid][0] + red[tid][1] + red[tid][2] + red[tid][3];
        y[(size_t)(b*PP + tid) * NN + n] = sv + b2g[0];
    }
}

// ---------------- launcher ---------------------------------------------------
extern "C" void kernel_launch(void* const* d_in, const int* in_sizes, int n_in,
                              void* d_out, int out_size)
{
    (void)in_sizes; (void)n_in; (void)out_size;
    const float* x      = (const float*)d_in[0];
    const float* tokW   = (const float*)d_in[1];
    const float* tokb   = (const float*)d_in[2];
    const float* t_qkvW = (const float*)d_in[3];
    const float* t_qkvb = (const float*)d_in[4];
    const float* t_pW   = (const float*)d_in[5];
    const float* t_pb   = (const float*)d_in[6];
    const float* g_qkvW = (const float*)d_in[7];
    const float* g_qkvb = (const float*)d_in[8];
    const float* g_pW   = (const float*)d_in[9];
    const float* g_pb   = (const float*)d_in[10];
    const float* s_qkvW = (const float*)d_in[11];
    const float* s_qkvb = (const float*)d_in[12];
    const float* s_pW   = (const float*)d_in[13];
    const float* s_pb   = (const float*)d_in[14];
    const float* resW   = (const float*)d_in[15];
    const float* resb   = (const float*)d_in[16];
    const float* normW  = (const float*)d_in[17];
    const float* normb  = (const float*)d_in[18];
    const float* fc1W   = (const float*)d_in[19];
    const float* fc1b   = (const float*)d_in[20];
    const float* fc2W   = (const float*)d_in[21];
    const float* fc2b   = (const float*)d_in[22];
    const float* e1W    = (const float*)d_in[23];
    const float* e1b    = (const float*)d_in[24];
    const float* e2W    = (const float*)d_in[25];
    const float* e2b    = (const float*)d_in[26];
    float* out = (float*)d_out;

    float *bgsB, *b12B;
    h16 *qkvB, *qkv12B, *xcB;
    cudaGetSymbolAddress((void**)&qkvB,   g_qkv);
    cudaGetSymbolAddress((void**)&qkv12B, g_qkv12);
    cudaGetSymbolAddress((void**)&xcB,    g_xc);
    cudaGetSymbolAddress((void**)&bgsB,   b_gs);
    cudaGetSymbolAddress((void**)&b12B,   b_12);

    h16 *hA,*at,*a2,*ml;
    cudaGetSymbolAddress((void**)&hA, a_hA);
    cudaGetSymbolAddress((void**)&at, a_at);
    cudaGetSymbolAddress((void**)&a2, a_a2);
    cudaGetSymbolAddress((void**)&ml, a_ml);

    h16 *tq,*gsF,*w12,*cb;
    cudaGetSymbolAddress((void**)&tq,  w_tq);
    cudaGetSymbolAddress((void**)&gsF, w_gsF);
    cudaGetSymbolAddress((void**)&w12, w_12F);
    cudaGetSymbolAddress((void**)&cb,  w_cb);

    const int MBt = TOK / 128;
    const int DSM = 61440;
    cudaFuncSetAttribute(mma_gemm, cudaFuncAttributeMaxDynamicSharedMemorySize, DSM);

    setup_all<<<3078, 256>>>(t_qkvW, fc2W, resW,
                             g_qkvW, s_qkvW, g_qkvb, s_qkvb, t_pW, t_pb,
                             fc1W, fc1b, g_pW, g_pb, s_pW, s_pb);

    embed_kernel<<<(TOK*DD)/256, 256>>>(x, tokW, tokb, hA);

    for (int l = 0; l < LL; ++l) {
        const size_t oq = (size_t)l*3*DD*DD, oqb = (size_t)l*3*DD;
        const size_t opb = (size_t)l*DD;
        const size_t ogs = (size_t)l*6*DD*DD;

        mma_gemm<<<dim3(3, MBt), 256, DSM>>>(hA, DD, nullptr, 0, tq+oq,
                                             t_qkvb+oqb, nullptr, qkvB, 3*DD, 0,
                                             nullptr, nullptr, nullptr, nullptr, 0);
        temporal_attn_kernel<<<BB*NN, 128>>>(qkvB, at);
        mma_gemm<<<dim3(6, MBt), 256, DSM>>>(at, DD, nullptr, 0, gsF+ogs,
                                             bgsB + (size_t)l*768, nullptr, qkv12B, 6*DD, 0,
                                             nullptr, nullptr, nullptr, nullptr, 0);
        spatial_attn_mma<<<dim3(NN/128, 2*HH, BB*TT), 256>>>(qkv12B, at, a2);
        mma_gemm<<<dim3(2, MBt), 256, DSM>>>(at, DD, a2, DD,
                                             w12+(size_t)l*HMM*2*DD,
                                             b12B+(size_t)l*HMM, nullptr,
                                             ml, HMM, 1,
                                             nullptr, nullptr, nullptr, nullptr, 0);
        mma_gemm<<<dim3(1, MBt), 256, DSM>>>(ml, HMM, hA, DD,
                                             cb+(size_t)l*DD*(HMM+DD),
                                             fc2b+opb, resb+opb,
                                             nullptr, DD, 0,
                                             normW+opb, normb+opb,
                                             hA, xcB + (size_t)l*DD, LL*DD);
    }

    head_kernel<<<BB*NN, 128>>>(xcB, e1W, e1b, e2W, e2b, out);
}